// round 1
// baseline (speedup 1.0000x reference)
#include <cuda_runtime.h>
#include <math.h>

// ---------------------------------------------------------------------------
// Problem constants
//   B=32, N=1280 (NS=1024 search + NT=256 target), D=384, H=8, HD=48
//   KV tokens per batch: 256 (search) + 64 (target) = 320
//   FF = 1536, SCALE = 1/sqrt(48)
// ---------------------------------------------------------------------------
#define BATCH   32
#define NTOK    1280
#define NS_     1024
#define NT_     256
#define DIM     384
#define HEADS   8
#define HDIM    48
#define NKV     320
#define FFDIM   1536
#define ATT_SCALE 0.14433756729740643f

// ---------------------------------------------------------------------------
// Scratch (device globals; no allocation allowed)
// ---------------------------------------------------------------------------
__device__ float g_xn [BATCH * NTOK * DIM];            // LN output (reused for ln2)
__device__ float g_qc [BATCH * NTOK * DIM];            // q conv output
__device__ float g_kc [BATCH * NKV  * DIM];            // k conv output
__device__ float g_vc [BATCH * NKV  * DIM];            // v conv output
__device__ float g_Q  [BATCH * NTOK * DIM];            // projected Q
__device__ float g_K  [BATCH * NKV  * DIM];            // projected K
__device__ float g_V  [BATCH * NKV  * DIM];            // projected V
__device__ float g_x2 [BATCH * NTOK * DIM];            // x + attn
__device__ float g_h1 [BATCH * NTOK * FFDIM];          // FFN hidden
__device__ float g_S  [(size_t)BATCH * HEADS * NS_ * NKV]; // search scores
__device__ float g_St [(size_t)BATCH * HEADS * NT_ * 64];  // target scores

// ---------------------------------------------------------------------------
// LayerNorm: one block (128 threads) per token, D=384 = 3*128
// ---------------------------------------------------------------------------
__global__ void ln_kernel(const float* __restrict__ x, const float* __restrict__ g,
                          const float* __restrict__ b, float* __restrict__ out) {
    int tok = blockIdx.x;
    int tid = threadIdx.x;
    const float* xp = x + (size_t)tok * DIM;
    float v0 = xp[tid], v1 = xp[tid + 128], v2 = xp[tid + 256];
    float s  = v0 + v1 + v2;
    float ss = v0 * v0 + v1 * v1 + v2 * v2;
#pragma unroll
    for (int o = 16; o > 0; o >>= 1) {
        s  += __shfl_xor_sync(0xffffffffu, s,  o);
        ss += __shfl_xor_sync(0xffffffffu, ss, o);
    }
    __shared__ float sh_s[4], sh_ss[4];
    if ((tid & 31) == 0) { sh_s[tid >> 5] = s; sh_ss[tid >> 5] = ss; }
    __syncthreads();
    float ts  = sh_s[0]  + sh_s[1]  + sh_s[2]  + sh_s[3];
    float tss = sh_ss[0] + sh_ss[1] + sh_ss[2] + sh_ss[3];
    float mean = ts * (1.0f / DIM);
    float var  = tss * (1.0f / DIM) - mean * mean;
    float rstd = rsqrtf(var + 1e-5f);
    float* op = out + (size_t)tok * DIM;
    op[tid]       = (v0 - mean) * rstd * g[tid]       + b[tid];
    op[tid + 128] = (v1 - mean) * rstd * g[tid + 128] + b[tid + 128];
    op[tid + 256] = (v2 - mean) * rstd * g[tid + 256] + b[tid + 256];
}

// ---------------------------------------------------------------------------
// Depthwise 3x3 conv + bias + BN affine, operating in token layout [b, tok, c]
// One block per output position, 384 threads (one per channel) -> coalesced.
// ---------------------------------------------------------------------------
__global__ void dwconv_bn(const float* __restrict__ in, const float* __restrict__ w,
                          const float* __restrict__ cb, const float* __restrict__ bng,
                          const float* __restrict__ bnb, float* __restrict__ out,
                          int hw_in, int hw_out, int stride,
                          int in_boff, int in_bstride, int out_boff, int out_bstride) {
    int c   = threadIdx.x;
    int blk = blockIdx.x;
    int ox  = blk % hw_out;
    int oy  = (blk / hw_out) % hw_out;
    int b   = blk / (hw_out * hw_out);
    const float* ip = in + (size_t)b * in_bstride + (size_t)in_boff * DIM;
    float acc = cb[c];
#pragma unroll
    for (int ky = 0; ky < 3; ky++) {
        int iy = oy * stride - 1 + ky;
        if (iy < 0 || iy >= hw_in) continue;
#pragma unroll
        for (int kx = 0; kx < 3; kx++) {
            int ix = ox * stride - 1 + kx;
            if (ix < 0 || ix >= hw_in) continue;
            acc += ip[(size_t)(iy * hw_in + ix) * DIM + c] * w[c * 9 + ky * 3 + kx];
        }
    }
    float sc = bng[c] * rsqrtf(1.0f + 1e-5f);
    out[(size_t)b * out_bstride + (size_t)(out_boff + oy * hw_out + ox) * DIM + c]
        = acc * sc + bnb[c];
}

// ---------------------------------------------------------------------------
// Tiled SGEMM:  C[m,n] = epi( A[m,:] . W[n,:] + bias[n] )
// 128x128 tile, BK=8, 256 threads, 8x8 micro-tile per thread.
// EPI: 0 = bias only, 1 = bias + exact GELU, 2 = bias + residual add.
// Requires M%128==0, N%128==0, K%8==0 (true for all our shapes).
// ---------------------------------------------------------------------------
template<int EPI>
__global__ void gemm128(const float* __restrict__ A, const float* __restrict__ W,
                        const float* __restrict__ bias, const float* __restrict__ res,
                        float* __restrict__ C, int M, int N, int K) {
    __shared__ float As[8][128];
    __shared__ float Bs[8][128];
    int n0 = blockIdx.x * 128, m0 = blockIdx.y * 128;
    int t = threadIdx.x;
    int tx = t & 15, ty = t >> 4;
    int lrow = t >> 1, lhalf = (t & 1) * 4;
    float acc[8][8] = {};
    for (int k0 = 0; k0 < K; k0 += 8) {
        float4 av = *(const float4*)(A + (size_t)(m0 + lrow) * K + k0 + lhalf);
        float4 bv = *(const float4*)(W + (size_t)(n0 + lrow) * K + k0 + lhalf);
        __syncthreads();
        As[lhalf + 0][lrow] = av.x; As[lhalf + 1][lrow] = av.y;
        As[lhalf + 2][lrow] = av.z; As[lhalf + 3][lrow] = av.w;
        Bs[lhalf + 0][lrow] = bv.x; Bs[lhalf + 1][lrow] = bv.y;
        Bs[lhalf + 2][lrow] = bv.z; Bs[lhalf + 3][lrow] = bv.w;
        __syncthreads();
#pragma unroll
        for (int kk = 0; kk < 8; kk++) {
            float a[8], bb[8];
#pragma unroll
            for (int i = 0; i < 8; i++) a[i] = As[kk][ty + 16 * i];
#pragma unroll
            for (int j = 0; j < 8; j++) bb[j] = Bs[kk][tx + 16 * j];
#pragma unroll
            for (int i = 0; i < 8; i++)
#pragma unroll
                for (int j = 0; j < 8; j++)
                    acc[i][j] += a[i] * bb[j];
        }
    }
#pragma unroll
    for (int i = 0; i < 8; i++) {
        int row = m0 + ty + 16 * i;
#pragma unroll
        for (int j = 0; j < 8; j++) {
            int col = n0 + tx + 16 * j;
            float v = acc[i][j] + bias[col];
            if (EPI == 1) v = 0.5f * v * (1.0f + erff(v * 0.70710678118654752f));
            size_t gi = (size_t)row * N + col;
            if (EPI == 2) v += res[gi];
            C[gi] = v;
        }
    }
}

// ---------------------------------------------------------------------------
// Attention scores: S[bh, q, m] = SCALE * dot(Q[b, q_base+q, h*48:], K[b, kv_base+m, h*48:])
// Block tile: 32 queries x 64 kv, 256 threads, 2x4 micro-tile.
// grid: (nkv/64, nq/32, B*H)
// ---------------------------------------------------------------------------
__global__ void attn_scores(const float* __restrict__ Q, const float* __restrict__ Kmat,
                            float* __restrict__ S,
                            int q_base, int kv_base, int nq, int nkv) {
    __shared__ float Qs[32][49];
    __shared__ float Ks[64][49];
    int bh = blockIdx.z, b = bh >> 3, h = bh & 7;
    int q0 = blockIdx.y * 32, m0 = blockIdx.x * 64;
    int t = threadIdx.x;
    for (int idx = t; idx < 384; idx += 256) {        // 32 rows x 12 float4
        int r = idx / 12, c4 = (idx % 12) * 4;
        float4 v = *(const float4*)(Q + (size_t)(b * NTOK + q_base + q0 + r) * DIM + h * HDIM + c4);
        Qs[r][c4] = v.x; Qs[r][c4 + 1] = v.y; Qs[r][c4 + 2] = v.z; Qs[r][c4 + 3] = v.w;
    }
    for (int idx = t; idx < 768; idx += 256) {        // 64 rows x 12 float4
        int r = idx / 12, c4 = (idx % 12) * 4;
        float4 v = *(const float4*)(Kmat + (size_t)(b * NKV + kv_base + m0 + r) * DIM + h * HDIM + c4);
        Ks[r][c4] = v.x; Ks[r][c4 + 1] = v.y; Ks[r][c4 + 2] = v.z; Ks[r][c4 + 3] = v.w;
    }
    __syncthreads();
    int tx = t & 15, ty = t >> 4;
    float acc[2][4] = {};
#pragma unroll
    for (int kk = 0; kk < 48; kk++) {
        float a0 = Qs[ty][kk], a1 = Qs[ty + 16][kk];
        float b0 = Ks[tx][kk], b1 = Ks[tx + 16][kk];
        float b2 = Ks[tx + 32][kk], b3 = Ks[tx + 48][kk];
        acc[0][0] += a0 * b0; acc[0][1] += a0 * b1; acc[0][2] += a0 * b2; acc[0][3] += a0 * b3;
        acc[1][0] += a1 * b0; acc[1][1] += a1 * b1; acc[1][2] += a1 * b2; acc[1][3] += a1 * b3;
    }
#pragma unroll
    for (int i = 0; i < 2; i++)
#pragma unroll
        for (int j = 0; j < 4; j++)
            S[((size_t)bh * nq + q0 + ty + 16 * i) * nkv + m0 + tx + 16 * j]
                = acc[i][j] * ATT_SCALE;
}

// ---------------------------------------------------------------------------
// Row softmax in place. One warp per row (rowlen <= 320 -> <=10 elems/lane).
// ---------------------------------------------------------------------------
__global__ void softmax_rows(float* __restrict__ S, int nrows, int rowlen) {
    int row = blockIdx.x * 8 + (threadIdx.x >> 5);
    if (row >= nrows) return;
    int lane = threadIdx.x & 31;
    float* p = S + (size_t)row * rowlen;
    float mx = -1e30f;
    float e[10];
    int cnt = 0;
    for (int m = lane; m < rowlen; m += 32) { float v = p[m]; e[cnt++] = v; mx = fmaxf(mx, v); }
#pragma unroll
    for (int o = 16; o > 0; o >>= 1) mx = fmaxf(mx, __shfl_xor_sync(0xffffffffu, mx, o));
    float sum = 0.0f;
    for (int i = 0; i < cnt; i++) { e[i] = expf(e[i] - mx); sum += e[i]; }
#pragma unroll
    for (int o = 16; o > 0; o >>= 1) sum += __shfl_xor_sync(0xffffffffu, sum, o);
    float inv = 1.0f / sum;
    cnt = 0;
    for (int m = lane; m < rowlen; m += 32) p[m] = e[cnt++] * inv;
}

// ---------------------------------------------------------------------------
// O = P @ V, fused with residual:  x2[b, q, h*48+c] = x[...] + sum_m P * V
// Block tile: 64 queries x 48 out-dims, loop over kv in tiles of 32.
// 256 threads, 4x3 micro-tile. grid: (nq/64, B*H)
// ---------------------------------------------------------------------------
__global__ void attn_av(const float* __restrict__ P, const float* __restrict__ V,
                        const float* __restrict__ x, float* __restrict__ x2,
                        int q_base, int kv_base, int nq, int nkv) {
    __shared__ float Ps[64][33];
    __shared__ float Vs[32][48];
    int bh = blockIdx.y, b = bh >> 3, h = bh & 7;
    int q0 = blockIdx.x * 64;
    int t = threadIdx.x, tx = t & 15, ty = t >> 4;
    float acc[4][3] = {};
    for (int k0 = 0; k0 < nkv; k0 += 32) {
        __syncthreads();
        for (int idx = t; idx < 512; idx += 256) {    // 64 rows x 8 float4
            int r = idx >> 3, c4 = (idx & 7) * 4;
            float4 v = *(const float4*)(P + ((size_t)bh * nq + q0 + r) * nkv + k0 + c4);
            Ps[r][c4] = v.x; Ps[r][c4 + 1] = v.y; Ps[r][c4 + 2] = v.z; Ps[r][c4 + 3] = v.w;
        }
        for (int idx = t; idx < 384; idx += 256) {    // 32 rows x 12 float4
            int r = idx / 12, c4 = (idx % 12) * 4;
            float4 v = *(const float4*)(V + (size_t)(b * NKV + kv_base + k0 + r) * DIM + h * HDIM + c4);
            Vs[r][c4] = v.x; Vs[r][c4 + 1] = v.y; Vs[r][c4 + 2] = v.z; Vs[r][c4 + 3] = v.w;
        }
        __syncthreads();
#pragma unroll
        for (int kk = 0; kk < 32; kk++) {
            float a0 = Ps[ty][kk], a1 = Ps[ty + 16][kk];
            float a2 = Ps[ty + 32][kk], a3 = Ps[ty + 48][kk];
            float b0 = Vs[kk][tx], b1 = Vs[kk][tx + 16], b2 = Vs[kk][tx + 32];
            acc[0][0] += a0 * b0; acc[0][1] += a0 * b1; acc[0][2] += a0 * b2;
            acc[1][0] += a1 * b0; acc[1][1] += a1 * b1; acc[1][2] += a1 * b2;
            acc[2][0] += a2 * b0; acc[2][1] += a2 * b1; acc[2][2] += a2 * b2;
            acc[3][0] += a3 * b0; acc[3][1] += a3 * b1; acc[3][2] += a3 * b2;
        }
    }
#pragma unroll
    for (int i = 0; i < 4; i++)
#pragma unroll
        for (int j = 0; j < 3; j++) {
            size_t gi = (size_t)(b * NTOK + q_base + q0 + ty + 16 * i) * DIM + h * HDIM + tx + 16 * j;
            x2[gi] = x[gi] + acc[i][j];
        }
}

// ---------------------------------------------------------------------------
// Launch
// ---------------------------------------------------------------------------
extern "C" void kernel_launch(void* const* d_in, const int* in_sizes, int n_in,
                              void* d_out, int out_size) {
    (void)in_sizes; (void)n_in; (void)out_size;
    const float* x     = (const float*)d_in[0];
    const float* ln1_g = (const float*)d_in[1];
    const float* ln1_b = (const float*)d_in[2];
    const float* dwq_w = (const float*)d_in[3];
    const float* dwq_b = (const float*)d_in[4];
    const float* bnq_g = (const float*)d_in[5];
    const float* bnq_b = (const float*)d_in[6];
    const float* dwk_w = (const float*)d_in[7];
    const float* dwk_b = (const float*)d_in[8];
    const float* bnk_g = (const float*)d_in[9];
    const float* bnk_b = (const float*)d_in[10];
    const float* dwv_w = (const float*)d_in[11];
    const float* dwv_b = (const float*)d_in[12];
    const float* bnv_g = (const float*)d_in[13];
    const float* bnv_b = (const float*)d_in[14];
    const float* pq_w  = (const float*)d_in[15];
    const float* pq_b  = (const float*)d_in[16];
    const float* pk_w  = (const float*)d_in[17];
    const float* pk_b  = (const float*)d_in[18];
    const float* pv_w  = (const float*)d_in[19];
    const float* pv_b  = (const float*)d_in[20];
    const float* ln2_g = (const float*)d_in[21];
    const float* ln2_b = (const float*)d_in[22];
    const float* ff1_w = (const float*)d_in[23];
    const float* ff1_b = (const float*)d_in[24];
    const float* ff2_w = (const float*)d_in[25];
    const float* ff2_b = (const float*)d_in[26];
    float* out = (float*)d_out;

    float *xn, *qc, *kc, *vc, *Q, *K, *V, *x2, *h1, *S, *St;
    cudaGetSymbolAddress((void**)&xn, g_xn);
    cudaGetSymbolAddress((void**)&qc, g_qc);
    cudaGetSymbolAddress((void**)&kc, g_kc);
    cudaGetSymbolAddress((void**)&vc, g_vc);
    cudaGetSymbolAddress((void**)&Q,  g_Q);
    cudaGetSymbolAddress((void**)&K,  g_K);
    cudaGetSymbolAddress((void**)&V,  g_V);
    cudaGetSymbolAddress((void**)&x2, g_x2);
    cudaGetSymbolAddress((void**)&h1, g_h1);
    cudaGetSymbolAddress((void**)&S,  g_S);
    cudaGetSymbolAddress((void**)&St, g_St);

    const int BS_X  = NTOK * DIM;   // batch stride of token-layout buffers
    const int BS_KV = NKV * DIM;    // batch stride of kv-layout buffers

    // 1. LN1
    ln_kernel<<<BATCH * NTOK, 128>>>(x, ln1_g, ln1_b, xn);

    // 2. Depthwise convs (+bias+BN), both branches
    dwconv_bn<<<BATCH * 1024, DIM>>>(xn, dwq_w, dwq_b, bnq_g, bnq_b, qc, 32, 32, 1, 0,    BS_X, 0,    BS_X);
    dwconv_bn<<<BATCH * 256,  DIM>>>(xn, dwq_w, dwq_b, bnq_g, bnq_b, qc, 16, 16, 1, 1024, BS_X, 1024, BS_X);
    dwconv_bn<<<BATCH * 256,  DIM>>>(xn, dwk_w, dwk_b, bnk_g, bnk_b, kc, 32, 16, 2, 0,    BS_X, 0,    BS_KV);
    dwconv_bn<<<BATCH * 64,   DIM>>>(xn, dwk_w, dwk_b, bnk_g, bnk_b, kc, 16, 8,  2, 1024, BS_X, 256,  BS_KV);
    dwconv_bn<<<BATCH * 256,  DIM>>>(xn, dwv_w, dwv_b, bnv_g, bnv_b, vc, 32, 16, 2, 0,    BS_X, 0,    BS_KV);
    dwconv_bn<<<BATCH * 64,   DIM>>>(xn, dwv_w, dwv_b, bnv_g, bnv_b, vc, 16, 8,  2, 1024, BS_X, 256,  BS_KV);

    // 3. Q/K/V projections
    gemm128<0><<<dim3(3, 320), 256>>>(qc, pq_w, pq_b, nullptr, Q, BATCH * NTOK, DIM, DIM);
    gemm128<0><<<dim3(3, 80),  256>>>(kc, pk_w, pk_b, nullptr, K, BATCH * NKV,  DIM, DIM);
    gemm128<0><<<dim3(3, 80),  256>>>(vc, pv_w, pv_b, nullptr, V, BATCH * NKV,  DIM, DIM);

    // 4. Attention
    attn_scores<<<dim3(5, 32, BATCH * HEADS), 256>>>(Q, K, S,  0,    0,   NS_, NKV);
    attn_scores<<<dim3(1, 8,  BATCH * HEADS), 256>>>(Q, K, St, 1024, 256, NT_, 64);
    softmax_rows<<<(BATCH * HEADS * NS_) / 8, 256>>>(S,  BATCH * HEADS * NS_, NKV);
    softmax_rows<<<(BATCH * HEADS * NT_) / 8, 256>>>(St, BATCH * HEADS * NT_, 64);
    attn_av<<<dim3(16, BATCH * HEADS), 256>>>(S,  V, x, x2, 0,    0,   NS_, NKV);
    attn_av<<<dim3(4,  BATCH * HEADS), 256>>>(St, V, x, x2, 1024, 256, NT_, 64);

    // 5. LN2 + FFN (residual fused into FFN2 epilogue, writes d_out)
    ln_kernel<<<BATCH * NTOK, 128>>>(x2, ln2_g, ln2_b, xn);
    gemm128<1><<<dim3(12, 320), 256>>>(xn, ff1_w, ff1_b, nullptr, h1, BATCH * NTOK, FFDIM, DIM);
    gemm128<2><<<dim3(3, 320),  256>>>(h1, ff2_w, ff2_b, x2, out, BATCH * NTOK, DIM, FFDIM);
}

// round 3
// speedup vs baseline: 1.6511x; 1.6511x over previous
#include <cuda_runtime.h>
#include <math.h>
#include <stdint.h>

// ---------------------------------------------------------------------------
// Problem constants
//   B=32, N=1280 (NS=1024 search + NT=256 target), D=384, H=8, HD=48
//   KV tokens per batch: 256 (search) + 64 (target) = 320
//   FF = 1536, SCALE = 1/sqrt(48)
// ---------------------------------------------------------------------------
#define BATCH   32
#define NTOK    1280
#define NS_     1024
#define NT_     256
#define DIM     384
#define HEADS   8
#define HDIM    48
#define NKV     320
#define FFDIM   1536
#define ATT_SCALE 0.14433756729740643f

// ---------------------------------------------------------------------------
// Scratch (device globals; no allocation allowed)
// ---------------------------------------------------------------------------
__device__ float g_xn [BATCH * NTOK * DIM];
__device__ float g_qc [BATCH * NTOK * DIM];
__device__ float g_kc [BATCH * NKV  * DIM];
__device__ float g_vc [BATCH * NKV  * DIM];
__device__ float g_Q  [BATCH * NTOK * DIM];
__device__ float g_K  [BATCH * NKV  * DIM];
__device__ float g_V  [BATCH * NKV  * DIM];
__device__ float g_x2 [BATCH * NTOK * DIM];
__device__ float g_h1 [BATCH * NTOK * FFDIM];
__device__ float g_S  [(size_t)BATCH * HEADS * NS_ * NKV];
__device__ float g_St [(size_t)BATCH * HEADS * NT_ * 64];

// ---------------------------------------------------------------------------
// Helpers
// ---------------------------------------------------------------------------
__device__ __forceinline__ float tf32r(float x) {
    uint32_t u;
    asm("cvt.rna.tf32.f32 %0, %1;" : "=r"(u) : "f"(x));
    return __uint_as_float(u);
}

__device__ __forceinline__ void mma_tf32(float* c, const uint32_t* a, const uint32_t* b) {
    asm volatile(
        "mma.sync.aligned.m16n8k8.row.col.f32.tf32.tf32.f32 "
        "{%0,%1,%2,%3}, {%4,%5,%6,%7}, {%8,%9}, {%0,%1,%2,%3};"
        : "+f"(c[0]), "+f"(c[1]), "+f"(c[2]), "+f"(c[3])
        : "r"(a[0]), "r"(a[1]), "r"(a[2]), "r"(a[3]), "r"(b[0]), "r"(b[1]));
}

// ---------------------------------------------------------------------------
// LayerNorm: one block (128 threads) per token, D=384 = 3*128
// ---------------------------------------------------------------------------
__global__ void ln_kernel(const float* __restrict__ x, const float* __restrict__ g,
                          const float* __restrict__ b, float* __restrict__ out) {
    int tok = blockIdx.x;
    int tid = threadIdx.x;
    const float* xp = x + (size_t)tok * DIM;
    float v0 = xp[tid], v1 = xp[tid + 128], v2 = xp[tid + 256];
    float s  = v0 + v1 + v2;
    float ss = v0 * v0 + v1 * v1 + v2 * v2;
#pragma unroll
    for (int o = 16; o > 0; o >>= 1) {
        s  += __shfl_xor_sync(0xffffffffu, s,  o);
        ss += __shfl_xor_sync(0xffffffffu, ss, o);
    }
    __shared__ float sh_s[4], sh_ss[4];
    if ((tid & 31) == 0) { sh_s[tid >> 5] = s; sh_ss[tid >> 5] = ss; }
    __syncthreads();
    float ts  = sh_s[0]  + sh_s[1]  + sh_s[2]  + sh_s[3];
    float tss = sh_ss[0] + sh_ss[1] + sh_ss[2] + sh_ss[3];
    float mean = ts * (1.0f / DIM);
    float var  = tss * (1.0f / DIM) - mean * mean;
    float rstd = rsqrtf(var + 1e-5f);
    float* op = out + (size_t)tok * DIM;
    op[tid]       = (v0 - mean) * rstd * g[tid]       + b[tid];
    op[tid + 128] = (v1 - mean) * rstd * g[tid + 128] + b[tid + 128];
    op[tid + 256] = (v2 - mean) * rstd * g[tid + 256] + b[tid + 256];
}

// ---------------------------------------------------------------------------
// Depthwise 3x3 conv + bias + BN affine in token layout [b, tok, c]
// ---------------------------------------------------------------------------
__global__ void dwconv_bn(const float* __restrict__ in, const float* __restrict__ w,
                          const float* __restrict__ cb, const float* __restrict__ bng,
                          const float* __restrict__ bnb, float* __restrict__ out,
                          int hw_in, int hw_out, int stride,
                          int in_boff, int in_bstride, int out_boff, int out_bstride) {
    int c   = threadIdx.x;
    int blk = blockIdx.x;
    int ox  = blk % hw_out;
    int oy  = (blk / hw_out) % hw_out;
    int b   = blk / (hw_out * hw_out);
    const float* ip = in + (size_t)b * in_bstride + (size_t)in_boff * DIM;
    float acc = cb[c];
#pragma unroll
    for (int ky = 0; ky < 3; ky++) {
        int iy = oy * stride - 1 + ky;
        if (iy < 0 || iy >= hw_in) continue;
#pragma unroll
        for (int kx = 0; kx < 3; kx++) {
            int ix = ox * stride - 1 + kx;
            if (ix < 0 || ix >= hw_in) continue;
            acc += ip[(size_t)(iy * hw_in + ix) * DIM + c] * w[c * 9 + ky * 3 + kx];
        }
    }
    float sc = bng[c] * rsqrtf(1.0f + 1e-5f);
    out[(size_t)b * out_bstride + (size_t)(out_boff + oy * hw_out + ox) * DIM + c]
        = acc * sc + bnb[c];
}

// ---------------------------------------------------------------------------
// TF32 tensor-core GEMM: C[m,n] = epi( dot(A[m,:], W[n,:]) + bias[n] )
// 128x128x16 CTA tile, 256 threads = 8 warps, warp tile 64x32 (4x4 mma tiles
// of m16n8k8). Register-prefetch pipelining, conflict-free smem (pad 136).
// EPI: 0 = bias, 1 = bias + exact GELU, 2 = bias + residual add.
// Requires M%128==0, N%128==0, K%16==0.
// ---------------------------------------------------------------------------
template<int EPI>
__global__ void __launch_bounds__(256)
gemm_tf32(const float* __restrict__ A, const float* __restrict__ W,
          const float* __restrict__ bias, const float* __restrict__ res,
          float* __restrict__ C, int M, int N, int K) {
    __shared__ float As[16][136];
    __shared__ float Bs[16][136];

    int n0 = blockIdx.x * 128, m0 = blockIdx.y * 128;
    int t = threadIdx.x;
    int lm = t & 127, lk = (t >> 7) * 8;

    const float* Aload = A + (size_t)(m0 + lm) * K + lk;
    const float* Bload = W + (size_t)(n0 + lm) * K + lk;

    int lane = t & 31, g = lane >> 2, tig = lane & 3;
    int w = t >> 5;
    int wm = (w >> 2) * 64, wn = (w & 3) * 32;

    float acc[4][4][4] = {};

    // prologue: fill tile k0=0
    {
        float4 a0v = *(const float4*)(Aload);
        float4 a1v = *(const float4*)(Aload + 4);
        float4 b0v = *(const float4*)(Bload);
        float4 b1v = *(const float4*)(Bload + 4);
        As[lk + 0][lm] = tf32r(a0v.x); As[lk + 1][lm] = tf32r(a0v.y);
        As[lk + 2][lm] = tf32r(a0v.z); As[lk + 3][lm] = tf32r(a0v.w);
        As[lk + 4][lm] = tf32r(a1v.x); As[lk + 5][lm] = tf32r(a1v.y);
        As[lk + 6][lm] = tf32r(a1v.z); As[lk + 7][lm] = tf32r(a1v.w);
        Bs[lk + 0][lm] = tf32r(b0v.x); Bs[lk + 1][lm] = tf32r(b0v.y);
        Bs[lk + 2][lm] = tf32r(b0v.z); Bs[lk + 3][lm] = tf32r(b0v.w);
        Bs[lk + 4][lm] = tf32r(b1v.x); Bs[lk + 5][lm] = tf32r(b1v.y);
        Bs[lk + 6][lm] = tf32r(b1v.z); Bs[lk + 7][lm] = tf32r(b1v.w);
    }
    __syncthreads();

    for (int k0 = 0; k0 < K; k0 += 16) {
        bool pref = (k0 + 16) < K;
        float4 na0, na1, nb0, nb1;
        if (pref) {
            na0 = *(const float4*)(Aload + k0 + 16);
            na1 = *(const float4*)(Aload + k0 + 20);
            nb0 = *(const float4*)(Bload + k0 + 16);
            nb1 = *(const float4*)(Bload + k0 + 20);
        }
#pragma unroll
        for (int ks = 0; ks < 16; ks += 8) {
            uint32_t af[4][4], bf[4][2];
#pragma unroll
            for (int mt = 0; mt < 4; mt++) {
                int r = wm + mt * 16 + g;
                af[mt][0] = __float_as_uint(As[ks + tig    ][r]);
                af[mt][1] = __float_as_uint(As[ks + tig    ][r + 8]);
                af[mt][2] = __float_as_uint(As[ks + tig + 4][r]);
                af[mt][3] = __float_as_uint(As[ks + tig + 4][r + 8]);
            }
#pragma unroll
            for (int nt = 0; nt < 4; nt++) {
                int c2 = wn + nt * 8 + g;
                bf[nt][0] = __float_as_uint(Bs[ks + tig    ][c2]);
                bf[nt][1] = __float_as_uint(Bs[ks + tig + 4][c2]);
            }
#pragma unroll
            for (int mt = 0; mt < 4; mt++)
#pragma unroll
                for (int nt = 0; nt < 4; nt++)
                    mma_tf32(acc[mt][nt], af[mt], bf[nt]);
        }
        if (pref) {
            __syncthreads();
            As[lk + 0][lm] = tf32r(na0.x); As[lk + 1][lm] = tf32r(na0.y);
            As[lk + 2][lm] = tf32r(na0.z); As[lk + 3][lm] = tf32r(na0.w);
            As[lk + 4][lm] = tf32r(na1.x); As[lk + 5][lm] = tf32r(na1.y);
            As[lk + 6][lm] = tf32r(na1.z); As[lk + 7][lm] = tf32r(na1.w);
            Bs[lk + 0][lm] = tf32r(nb0.x); Bs[lk + 1][lm] = tf32r(nb0.y);
            Bs[lk + 2][lm] = tf32r(nb0.z); Bs[lk + 3][lm] = tf32r(nb0.w);
            Bs[lk + 4][lm] = tf32r(nb1.x); Bs[lk + 5][lm] = tf32r(nb1.y);
            Bs[lk + 6][lm] = tf32r(nb1.z); Bs[lk + 7][lm] = tf32r(nb1.w);
            __syncthreads();
        }
    }

    // epilogue
#pragma unroll
    for (int mt = 0; mt < 4; mt++) {
#pragma unroll
        for (int nt = 0; nt < 4; nt++) {
            int row = m0 + wm + mt * 16 + g;
            int col = n0 + wn + nt * 8 + 2 * tig;
#pragma unroll
            for (int half = 0; half < 2; half++) {
                int r = row + half * 8;
                float v0 = acc[mt][nt][half * 2 + 0] + bias[col];
                float v1 = acc[mt][nt][half * 2 + 1] + bias[col + 1];
                if (EPI == 1) {
                    v0 = 0.5f * v0 * (1.0f + erff(v0 * 0.70710678118654752f));
                    v1 = 0.5f * v1 * (1.0f + erff(v1 * 0.70710678118654752f));
                }
                size_t gi = (size_t)r * N + col;
                if (EPI == 2) { v0 += res[gi]; v1 += res[gi + 1]; }
                *(float2*)(C + gi) = make_float2(v0, v1);
            }
        }
    }
}

// ---------------------------------------------------------------------------
// Attention scores: 64q x 64kv tile, 256 threads, 4x4 micro-tile.
// grid: (nkv/64, nq/64, B*H)
// ---------------------------------------------------------------------------
__global__ void attn_scores(const float* __restrict__ Q, const float* __restrict__ Kmat,
                            float* __restrict__ S,
                            int q_base, int kv_base, int nq, int nkv) {
    __shared__ float Qs[64][49];
    __shared__ float Ks[64][49];
    int bh = blockIdx.z, b = bh >> 3, h = bh & 7;
    int q0 = blockIdx.y * 64, m0 = blockIdx.x * 64;
    int t = threadIdx.x;
    for (int idx = t; idx < 768; idx += 256) {
        int r = idx / 12, c4 = (idx % 12) * 4;
        float4 v = *(const float4*)(Q + (size_t)(b * NTOK + q_base + q0 + r) * DIM + h * HDIM + c4);
        Qs[r][c4] = v.x; Qs[r][c4 + 1] = v.y; Qs[r][c4 + 2] = v.z; Qs[r][c4 + 3] = v.w;
        float4 u = *(const float4*)(Kmat + (size_t)(b * NKV + kv_base + m0 + r) * DIM + h * HDIM + c4);
        Ks[r][c4] = u.x; Ks[r][c4 + 1] = u.y; Ks[r][c4 + 2] = u.z; Ks[r][c4 + 3] = u.w;
    }
    __syncthreads();
    int tx = t & 15, ty = t >> 4;
    float acc[4][4] = {};
#pragma unroll 4
    for (int kk = 0; kk < 48; kk++) {
        float a[4], bb[4];
#pragma unroll
        for (int i = 0; i < 4; i++) a[i]  = Qs[ty + 16 * i][kk];
#pragma unroll
        for (int j = 0; j < 4; j++) bb[j] = Ks[tx + 16 * j][kk];
#pragma unroll
        for (int i = 0; i < 4; i++)
#pragma unroll
            for (int j = 0; j < 4; j++)
                acc[i][j] += a[i] * bb[j];
    }
#pragma unroll
    for (int i = 0; i < 4; i++)
#pragma unroll
        for (int j = 0; j < 4; j++)
            S[((size_t)bh * nq + q0 + ty + 16 * i) * nkv + m0 + tx + 16 * j]
                = acc[i][j] * ATT_SCALE;
}

// ---------------------------------------------------------------------------
// Row softmax in place. One warp per row.
// ---------------------------------------------------------------------------
__global__ void softmax_rows(float* __restrict__ S, int nrows, int rowlen) {
    int row = blockIdx.x * 8 + (threadIdx.x >> 5);
    if (row >= nrows) return;
    int lane = threadIdx.x & 31;
    float* p = S + (size_t)row * rowlen;
    float mx = -1e30f;
    float e[10];
    int cnt = 0;
    for (int m = lane; m < rowlen; m += 32) { float v = p[m]; e[cnt++] = v; mx = fmaxf(mx, v); }
#pragma unroll
    for (int o = 16; o > 0; o >>= 1) mx = fmaxf(mx, __shfl_xor_sync(0xffffffffu, mx, o));
    float sum = 0.0f;
    for (int i = 0; i < cnt; i++) { e[i] = expf(e[i] - mx); sum += e[i]; }
#pragma unroll
    for (int o = 16; o > 0; o >>= 1) sum += __shfl_xor_sync(0xffffffffu, sum, o);
    float inv = 1.0f / sum;
    cnt = 0;
    for (int m = lane; m < rowlen; m += 32) p[m] = e[cnt++] * inv;
}

// ---------------------------------------------------------------------------
// O = P @ V fused with residual: 128q x 48 tile, 256 threads, 8x3 micro-tile.
// grid: (nq/128, B*H)
// ---------------------------------------------------------------------------
__global__ void attn_av(const float* __restrict__ P, const float* __restrict__ V,
                        const float* __restrict__ x, float* __restrict__ x2,
                        int q_base, int kv_base, int nq, int nkv) {
    __shared__ float Ps[128][33];
    __shared__ float Vs[32][49];
    int bh = blockIdx.y, b = bh >> 3, h = bh & 7;
    int q0 = blockIdx.x * 128;
    int t = threadIdx.x, tx = t & 15, ty = t >> 4;
    float acc[8][3] = {};
    for (int k0 = 0; k0 < nkv; k0 += 32) {
        __syncthreads();
        for (int idx = t; idx < 1024; idx += 256) {   // 128 rows x 8 float4
            int r = idx >> 3, c4 = (idx & 7) * 4;
            float4 v = *(const float4*)(P + ((size_t)bh * nq + q0 + r) * nkv + k0 + c4);
            Ps[r][c4] = v.x; Ps[r][c4 + 1] = v.y; Ps[r][c4 + 2] = v.z; Ps[r][c4 + 3] = v.w;
        }
        for (int idx = t; idx < 384; idx += 256) {    // 32 rows x 12 float4
            int r = idx / 12, c4 = (idx % 12) * 4;
            float4 v = *(const float4*)(V + (size_t)(b * NKV + kv_base + k0 + r) * DIM + h * HDIM + c4);
            Vs[r][c4] = v.x; Vs[r][c4 + 1] = v.y; Vs[r][c4 + 2] = v.z; Vs[r][c4 + 3] = v.w;
        }
        __syncthreads();
#pragma unroll 2
        for (int kk = 0; kk < 32; kk++) {
            float a[8], bb[3];
#pragma unroll
            for (int i = 0; i < 8; i++) a[i]  = Ps[ty + 16 * i][kk];
#pragma unroll
            for (int j = 0; j < 3; j++) bb[j] = Vs[kk][tx + 16 * j];
#pragma unroll
            for (int i = 0; i < 8; i++)
#pragma unroll
                for (int j = 0; j < 3; j++)
                    acc[i][j] += a[i] * bb[j];
        }
    }
#pragma unroll
    for (int i = 0; i < 8; i++)
#pragma unroll
        for (int j = 0; j < 3; j++) {
            size_t gi = (size_t)(b * NTOK + q_base + q0 + ty + 16 * i) * DIM + h * HDIM + tx + 16 * j;
            x2[gi] = x[gi] + acc[i][j];
        }
}

// ---------------------------------------------------------------------------
// Launch
// ---------------------------------------------------------------------------
extern "C" void kernel_launch(void* const* d_in, const int* in_sizes, int n_in,
                              void* d_out, int out_size) {
    (void)in_sizes; (void)n_in; (void)out_size;
    const float* x     = (const float*)d_in[0];
    const float* ln1_g = (const float*)d_in[1];
    const float* ln1_b = (const float*)d_in[2];
    const float* dwq_w = (const float*)d_in[3];
    const float* dwq_b = (const float*)d_in[4];
    const float* bnq_g = (const float*)d_in[5];
    const float* bnq_b = (const float*)d_in[6];
    const float* dwk_w = (const float*)d_in[7];
    const float* dwk_b = (const float*)d_in[8];
    const float* bnk_g = (const float*)d_in[9];
    const float* bnk_b = (const float*)d_in[10];
    const float* dwv_w = (const float*)d_in[11];
    const float* dwv_b = (const float*)d_in[12];
    const float* bnv_g = (const float*)d_in[13];
    const float* bnv_b = (const float*)d_in[14];
    const float* pq_w  = (const float*)d_in[15];
    const float* pq_b  = (const float*)d_in[16];
    const float* pk_w  = (const float*)d_in[17];
    const float* pk_b  = (const float*)d_in[18];
    const float* pv_w  = (const float*)d_in[19];
    const float* pv_b  = (const float*)d_in[20];
    const float* ln2_g = (const float*)d_in[21];
    const float* ln2_b = (const float*)d_in[22];
    const float* ff1_w = (const float*)d_in[23];
    const float* ff1_b = (const float*)d_in[24];
    const float* ff2_w = (const float*)d_in[25];
    const float* ff2_b = (const float*)d_in[26];
    float* out = (float*)d_out;

    float *xn, *qc, *kc, *vc, *Q, *K, *V, *x2, *h1, *S, *St;
    cudaGetSymbolAddress((void**)&xn, g_xn);
    cudaGetSymbolAddress((void**)&qc, g_qc);
    cudaGetSymbolAddress((void**)&kc, g_kc);
    cudaGetSymbolAddress((void**)&vc, g_vc);
    cudaGetSymbolAddress((void**)&Q,  g_Q);
    cudaGetSymbolAddress((void**)&K,  g_K);
    cudaGetSymbolAddress((void**)&V,  g_V);
    cudaGetSymbolAddress((void**)&x2, g_x2);
    cudaGetSymbolAddress((void**)&h1, g_h1);
    cudaGetSymbolAddress((void**)&S,  g_S);
    cudaGetSymbolAddress((void**)&St, g_St);

    const int BS_X  = NTOK * DIM;
    const int BS_KV = NKV * DIM;

    // 1. LN1
    ln_kernel<<<BATCH * NTOK, 128>>>(x, ln1_g, ln1_b, xn);

    // 2. Depthwise convs (+bias+BN)
    dwconv_bn<<<BATCH * 1024, DIM>>>(xn, dwq_w, dwq_b, bnq_g, bnq_b, qc, 32, 32, 1, 0,    BS_X, 0,    BS_X);
    dwconv_bn<<<BATCH * 256,  DIM>>>(xn, dwq_w, dwq_b, bnq_g, bnq_b, qc, 16, 16, 1, 1024, BS_X, 1024, BS_X);
    dwconv_bn<<<BATCH * 256,  DIM>>>(xn, dwk_w, dwk_b, bnk_g, bnk_b, kc, 32, 16, 2, 0,    BS_X, 0,    BS_KV);
    dwconv_bn<<<BATCH * 64,   DIM>>>(xn, dwk_w, dwk_b, bnk_g, bnk_b, kc, 16, 8,  2, 1024, BS_X, 256,  BS_KV);
    dwconv_bn<<<BATCH * 256,  DIM>>>(xn, dwv_w, dwv_b, bnv_g, bnv_b, vc, 32, 16, 2, 0,    BS_X, 0,    BS_KV);
    dwconv_bn<<<BATCH * 64,   DIM>>>(xn, dwv_w, dwv_b, bnv_g, bnv_b, vc, 16, 8,  2, 1024, BS_X, 256,  BS_KV);

    // 3. Q/K/V projections (TF32 tensor cores)
    gemm_tf32<0><<<dim3(3, 320), 256>>>(qc, pq_w, pq_b, nullptr, Q, BATCH * NTOK, DIM, DIM);
    gemm_tf32<0><<<dim3(3, 80),  256>>>(kc, pk_w, pk_b, nullptr, K, BATCH * NKV,  DIM, DIM);
    gemm_tf32<0><<<dim3(3, 80),  256>>>(vc, pv_w, pv_b, nullptr, V, BATCH * NKV,  DIM, DIM);

    // 4. Attention
    attn_scores<<<dim3(5, 16, BATCH * HEADS), 256>>>(Q, K, S,  0,    0,   NS_, NKV);
    attn_scores<<<dim3(1, 4,  BATCH * HEADS), 256>>>(Q, K, St, 1024, 256, NT_, 64);
    softmax_rows<<<(BATCH * HEADS * NS_) / 8, 256>>>(S,  BATCH * HEADS * NS_, NKV);
    softmax_rows<<<(BATCH * HEADS * NT_) / 8, 256>>>(St, BATCH * HEADS * NT_, 64);
    attn_av<<<dim3(8, BATCH * HEADS), 256>>>(S,  V, x, x2, 0,    0,   NS_, NKV);
    attn_av<<<dim3(2, BATCH * HEADS), 256>>>(St, V, x, x2, 1024, 256, NT_, 64);

    // 5. LN2 + FFN (TF32; residual fused into FFN2 epilogue, writes d_out)
    ln_kernel<<<BATCH * NTOK, 128>>>(x2, ln2_g, ln2_b, xn);
    gemm_tf32<1><<<dim3(12, 320), 256>>>(xn, ff1_w, ff1_b, nullptr, h1, BATCH * NTOK, FFDIM, DIM);
    gemm_tf32<2><<<dim3(3, 320),  256>>>(h1, ff2_w, ff2_b, x2, out, BATCH * NTOK, DIM, FFDIM);
}

// round 4
// speedup vs baseline: 1.9733x; 1.1951x over previous
#include <cuda_runtime.h>
#include <math.h>
#include <stdint.h>

// ---------------------------------------------------------------------------
// Problem constants
// ---------------------------------------------------------------------------
#define BATCH   32
#define NTOK    1280
#define NS_     1024
#define NT_     256
#define DIM     384
#define HEADS   8
#define HDIM    48
#define NKV     320
#define FFDIM   1536
#define ATT_SCALE 0.14433756729740643f

// ---------------------------------------------------------------------------
// Scratch (device globals; no allocation allowed)
// ---------------------------------------------------------------------------
__device__ float g_xn [BATCH * NTOK * DIM];
__device__ float g_qc [BATCH * NTOK * DIM];
__device__ float g_kc [BATCH * NKV  * DIM];
__device__ float g_vc [BATCH * NKV  * DIM];
__device__ float g_Q  [BATCH * NTOK * DIM];
__device__ float g_K  [BATCH * NKV  * DIM];
__device__ float g_V  [BATCH * NKV  * DIM];
__device__ float g_x2 [BATCH * NTOK * DIM];
__device__ float g_h1 [BATCH * NTOK * FFDIM];

// ---------------------------------------------------------------------------
// Helpers
// ---------------------------------------------------------------------------
__device__ __forceinline__ float tf32r(float x) {
    uint32_t u;
    asm("cvt.rna.tf32.f32 %0, %1;" : "=r"(u) : "f"(x));
    return __uint_as_float(u);
}

__device__ __forceinline__ void mma_tf32(float* c, const uint32_t* a, const uint32_t* b) {
    asm volatile(
        "mma.sync.aligned.m16n8k8.row.col.f32.tf32.tf32.f32 "
        "{%0,%1,%2,%3}, {%4,%5,%6,%7}, {%8,%9}, {%0,%1,%2,%3};"
        : "+f"(c[0]), "+f"(c[1]), "+f"(c[2]), "+f"(c[3])
        : "r"(a[0]), "r"(a[1]), "r"(a[2]), "r"(a[3]), "r"(b[0]), "r"(b[1]));
}

// ---------------------------------------------------------------------------
// LayerNorm: one block (128 threads) per token
// ---------------------------------------------------------------------------
__global__ void ln_kernel(const float* __restrict__ x, const float* __restrict__ g,
                          const float* __restrict__ b, float* __restrict__ out) {
    int tok = blockIdx.x;
    int tid = threadIdx.x;
    const float* xp = x + (size_t)tok * DIM;
    float v0 = xp[tid], v1 = xp[tid + 128], v2 = xp[tid + 256];
    float s  = v0 + v1 + v2;
    float ss = v0 * v0 + v1 * v1 + v2 * v2;
#pragma unroll
    for (int o = 16; o > 0; o >>= 1) {
        s  += __shfl_xor_sync(0xffffffffu, s,  o);
        ss += __shfl_xor_sync(0xffffffffu, ss, o);
    }
    __shared__ float sh_s[4], sh_ss[4];
    if ((tid & 31) == 0) { sh_s[tid >> 5] = s; sh_ss[tid >> 5] = ss; }
    __syncthreads();
    float ts  = sh_s[0]  + sh_s[1]  + sh_s[2]  + sh_s[3];
    float tss = sh_ss[0] + sh_ss[1] + sh_ss[2] + sh_ss[3];
    float mean = ts * (1.0f / DIM);
    float var  = tss * (1.0f / DIM) - mean * mean;
    float rstd = rsqrtf(var + 1e-5f);
    float* op = out + (size_t)tok * DIM;
    op[tid]       = (v0 - mean) * rstd * g[tid]       + b[tid];
    op[tid + 128] = (v1 - mean) * rstd * g[tid + 128] + b[tid + 128];
    op[tid + 256] = (v2 - mean) * rstd * g[tid + 256] + b[tid + 256];
}

// ---------------------------------------------------------------------------
// Depthwise 3x3 conv + bias + BN affine in token layout [b, tok, c]
// ---------------------------------------------------------------------------
__global__ void dwconv_bn(const float* __restrict__ in, const float* __restrict__ w,
                          const float* __restrict__ cb, const float* __restrict__ bng,
                          const float* __restrict__ bnb, float* __restrict__ out,
                          int hw_in, int hw_out, int stride,
                          int in_boff, int in_bstride, int out_boff, int out_bstride) {
    int c   = threadIdx.x;
    int blk = blockIdx.x;
    int ox  = blk % hw_out;
    int oy  = (blk / hw_out) % hw_out;
    int b   = blk / (hw_out * hw_out);
    const float* ip = in + (size_t)b * in_bstride + (size_t)in_boff * DIM;
    float acc = cb[c];
#pragma unroll
    for (int ky = 0; ky < 3; ky++) {
        int iy = oy * stride - 1 + ky;
        if (iy < 0 || iy >= hw_in) continue;
#pragma unroll
        for (int kx = 0; kx < 3; kx++) {
            int ix = ox * stride - 1 + kx;
            if (ix < 0 || ix >= hw_in) continue;
            acc += ip[(size_t)(iy * hw_in + ix) * DIM + c] * w[c * 9 + ky * 3 + kx];
        }
    }
    float sc = bng[c] * rsqrtf(1.0f + 1e-5f);
    out[(size_t)b * out_bstride + (size_t)(out_boff + oy * hw_out + ox) * DIM + c]
        = acc * sc + bnb[c];
}

// ---------------------------------------------------------------------------
// TF32 tensor-core GEMM (128x128x16 CTA tile, 8 warps, 64x32 warp tiles)
// EPI: 0 = bias, 1 = bias + exact GELU, 2 = bias + residual add.
// ---------------------------------------------------------------------------
template<int EPI>
__global__ void __launch_bounds__(256)
gemm_tf32(const float* __restrict__ A, const float* __restrict__ W,
          const float* __restrict__ bias, const float* __restrict__ res,
          float* __restrict__ C, int M, int N, int K) {
    __shared__ float As[16][136];
    __shared__ float Bs[16][136];

    int n0 = blockIdx.x * 128, m0 = blockIdx.y * 128;
    int t = threadIdx.x;
    int lm = t & 127, lk = (t >> 7) * 8;

    const float* Aload = A + (size_t)(m0 + lm) * K + lk;
    const float* Bload = W + (size_t)(n0 + lm) * K + lk;

    int lane = t & 31, g = lane >> 2, tig = lane & 3;
    int w = t >> 5;
    int wm = (w >> 2) * 64, wn = (w & 3) * 32;

    float acc[4][4][4] = {};

    {
        float4 a0v = *(const float4*)(Aload);
        float4 a1v = *(const float4*)(Aload + 4);
        float4 b0v = *(const float4*)(Bload);
        float4 b1v = *(const float4*)(Bload + 4);
        As[lk + 0][lm] = tf32r(a0v.x); As[lk + 1][lm] = tf32r(a0v.y);
        As[lk + 2][lm] = tf32r(a0v.z); As[lk + 3][lm] = tf32r(a0v.w);
        As[lk + 4][lm] = tf32r(a1v.x); As[lk + 5][lm] = tf32r(a1v.y);
        As[lk + 6][lm] = tf32r(a1v.z); As[lk + 7][lm] = tf32r(a1v.w);
        Bs[lk + 0][lm] = tf32r(b0v.x); Bs[lk + 1][lm] = tf32r(b0v.y);
        Bs[lk + 2][lm] = tf32r(b0v.z); Bs[lk + 3][lm] = tf32r(b0v.w);
        Bs[lk + 4][lm] = tf32r(b1v.x); Bs[lk + 5][lm] = tf32r(b1v.y);
        Bs[lk + 6][lm] = tf32r(b1v.z); Bs[lk + 7][lm] = tf32r(b1v.w);
    }
    __syncthreads();

    for (int k0 = 0; k0 < K; k0 += 16) {
        bool pref = (k0 + 16) < K;
        float4 na0, na1, nb0, nb1;
        if (pref) {
            na0 = *(const float4*)(Aload + k0 + 16);
            na1 = *(const float4*)(Aload + k0 + 20);
            nb0 = *(const float4*)(Bload + k0 + 16);
            nb1 = *(const float4*)(Bload + k0 + 20);
        }
#pragma unroll
        for (int ks = 0; ks < 16; ks += 8) {
            uint32_t af[4][4], bf[4][2];
#pragma unroll
            for (int mt = 0; mt < 4; mt++) {
                int r = wm + mt * 16 + g;
                af[mt][0] = __float_as_uint(As[ks + tig    ][r]);
                af[mt][1] = __float_as_uint(As[ks + tig    ][r + 8]);
                af[mt][2] = __float_as_uint(As[ks + tig + 4][r]);
                af[mt][3] = __float_as_uint(As[ks + tig + 4][r + 8]);
            }
#pragma unroll
            for (int nt = 0; nt < 4; nt++) {
                int c2 = wn + nt * 8 + g;
                bf[nt][0] = __float_as_uint(Bs[ks + tig    ][c2]);
                bf[nt][1] = __float_as_uint(Bs[ks + tig + 4][c2]);
            }
#pragma unroll
            for (int mt = 0; mt < 4; mt++)
#pragma unroll
                for (int nt = 0; nt < 4; nt++)
                    mma_tf32(acc[mt][nt], af[mt], bf[nt]);
        }
        if (pref) {
            __syncthreads();
            As[lk + 0][lm] = tf32r(na0.x); As[lk + 1][lm] = tf32r(na0.y);
            As[lk + 2][lm] = tf32r(na0.z); As[lk + 3][lm] = tf32r(na0.w);
            As[lk + 4][lm] = tf32r(na1.x); As[lk + 5][lm] = tf32r(na1.y);
            As[lk + 6][lm] = tf32r(na1.z); As[lk + 7][lm] = tf32r(na1.w);
            Bs[lk + 0][lm] = tf32r(nb0.x); Bs[lk + 1][lm] = tf32r(nb0.y);
            Bs[lk + 2][lm] = tf32r(nb0.z); Bs[lk + 3][lm] = tf32r(nb0.w);
            Bs[lk + 4][lm] = tf32r(nb1.x); Bs[lk + 5][lm] = tf32r(nb1.y);
            Bs[lk + 6][lm] = tf32r(nb1.z); Bs[lk + 7][lm] = tf32r(nb1.w);
            __syncthreads();
        }
    }

#pragma unroll
    for (int mt = 0; mt < 4; mt++) {
#pragma unroll
        for (int nt = 0; nt < 4; nt++) {
            int row = m0 + wm + mt * 16 + g;
            int col = n0 + wn + nt * 8 + 2 * tig;
#pragma unroll
            for (int half = 0; half < 2; half++) {
                int r = row + half * 8;
                float v0 = acc[mt][nt][half * 2 + 0] + bias[col];
                float v1 = acc[mt][nt][half * 2 + 1] + bias[col + 1];
                if (EPI == 1) {
                    v0 = 0.5f * v0 * (1.0f + erff(v0 * 0.70710678118654752f));
                    v1 = 0.5f * v1 * (1.0f + erff(v1 * 0.70710678118654752f));
                }
                size_t gi = (size_t)r * N + col;
                if (EPI == 2) { v0 += res[gi]; v1 += res[gi + 1]; }
                *(float2*)(C + gi) = make_float2(v0, v1);
            }
        }
    }
}

// ---------------------------------------------------------------------------
// Fused flash attention (TF32 tensor cores) + residual.
// CTA = 64 queries of one (b,h); 4 warps, 16 query rows each; KV tiles of 64.
// Online softmax in registers; P staged through per-warp private smem.
// x2 = x + softmax(Q K^T * scale) V   (scale folded into Q)
// grid: (nq/64, B*H)
// ---------------------------------------------------------------------------
__global__ void __launch_bounds__(128)
attn_fused(const float* __restrict__ Q, const float* __restrict__ Kg,
           const float* __restrict__ Vg, const float* __restrict__ x,
           float* __restrict__ x2, int q_base, int kv_base, int nkv) {
    __shared__ __align__(16) float Ks[48][72];      // [d][kv], tf32
    __shared__ __align__(16) float Vs[64][56];      // [kv][d], tf32
    __shared__ __align__(16) float Pool[4352];      // Qs[64][49] aliased with Ps[4][16][68]

    int bh = blockIdx.y, b = bh >> 3, h = bh & 7;
    int q0 = blockIdx.x * 64;
    int t = threadIdx.x;
    int w = t >> 5, lane = t & 31, g = lane >> 2, tig = lane & 3;

    // stage Q tile (scaled, tf32) into Pool as Qs[row][d], stride 49
    for (int idx = t; idx < 768; idx += 128) {
        int r = idx / 12, c4 = (idx % 12) * 4;
        float4 v = *(const float4*)(Q + (size_t)(b * NTOK + q_base + q0 + r) * DIM + h * HDIM + c4);
        float* q = Pool + r * 49 + c4;
        q[0] = tf32r(v.x * ATT_SCALE); q[1] = tf32r(v.y * ATT_SCALE);
        q[2] = tf32r(v.z * ATT_SCALE); q[3] = tf32r(v.w * ATT_SCALE);
    }
    __syncthreads();

    // Q fragments (kept in registers for the whole kv loop)
    uint32_t qf[6][4];
    int wrow = w * 16;
#pragma unroll
    for (int kt = 0; kt < 6; kt++) {
        qf[kt][0] = __float_as_uint(Pool[(wrow + g    ) * 49 + kt * 8 + tig    ]);
        qf[kt][1] = __float_as_uint(Pool[(wrow + g + 8) * 49 + kt * 8 + tig    ]);
        qf[kt][2] = __float_as_uint(Pool[(wrow + g    ) * 49 + kt * 8 + tig + 4]);
        qf[kt][3] = __float_as_uint(Pool[(wrow + g + 8) * 49 + kt * 8 + tig + 4]);
    }

    float m0r = -1e30f, m1r = -1e30f, l0 = 0.0f, l1 = 0.0f;
    float oacc[6][4] = {};
    float* Ps = Pool + w * (16 * 68);               // per-warp private patch

    for (int k0 = 0; k0 < nkv; k0 += 64) {
        __syncthreads();                            // covers Qs reads / prev Ks,Vs reads
        for (int idx = t; idx < 768; idx += 128) {  // K tile -> Ks[d][kv]
            int r = idx / 12, c4 = (idx % 12) * 4;
            float4 v = *(const float4*)(Kg + (size_t)(b * NKV + kv_base + k0 + r) * DIM + h * HDIM + c4);
            Ks[c4 + 0][r] = tf32r(v.x); Ks[c4 + 1][r] = tf32r(v.y);
            Ks[c4 + 2][r] = tf32r(v.z); Ks[c4 + 3][r] = tf32r(v.w);
        }
        for (int idx = t; idx < 768; idx += 128) {  // V tile -> Vs[kv][d]
            int r = idx / 12, c4 = (idx % 12) * 4;
            float4 v = *(const float4*)(Vg + (size_t)(b * NKV + kv_base + k0 + r) * DIM + h * HDIM + c4);
            float* p = &Vs[r][c4];
            p[0] = tf32r(v.x); p[1] = tf32r(v.y); p[2] = tf32r(v.z); p[3] = tf32r(v.w);
        }
        __syncthreads();

        // S tile = Q @ K^T   (16 rows x 64 cols per warp)
        float sf[8][4] = {};
#pragma unroll
        for (int kt = 0; kt < 6; kt++) {
            uint32_t bf[8][2];
#pragma unroll
            for (int nt = 0; nt < 8; nt++) {
                bf[nt][0] = __float_as_uint(Ks[kt * 8 + tig    ][nt * 8 + g]);
                bf[nt][1] = __float_as_uint(Ks[kt * 8 + tig + 4][nt * 8 + g]);
            }
#pragma unroll
            for (int nt = 0; nt < 8; nt++)
                mma_tf32(sf[nt], qf[kt], bf[nt]);
        }

        // online softmax: rows g (c0,c1) and g+8 (c2,c3)
        float tm0 = -1e30f, tm1 = -1e30f;
#pragma unroll
        for (int nt = 0; nt < 8; nt++) {
            tm0 = fmaxf(tm0, fmaxf(sf[nt][0], sf[nt][1]));
            tm1 = fmaxf(tm1, fmaxf(sf[nt][2], sf[nt][3]));
        }
        tm0 = fmaxf(tm0, __shfl_xor_sync(0xffffffffu, tm0, 1));
        tm0 = fmaxf(tm0, __shfl_xor_sync(0xffffffffu, tm0, 2));
        tm1 = fmaxf(tm1, __shfl_xor_sync(0xffffffffu, tm1, 1));
        tm1 = fmaxf(tm1, __shfl_xor_sync(0xffffffffu, tm1, 2));
        float nm0 = fmaxf(m0r, tm0), nm1 = fmaxf(m1r, tm1);
        float f0 = __expf(m0r - nm0), f1 = __expf(m1r - nm1);
        m0r = nm0; m1r = nm1;
        l0 *= f0; l1 *= f1;
#pragma unroll
        for (int nt = 0; nt < 6; nt++) {
            oacc[nt][0] *= f0; oacc[nt][1] *= f0;
            oacc[nt][2] *= f1; oacc[nt][3] *= f1;
        }
#pragma unroll
        for (int nt = 0; nt < 8; nt++) {
            float p0 = __expf(sf[nt][0] - m0r);
            float p1 = __expf(sf[nt][1] - m0r);
            float p2 = __expf(sf[nt][2] - m1r);
            float p3 = __expf(sf[nt][3] - m1r);
            l0 += p0 + p1; l1 += p2 + p3;
            Ps[(g    ) * 68 + nt * 8 + 2 * tig    ] = tf32r(p0);
            Ps[(g    ) * 68 + nt * 8 + 2 * tig + 1] = tf32r(p1);
            Ps[(g + 8) * 68 + nt * 8 + 2 * tig    ] = tf32r(p2);
            Ps[(g + 8) * 68 + nt * 8 + 2 * tig + 1] = tf32r(p3);
        }
        __syncwarp();

        // O += P @ V
#pragma unroll
        for (int kt = 0; kt < 8; kt++) {
            uint32_t pa[4];
            pa[0] = __float_as_uint(Ps[(g    ) * 68 + kt * 8 + tig    ]);
            pa[1] = __float_as_uint(Ps[(g + 8) * 68 + kt * 8 + tig    ]);
            pa[2] = __float_as_uint(Ps[(g    ) * 68 + kt * 8 + tig + 4]);
            pa[3] = __float_as_uint(Ps[(g + 8) * 68 + kt * 8 + tig + 4]);
#pragma unroll
            for (int nt = 0; nt < 6; nt++) {
                uint32_t vb[2];
                vb[0] = __float_as_uint(Vs[kt * 8 + tig    ][nt * 8 + g]);
                vb[1] = __float_as_uint(Vs[kt * 8 + tig + 4][nt * 8 + g]);
                mma_tf32(oacc[nt], pa, vb);
            }
        }
        __syncwarp();
    }

    // epilogue: normalize + residual
    l0 += __shfl_xor_sync(0xffffffffu, l0, 1);
    l0 += __shfl_xor_sync(0xffffffffu, l0, 2);
    l1 += __shfl_xor_sync(0xffffffffu, l1, 1);
    l1 += __shfl_xor_sync(0xffffffffu, l1, 2);
    float inv0 = 1.0f / l0, inv1 = 1.0f / l1;
    int r0 = b * NTOK + q_base + q0 + wrow + g;
#pragma unroll
    for (int nt = 0; nt < 6; nt++) {
        int col = h * HDIM + nt * 8 + 2 * tig;
        size_t gi0 = (size_t)r0 * DIM + col;
        size_t gi1 = (size_t)(r0 + 8) * DIM + col;
        float2 xa = *(const float2*)(x + gi0);
        float2 xb = *(const float2*)(x + gi1);
        *(float2*)(x2 + gi0) = make_float2(xa.x + oacc[nt][0] * inv0, xa.y + oacc[nt][1] * inv0);
        *(float2*)(x2 + gi1) = make_float2(xb.x + oacc[nt][2] * inv1, xb.y + oacc[nt][3] * inv1);
    }
}

// ---------------------------------------------------------------------------
// Launch
// ---------------------------------------------------------------------------
extern "C" void kernel_launch(void* const* d_in, const int* in_sizes, int n_in,
                              void* d_out, int out_size) {
    (void)in_sizes; (void)n_in; (void)out_size;
    const float* x     = (const float*)d_in[0];
    const float* ln1_g = (const float*)d_in[1];
    const float* ln1_b = (const float*)d_in[2];
    const float* dwq_w = (const float*)d_in[3];
    const float* dwq_b = (const float*)d_in[4];
    const float* bnq_g = (const float*)d_in[5];
    const float* bnq_b = (const float*)d_in[6];
    const float* dwk_w = (const float*)d_in[7];
    const float* dwk_b = (const float*)d_in[8];
    const float* bnk_g = (const float*)d_in[9];
    const float* bnk_b = (const float*)d_in[10];
    const float* dwv_w = (const float*)d_in[11];
    const float* dwv_b = (const float*)d_in[12];
    const float* bnv_g = (const float*)d_in[13];
    const float* bnv_b = (const float*)d_in[14];
    const float* pq_w  = (const float*)d_in[15];
    const float* pq_b  = (const float*)d_in[16];
    const float* pk_w  = (const float*)d_in[17];
    const float* pk_b  = (const float*)d_in[18];
    const float* pv_w  = (const float*)d_in[19];
    const float* pv_b  = (const float*)d_in[20];
    const float* ln2_g = (const float*)d_in[21];
    const float* ln2_b = (const float*)d_in[22];
    const float* ff1_w = (const float*)d_in[23];
    const float* ff1_b = (const float*)d_in[24];
    const float* ff2_w = (const float*)d_in[25];
    const float* ff2_b = (const float*)d_in[26];
    float* out = (float*)d_out;

    float *xn, *qc, *kc, *vc, *Q, *K, *V, *x2, *h1;
    cudaGetSymbolAddress((void**)&xn, g_xn);
    cudaGetSymbolAddress((void**)&qc, g_qc);
    cudaGetSymbolAddress((void**)&kc, g_kc);
    cudaGetSymbolAddress((void**)&vc, g_vc);
    cudaGetSymbolAddress((void**)&Q,  g_Q);
    cudaGetSymbolAddress((void**)&K,  g_K);
    cudaGetSymbolAddress((void**)&V,  g_V);
    cudaGetSymbolAddress((void**)&x2, g_x2);
    cudaGetSymbolAddress((void**)&h1, g_h1);

    const int BS_X  = NTOK * DIM;
    const int BS_KV = NKV * DIM;

    // 1. LN1
    ln_kernel<<<BATCH * NTOK, 128>>>(x, ln1_g, ln1_b, xn);

    // 2. Depthwise convs (+bias+BN)
    dwconv_bn<<<BATCH * 1024, DIM>>>(xn, dwq_w, dwq_b, bnq_g, bnq_b, qc, 32, 32, 1, 0,    BS_X, 0,    BS_X);
    dwconv_bn<<<BATCH * 256,  DIM>>>(xn, dwq_w, dwq_b, bnq_g, bnq_b, qc, 16, 16, 1, 1024, BS_X, 1024, BS_X);
    dwconv_bn<<<BATCH * 256,  DIM>>>(xn, dwk_w, dwk_b, bnk_g, bnk_b, kc, 32, 16, 2, 0,    BS_X, 0,    BS_KV);
    dwconv_bn<<<BATCH * 64,   DIM>>>(xn, dwk_w, dwk_b, bnk_g, bnk_b, kc, 16, 8,  2, 1024, BS_X, 256,  BS_KV);
    dwconv_bn<<<BATCH * 256,  DIM>>>(xn, dwv_w, dwv_b, bnv_g, bnv_b, vc, 32, 16, 2, 0,    BS_X, 0,    BS_KV);
    dwconv_bn<<<BATCH * 64,   DIM>>>(xn, dwv_w, dwv_b, bnv_g, bnv_b, vc, 16, 8,  2, 1024, BS_X, 256,  BS_KV);

    // 3. Q/K/V projections (TF32 tensor cores)
    gemm_tf32<0><<<dim3(3, 320), 256>>>(qc, pq_w, pq_b, nullptr, Q, BATCH * NTOK, DIM, DIM);
    gemm_tf32<0><<<dim3(3, 80),  256>>>(kc, pk_w, pk_b, nullptr, K, BATCH * NKV,  DIM, DIM);
    gemm_tf32<0><<<dim3(3, 80),  256>>>(vc, pv_w, pv_b, nullptr, V, BATCH * NKV,  DIM, DIM);

    // 4. Fused flash attention (+ residual), search then target
    attn_fused<<<dim3(16, BATCH * HEADS), 128>>>(Q, K, V, x, x2, 0,    0,   NKV);
    attn_fused<<<dim3(4,  BATCH * HEADS), 128>>>(Q, K, V, x, x2, 1024, 256, 64);

    // 5. LN2 + FFN (TF32; residual fused into FFN2 epilogue, writes d_out)
    ln_kernel<<<BATCH * NTOK, 128>>>(x2, ln2_g, ln2_b, xn);
    gemm_tf32<1><<<dim3(12, 320), 256>>>(xn, ff1_w, ff1_b, nullptr, h1, BATCH * NTOK, FFDIM, DIM);
    gemm_tf32<2><<<dim3(3, 320),  256>>>(h1, ff2_w, ff2_b, x2, out, BATCH * NTOK, DIM, FFDIM);
}

// round 5
// speedup vs baseline: 2.5706x; 1.3026x over previous
#include <cuda_runtime.h>
#include <math.h>
#include <stdint.h>

// ---------------------------------------------------------------------------
// Problem constants
// ---------------------------------------------------------------------------
#define BATCH   32
#define NTOK    1280
#define NS_     1024
#define NT_     256
#define DIM     384
#define HEADS   8
#define HDIM    48
#define NKV     320
#define FFDIM   1536
#define ATT_SCALE 0.14433756729740643f

// ---------------------------------------------------------------------------
// Scratch (device globals; no allocation allowed)
// ---------------------------------------------------------------------------
__device__ float g_xn [BATCH * NTOK * DIM];
__device__ float g_qc [BATCH * NTOK * DIM];
__device__ float g_kc [BATCH * NKV  * DIM];
__device__ float g_vc [BATCH * NKV  * DIM];
__device__ float g_Q  [BATCH * NTOK * DIM];
__device__ float g_K  [BATCH * NKV  * DIM];
__device__ float g_V  [BATCH * NKV  * DIM];
__device__ float g_x2 [BATCH * NTOK * DIM];
__device__ float g_h1 [BATCH * NTOK * FFDIM];
__device__ float g_wq [DIM * DIM];       // tf32-rounded weights
__device__ float g_wk [DIM * DIM];
__device__ float g_wv [DIM * DIM];
__device__ float g_w1 [FFDIM * DIM];
__device__ float g_w2 [DIM * FFDIM];

// ---------------------------------------------------------------------------
// Helpers
// ---------------------------------------------------------------------------
__device__ __forceinline__ float tf32r(float x) {
    uint32_t u;
    asm("cvt.rna.tf32.f32 %0, %1;" : "=r"(u) : "f"(x));
    return __uint_as_float(u);
}

__device__ __forceinline__ void mma_tf32(float* c, const uint32_t* a, const uint32_t* b) {
    asm volatile(
        "mma.sync.aligned.m16n8k8.row.col.f32.tf32.tf32.f32 "
        "{%0,%1,%2,%3}, {%4,%5,%6,%7}, {%8,%9}, {%0,%1,%2,%3};"
        : "+f"(c[0]), "+f"(c[1]), "+f"(c[2]), "+f"(c[3])
        : "r"(a[0]), "r"(a[1]), "r"(a[2]), "r"(a[3]), "r"(b[0]), "r"(b[1]));
}

#define CP_A16(dst, src) \
    asm volatile("cp.async.ca.shared.global [%0], [%1], 16;" :: "r"(dst), "l"(src))
#define CP_COMMIT() asm volatile("cp.async.commit_group;")
#define CP_WAIT1()  asm volatile("cp.async.wait_group 1;")

// ---------------------------------------------------------------------------
// Weight conversion to tf32 (grid-stride)
// ---------------------------------------------------------------------------
__global__ void cvt_tf32(const float* __restrict__ src, float* __restrict__ dst, int n) {
    int i = blockIdx.x * 256 + threadIdx.x;
    if (i < n) dst[i] = tf32r(src[i]);
}

// ---------------------------------------------------------------------------
// LayerNorm: one block (128 threads) per token; output tf32-rounded
// ---------------------------------------------------------------------------
__global__ void ln_kernel(const float* __restrict__ x, const float* __restrict__ g,
                          const float* __restrict__ b, float* __restrict__ out) {
    int tok = blockIdx.x;
    int tid = threadIdx.x;
    const float* xp = x + (size_t)tok * DIM;
    float v0 = xp[tid], v1 = xp[tid + 128], v2 = xp[tid + 256];
    float s  = v0 + v1 + v2;
    float ss = v0 * v0 + v1 * v1 + v2 * v2;
#pragma unroll
    for (int o = 16; o > 0; o >>= 1) {
        s  += __shfl_xor_sync(0xffffffffu, s,  o);
        ss += __shfl_xor_sync(0xffffffffu, ss, o);
    }
    __shared__ float sh_s[4], sh_ss[4];
    if ((tid & 31) == 0) { sh_s[tid >> 5] = s; sh_ss[tid >> 5] = ss; }
    __syncthreads();
    float ts  = sh_s[0]  + sh_s[1]  + sh_s[2]  + sh_s[3];
    float tss = sh_ss[0] + sh_ss[1] + sh_ss[2] + sh_ss[3];
    float mean = ts * (1.0f / DIM);
    float var  = tss * (1.0f / DIM) - mean * mean;
    float rstd = rsqrtf(var + 1e-5f);
    float* op = out + (size_t)tok * DIM;
    op[tid]       = tf32r((v0 - mean) * rstd * g[tid]       + b[tid]);
    op[tid + 128] = tf32r((v1 - mean) * rstd * g[tid + 128] + b[tid + 128]);
    op[tid + 256] = tf32r((v2 - mean) * rstd * g[tid + 256] + b[tid + 256]);
}

// ---------------------------------------------------------------------------
// Depthwise 3x3 conv + bias + BN affine; output tf32-rounded
// ---------------------------------------------------------------------------
__global__ void dwconv_bn(const float* __restrict__ in, const float* __restrict__ w,
                          const float* __restrict__ cb, const float* __restrict__ bng,
                          const float* __restrict__ bnb, float* __restrict__ out,
                          int hw_in, int hw_out, int stride,
                          int in_boff, int in_bstride, int out_boff, int out_bstride) {
    int c   = threadIdx.x;
    int blk = blockIdx.x;
    int ox  = blk % hw_out;
    int oy  = (blk / hw_out) % hw_out;
    int b   = blk / (hw_out * hw_out);
    const float* ip = in + (size_t)b * in_bstride + (size_t)in_boff * DIM;
    float acc = cb[c];
#pragma unroll
    for (int ky = 0; ky < 3; ky++) {
        int iy = oy * stride - 1 + ky;
        if (iy < 0 || iy >= hw_in) continue;
#pragma unroll
        for (int kx = 0; kx < 3; kx++) {
            int ix = ox * stride - 1 + kx;
            if (ix < 0 || ix >= hw_in) continue;
            acc += ip[(size_t)(iy * hw_in + ix) * DIM + c] * w[c * 9 + ky * 3 + kx];
        }
    }
    float sc = bng[c] * rsqrtf(1.0f + 1e-5f);
    out[(size_t)b * out_bstride + (size_t)(out_boff + oy * hw_out + ox) * DIM + c]
        = tf32r(acc * sc + bnb[c]);
}

// ---------------------------------------------------------------------------
// cp.async 3-stage TF32 GEMM. Operands must be pre-rounded to tf32 in gmem.
// 128x128x16 CTA tile, 8 warps, 64x32 warp tiles. smem stride 20 (bank-free).
// EPI: 0 = bias (round out), 1 = bias+GELU (round out), 2 = bias+residual.
// Dynamic smem: 3 stages * (2560 + 2560) floats = 61440 B.
// ---------------------------------------------------------------------------
#define GSTG 5120

__device__ __forceinline__ void gemm_load_stage(
    uint32_t smem_u32, const float* Asrc, const float* Bsrc,
    int s, int k0, int row, int kc) {
    uint32_t dA = smem_u32 + (uint32_t)(s * GSTG + row * 20 + kc * 4) * 4u;
    const float* pA = Asrc + k0;
    CP_A16(dA, pA);
    CP_A16(dA + 16u, pA + 4);
    uint32_t dB = smem_u32 + (uint32_t)(s * GSTG + 2560 + row * 20 + kc * 4) * 4u;
    const float* pB = Bsrc + k0;
    CP_A16(dB, pB);
    CP_A16(dB + 16u, pB + 4);
}

template<int EPI>
__global__ void __launch_bounds__(256, 2)
gemm_cp(const float* __restrict__ A, const float* __restrict__ W,
        const float* __restrict__ bias, const float* __restrict__ res,
        float* __restrict__ C, int M, int N, int K) {
    extern __shared__ float smem[];
    uint32_t smem_u32 = (uint32_t)__cvta_generic_to_shared(smem);

    int n0 = blockIdx.x * 128, m0 = blockIdx.y * 128;
    int t = threadIdx.x;
    int row = t >> 1, kc = (t & 1) * 2;

    const float* Asrc = A + (size_t)(m0 + row) * K + kc * 4;
    const float* Bsrc = W + (size_t)(n0 + row) * K + kc * 4;

    int lane = t & 31, g = lane >> 2, tig = lane & 3;
    int w = t >> 5;
    int wm = (w >> 2) * 64, wn = (w & 3) * 32;

    float acc[4][4][4] = {};
    int ntiles = K >> 4;

    gemm_load_stage(smem_u32, Asrc, Bsrc, 0, 0, row, kc);
    CP_COMMIT();
    gemm_load_stage(smem_u32, Asrc, Bsrc, 1, 16, row, kc);
    CP_COMMIT();

    for (int i = 0; i < ntiles; i++) {
        CP_WAIT1();
        __syncthreads();
        if (i + 2 < ntiles)
            gemm_load_stage(smem_u32, Asrc, Bsrc, (i + 2) % 3, (i + 2) * 16, row, kc);
        CP_COMMIT();

        const float* As_ = smem + (i % 3) * GSTG;
        const float* Bs_ = As_ + 2560;
#pragma unroll
        for (int ks = 0; ks < 16; ks += 8) {
            uint32_t af[4][4], bf[4][2];
#pragma unroll
            for (int mt = 0; mt < 4; mt++) {
                int r = wm + mt * 16 + g;
                af[mt][0] = __float_as_uint(As_[r * 20 + ks + tig]);
                af[mt][1] = __float_as_uint(As_[(r + 8) * 20 + ks + tig]);
                af[mt][2] = __float_as_uint(As_[r * 20 + ks + tig + 4]);
                af[mt][3] = __float_as_uint(As_[(r + 8) * 20 + ks + tig + 4]);
            }
#pragma unroll
            for (int nt = 0; nt < 4; nt++) {
                int c2 = wn + nt * 8 + g;
                bf[nt][0] = __float_as_uint(Bs_[c2 * 20 + ks + tig]);
                bf[nt][1] = __float_as_uint(Bs_[c2 * 20 + ks + tig + 4]);
            }
#pragma unroll
            for (int mt = 0; mt < 4; mt++)
#pragma unroll
                for (int nt = 0; nt < 4; nt++)
                    mma_tf32(acc[mt][nt], af[mt], bf[nt]);
        }
    }

    // epilogue
#pragma unroll
    for (int mt = 0; mt < 4; mt++) {
#pragma unroll
        for (int nt = 0; nt < 4; nt++) {
            int rbase = m0 + wm + mt * 16 + g;
            int col = n0 + wn + nt * 8 + 2 * tig;
#pragma unroll
            for (int half = 0; half < 2; half++) {
                int r = rbase + half * 8;
                float v0 = acc[mt][nt][half * 2 + 0] + bias[col];
                float v1 = acc[mt][nt][half * 2 + 1] + bias[col + 1];
                if (EPI == 1) {
                    v0 = 0.5f * v0 * (1.0f + erff(v0 * 0.70710678118654752f));
                    v1 = 0.5f * v1 * (1.0f + erff(v1 * 0.70710678118654752f));
                }
                size_t gi = (size_t)r * N + col;
                if (EPI == 2) {
                    v0 += res[gi]; v1 += res[gi + 1];
                } else {
                    v0 = tf32r(v0); v1 = tf32r(v1);
                }
                *(float2*)(C + gi) = make_float2(v0, v1);
            }
        }
    }
}

// ---------------------------------------------------------------------------
// Fused flash attention (TF32 tensor cores) + residual.
// Q/K/V arrive pre-rounded to tf32; scale applied to S post-mma.
// CTA = 64 queries of one (b,h); 4 warps; KV tiles of 64.
// grid: (nq/64, B*H)
// ---------------------------------------------------------------------------
__global__ void __launch_bounds__(128)
attn_fused(const float* __restrict__ Q, const float* __restrict__ Kg,
           const float* __restrict__ Vg, const float* __restrict__ x,
           float* __restrict__ x2, int q_base, int kv_base, int nkv) {
    __shared__ __align__(16) float Ks[48][72];      // [d][kv]
    __shared__ __align__(16) float Vs[64][56];      // [kv][d]
    __shared__ __align__(16) float Pool[4352];      // Qs[64][49] aliased with Ps[4][16][68]

    int bh = blockIdx.y, b = bh >> 3, h = bh & 7;
    int q0 = blockIdx.x * 64;
    int t = threadIdx.x;
    int w = t >> 5, lane = t & 31, g = lane >> 2, tig = lane & 3;

    for (int idx = t; idx < 768; idx += 128) {
        int r = idx / 12, c4 = (idx % 12) * 4;
        float4 v = *(const float4*)(Q + (size_t)(b * NTOK + q_base + q0 + r) * DIM + h * HDIM + c4);
        float* q = Pool + r * 49 + c4;
        q[0] = v.x; q[1] = v.y; q[2] = v.z; q[3] = v.w;
    }
    __syncthreads();

    uint32_t qf[6][4];
    int wrow = w * 16;
#pragma unroll
    for (int kt = 0; kt < 6; kt++) {
        qf[kt][0] = __float_as_uint(Pool[(wrow + g    ) * 49 + kt * 8 + tig    ]);
        qf[kt][1] = __float_as_uint(Pool[(wrow + g + 8) * 49 + kt * 8 + tig    ]);
        qf[kt][2] = __float_as_uint(Pool[(wrow + g    ) * 49 + kt * 8 + tig + 4]);
        qf[kt][3] = __float_as_uint(Pool[(wrow + g + 8) * 49 + kt * 8 + tig + 4]);
    }

    float m0r = -1e30f, m1r = -1e30f, l0 = 0.0f, l1 = 0.0f;
    float oacc[6][4] = {};
    float* Ps = Pool + w * (16 * 68);

    for (int k0 = 0; k0 < nkv; k0 += 64) {
        __syncthreads();
        for (int idx = t; idx < 768; idx += 128) {
            int r = idx / 12, c4 = (idx % 12) * 4;
            float4 v = *(const float4*)(Kg + (size_t)(b * NKV + kv_base + k0 + r) * DIM + h * HDIM + c4);
            Ks[c4 + 0][r] = v.x; Ks[c4 + 1][r] = v.y;
            Ks[c4 + 2][r] = v.z; Ks[c4 + 3][r] = v.w;
        }
        for (int idx = t; idx < 768; idx += 128) {
            int r = idx / 12, c4 = (idx % 12) * 4;
            float4 v = *(const float4*)(Vg + (size_t)(b * NKV + kv_base + k0 + r) * DIM + h * HDIM + c4);
            float* p = &Vs[r][c4];
            p[0] = v.x; p[1] = v.y; p[2] = v.z; p[3] = v.w;
        }
        __syncthreads();

        float sf[8][4] = {};
#pragma unroll
        for (int kt = 0; kt < 6; kt++) {
            uint32_t bf[8][2];
#pragma unroll
            for (int nt = 0; nt < 8; nt++) {
                bf[nt][0] = __float_as_uint(Ks[kt * 8 + tig    ][nt * 8 + g]);
                bf[nt][1] = __float_as_uint(Ks[kt * 8 + tig + 4][nt * 8 + g]);
            }
#pragma unroll
            for (int nt = 0; nt < 8; nt++)
                mma_tf32(sf[nt], qf[kt], bf[nt]);
        }
#pragma unroll
        for (int nt = 0; nt < 8; nt++) {
            sf[nt][0] *= ATT_SCALE; sf[nt][1] *= ATT_SCALE;
            sf[nt][2] *= ATT_SCALE; sf[nt][3] *= ATT_SCALE;
        }

        float tm0 = -1e30f, tm1 = -1e30f;
#pragma unroll
        for (int nt = 0; nt < 8; nt++) {
            tm0 = fmaxf(tm0, fmaxf(sf[nt][0], sf[nt][1]));
            tm1 = fmaxf(tm1, fmaxf(sf[nt][2], sf[nt][3]));
        }
        tm0 = fmaxf(tm0, __shfl_xor_sync(0xffffffffu, tm0, 1));
        tm0 = fmaxf(tm0, __shfl_xor_sync(0xffffffffu, tm0, 2));
        tm1 = fmaxf(tm1, __shfl_xor_sync(0xffffffffu, tm1, 1));
        tm1 = fmaxf(tm1, __shfl_xor_sync(0xffffffffu, tm1, 2));
        float nm0 = fmaxf(m0r, tm0), nm1 = fmaxf(m1r, tm1);
        float f0 = __expf(m0r - nm0), f1 = __expf(m1r - nm1);
        m0r = nm0; m1r = nm1;
        l0 *= f0; l1 *= f1;
#pragma unroll
        for (int nt = 0; nt < 6; nt++) {
            oacc[nt][0] *= f0; oacc[nt][1] *= f0;
            oacc[nt][2] *= f1; oacc[nt][3] *= f1;
        }
#pragma unroll
        for (int nt = 0; nt < 8; nt++) {
            float p0 = __expf(sf[nt][0] - m0r);
            float p1 = __expf(sf[nt][1] - m0r);
            float p2 = __expf(sf[nt][2] - m1r);
            float p3 = __expf(sf[nt][3] - m1r);
            l0 += p0 + p1; l1 += p2 + p3;
            Ps[(g    ) * 68 + nt * 8 + 2 * tig    ] = tf32r(p0);
            Ps[(g    ) * 68 + nt * 8 + 2 * tig + 1] = tf32r(p1);
            Ps[(g + 8) * 68 + nt * 8 + 2 * tig    ] = tf32r(p2);
            Ps[(g + 8) * 68 + nt * 8 + 2 * tig + 1] = tf32r(p3);
        }
        __syncwarp();

#pragma unroll
        for (int kt = 0; kt < 8; kt++) {
            uint32_t pa[4];
            pa[0] = __float_as_uint(Ps[(g    ) * 68 + kt * 8 + tig    ]);
            pa[1] = __float_as_uint(Ps[(g + 8) * 68 + kt * 8 + tig    ]);
            pa[2] = __float_as_uint(Ps[(g    ) * 68 + kt * 8 + tig + 4]);
            pa[3] = __float_as_uint(Ps[(g + 8) * 68 + kt * 8 + tig + 4]);
#pragma unroll
            for (int nt = 0; nt < 6; nt++) {
                uint32_t vb[2];
                vb[0] = __float_as_uint(Vs[kt * 8 + tig    ][nt * 8 + g]);
                vb[1] = __float_as_uint(Vs[kt * 8 + tig + 4][nt * 8 + g]);
                mma_tf32(oacc[nt], pa, vb);
            }
        }
        __syncwarp();
    }

    l0 += __shfl_xor_sync(0xffffffffu, l0, 1);
    l0 += __shfl_xor_sync(0xffffffffu, l0, 2);
    l1 += __shfl_xor_sync(0xffffffffu, l1, 1);
    l1 += __shfl_xor_sync(0xffffffffu, l1, 2);
    float inv0 = 1.0f / l0, inv1 = 1.0f / l1;
    int r0 = b * NTOK + q_base + q0 + wrow + g;
#pragma unroll
    for (int nt = 0; nt < 6; nt++) {
        int col = h * HDIM + nt * 8 + 2 * tig;
        size_t gi0 = (size_t)r0 * DIM + col;
        size_t gi1 = (size_t)(r0 + 8) * DIM + col;
        float2 xa = *(const float2*)(x + gi0);
        float2 xb = *(const float2*)(x + gi1);
        *(float2*)(x2 + gi0) = make_float2(xa.x + oacc[nt][0] * inv0, xa.y + oacc[nt][1] * inv0);
        *(float2*)(x2 + gi1) = make_float2(xb.x + oacc[nt][2] * inv1, xb.y + oacc[nt][3] * inv1);
    }
}

// ---------------------------------------------------------------------------
// Launch
// ---------------------------------------------------------------------------
extern "C" void kernel_launch(void* const* d_in, const int* in_sizes, int n_in,
                              void* d_out, int out_size) {
    (void)in_sizes; (void)n_in; (void)out_size;
    const float* x     = (const float*)d_in[0];
    const float* ln1_g = (const float*)d_in[1];
    const float* ln1_b = (const float*)d_in[2];
    const float* dwq_w = (const float*)d_in[3];
    const float* dwq_b = (const float*)d_in[4];
    const float* bnq_g = (const float*)d_in[5];
    const float* bnq_b = (const float*)d_in[6];
    const float* dwk_w = (const float*)d_in[7];
    const float* dwk_b = (const float*)d_in[8];
    const float* bnk_g = (const float*)d_in[9];
    const float* bnk_b = (const float*)d_in[10];
    const float* dwv_w = (const float*)d_in[11];
    const float* dwv_b = (const float*)d_in[12];
    const float* bnv_g = (const float*)d_in[13];
    const float* bnv_b = (const float*)d_in[14];
    const float* pq_w  = (const float*)d_in[15];
    const float* pq_b  = (const float*)d_in[16];
    const float* pk_w  = (const float*)d_in[17];
    const float* pk_b  = (const float*)d_in[18];
    const float* pv_w  = (const float*)d_in[19];
    const float* pv_b  = (const float*)d_in[20];
    const float* ln2_g = (const float*)d_in[21];
    const float* ln2_b = (const float*)d_in[22];
    const float* ff1_w = (const float*)d_in[23];
    const float* ff1_b = (const float*)d_in[24];
    const float* ff2_w = (const float*)d_in[25];
    const float* ff2_b = (const float*)d_in[26];
    float* out = (float*)d_out;

    float *xn, *qc, *kc, *vc, *Q, *K, *V, *x2, *h1, *wq, *wk, *wv, *w1, *w2;
    cudaGetSymbolAddress((void**)&xn, g_xn);
    cudaGetSymbolAddress((void**)&qc, g_qc);
    cudaGetSymbolAddress((void**)&kc, g_kc);
    cudaGetSymbolAddress((void**)&vc, g_vc);
    cudaGetSymbolAddress((void**)&Q,  g_Q);
    cudaGetSymbolAddress((void**)&K,  g_K);
    cudaGetSymbolAddress((void**)&V,  g_V);
    cudaGetSymbolAddress((void**)&x2, g_x2);
    cudaGetSymbolAddress((void**)&h1, g_h1);
    cudaGetSymbolAddress((void**)&wq, g_wq);
    cudaGetSymbolAddress((void**)&wk, g_wk);
    cudaGetSymbolAddress((void**)&wv, g_wv);
    cudaGetSymbolAddress((void**)&w1, g_w1);
    cudaGetSymbolAddress((void**)&w2, g_w2);

    static int smem_set = 0;
    if (!smem_set) {
        cudaFuncSetAttribute(gemm_cp<0>, cudaFuncAttributeMaxDynamicSharedMemorySize, 61440);
        cudaFuncSetAttribute(gemm_cp<1>, cudaFuncAttributeMaxDynamicSharedMemorySize, 61440);
        cudaFuncSetAttribute(gemm_cp<2>, cudaFuncAttributeMaxDynamicSharedMemorySize, 61440);
        smem_set = 1;
    }

    const int BS_X  = NTOK * DIM;
    const int BS_KV = NKV * DIM;
    const int NW = DIM * DIM;
    const int NF = FFDIM * DIM;

    // 0. Weight conversion to tf32
    cvt_tf32<<<(NW + 255) / 256, 256>>>(pq_w, wq, NW);
    cvt_tf32<<<(NW + 255) / 256, 256>>>(pk_w, wk, NW);
    cvt_tf32<<<(NW + 255) / 256, 256>>>(pv_w, wv, NW);
    cvt_tf32<<<(NF + 255) / 256, 256>>>(ff1_w, w1, NF);
    cvt_tf32<<<(NF + 255) / 256, 256>>>(ff2_w, w2, NF);

    // 1. LN1 (tf32-rounded output)
    ln_kernel<<<BATCH * NTOK, 128>>>(x, ln1_g, ln1_b, xn);

    // 2. Depthwise convs (+bias+BN, tf32-rounded outputs)
    dwconv_bn<<<BATCH * 1024, DIM>>>(xn, dwq_w, dwq_b, bnq_g, bnq_b, qc, 32, 32, 1, 0,    BS_X, 0,    BS_X);
    dwconv_bn<<<BATCH * 256,  DIM>>>(xn, dwq_w, dwq_b, bnq_g, bnq_b, qc, 16, 16, 1, 1024, BS_X, 1024, BS_X);
    dwconv_bn<<<BATCH * 256,  DIM>>>(xn, dwk_w, dwk_b, bnk_g, bnk_b, kc, 32, 16, 2, 0,    BS_X, 0,    BS_KV);
    dwconv_bn<<<BATCH * 64,   DIM>>>(xn, dwk_w, dwk_b, bnk_g, bnk_b, kc, 16, 8,  2, 1024, BS_X, 256,  BS_KV);
    dwconv_bn<<<BATCH * 256,  DIM>>>(xn, dwv_w, dwv_b, bnv_g, bnv_b, vc, 32, 16, 2, 0,    BS_X, 0,    BS_KV);
    dwconv_bn<<<BATCH * 64,   DIM>>>(xn, dwv_w, dwv_b, bnv_g, bnv_b, vc, 16, 8,  2, 1024, BS_X, 256,  BS_KV);

    // 3. Q/K/V projections (cp.async TF32 GEMM; outputs rounded)
    gemm_cp<0><<<dim3(3, 320), 256, 61440>>>(qc, wq, pq_b, nullptr, Q, BATCH * NTOK, DIM, DIM);
    gemm_cp<0><<<dim3(3, 80),  256, 61440>>>(kc, wk, pk_b, nullptr, K, BATCH * NKV,  DIM, DIM);
    gemm_cp<0><<<dim3(3, 80),  256, 61440>>>(vc, wv, pv_b, nullptr, V, BATCH * NKV,  DIM, DIM);

    // 4. Fused flash attention (+ residual)
    attn_fused<<<dim3(16, BATCH * HEADS), 128>>>(Q, K, V, x, x2, 0,    0,   NKV);
    attn_fused<<<dim3(4,  BATCH * HEADS), 128>>>(Q, K, V, x, x2, 1024, 256, 64);

    // 5. LN2 + FFN (residual fused into FFN2 epilogue, writes d_out)
    ln_kernel<<<BATCH * NTOK, 128>>>(x2, ln2_g, ln2_b, xn);
    gemm_cp<1><<<dim3(12, 320), 256, 61440>>>(xn, w1, ff1_b, nullptr, h1, BATCH * NTOK, FFDIM, DIM);
    gemm_cp<2><<<dim3(3, 320),  256, 61440>>>(h1, w2, ff2_b, x2, out, BATCH * NTOK, DIM, FFDIM);
}

// round 7
// speedup vs baseline: 4.2497x; 1.6532x over previous
#include <cuda_runtime.h>
#include <cuda_bf16.h>
#include <math.h>
#include <stdint.h>

// ---------------------------------------------------------------------------
// Problem constants
// ---------------------------------------------------------------------------
#define BATCH   32
#define NTOK    1280
#define NS_     1024
#define NT_     256
#define DIM     384
#define HEADS   8
#define HDIM    48
#define NKV     320
#define FFDIM   1536
#define ATT_SCALE 0.14433756729740643f

typedef __nv_bfloat16 bf16;

// ---------------------------------------------------------------------------
// Scratch (device globals; no allocation allowed)
// ---------------------------------------------------------------------------
__device__ bf16  g_xn [BATCH * NTOK * DIM];
__device__ bf16  g_qc [BATCH * NTOK * DIM];
__device__ bf16  g_kc [BATCH * NKV  * DIM];
__device__ bf16  g_vc [BATCH * NKV  * DIM];
__device__ bf16  g_Q  [BATCH * NTOK * DIM];
__device__ bf16  g_K  [BATCH * NKV  * DIM];
__device__ bf16  g_V  [BATCH * NKV  * DIM];
__device__ float g_x2 [BATCH * NTOK * DIM];
__device__ bf16  g_h1 [BATCH * NTOK * FFDIM];
__device__ bf16  g_wq [DIM * DIM];
__device__ bf16  g_wk [DIM * DIM];
__device__ bf16  g_wv [DIM * DIM];
__device__ bf16  g_w1 [FFDIM * DIM];
__device__ bf16  g_w2 [DIM * FFDIM];

// ---------------------------------------------------------------------------
// Helpers
// ---------------------------------------------------------------------------
__device__ __forceinline__ void mma_bf16(float* c, const uint32_t* a, const uint32_t* b) {
    asm volatile(
        "mma.sync.aligned.m16n8k16.row.col.f32.bf16.bf16.f32 "
        "{%0,%1,%2,%3}, {%4,%5,%6,%7}, {%8,%9}, {%0,%1,%2,%3};"
        : "+f"(c[0]), "+f"(c[1]), "+f"(c[2]), "+f"(c[3])
        : "r"(a[0]), "r"(a[1]), "r"(a[2]), "r"(a[3]), "r"(b[0]), "r"(b[1]));
}

__device__ __forceinline__ uint32_t pack_bf2(float lo, float hi) {
    __nv_bfloat162 p = __floats2bfloat162_rn(lo, hi);
    return *(uint32_t*)&p;
}

#define CP_A16(dst, src) \
    asm volatile("cp.async.ca.shared.global [%0], [%1], 16;" :: "r"(dst), "l"(src))
#define CP_COMMIT() asm volatile("cp.async.commit_group;")
#define CP_WAIT1()  asm volatile("cp.async.wait_group 1;")

// ---------------------------------------------------------------------------
// Weight conversion fp32 -> bf16
// ---------------------------------------------------------------------------
__global__ void cvt_bf16(const float* __restrict__ src, bf16* __restrict__ dst, int n) {
    int i = blockIdx.x * 256 + threadIdx.x;
    if (i < n) dst[i] = __float2bfloat16(src[i]);
}

// ---------------------------------------------------------------------------
// LayerNorm: warp per token, float4 loads, bf16 packed stores.
// grid = BATCH*NTOK/8 blocks of 256.
// ---------------------------------------------------------------------------
__global__ void ln_kernel(const float* __restrict__ x, const float* __restrict__ g,
                          const float* __restrict__ b, bf16* __restrict__ out) {
    int tok  = (blockIdx.x * 256 + threadIdx.x) >> 5;
    int lane = threadIdx.x & 31;
    const float* xp = x + (size_t)tok * DIM;
    float4 v[3];
    float s = 0.0f, ss = 0.0f;
#pragma unroll
    for (int i = 0; i < 3; i++) {
        v[i] = *(const float4*)(xp + (lane + 32 * i) * 4);
        s  += v[i].x + v[i].y + v[i].z + v[i].w;
        ss += v[i].x * v[i].x + v[i].y * v[i].y + v[i].z * v[i].z + v[i].w * v[i].w;
    }
#pragma unroll
    for (int o = 16; o > 0; o >>= 1) {
        s  += __shfl_xor_sync(0xffffffffu, s,  o);
        ss += __shfl_xor_sync(0xffffffffu, ss, o);
    }
    float mean = s * (1.0f / DIM);
    float var  = ss * (1.0f / DIM) - mean * mean;
    float rstd = rsqrtf(var + 1e-5f);
    bf16* op = out + (size_t)tok * DIM;
#pragma unroll
    for (int i = 0; i < 3; i++) {
        int c = (lane + 32 * i) * 4;
        float4 gg = *(const float4*)(g + c);
        float4 bb = *(const float4*)(b + c);
        uint2 w;
        w.x = pack_bf2((v[i].x - mean) * rstd * gg.x + bb.x,
                       (v[i].y - mean) * rstd * gg.y + bb.y);
        w.y = pack_bf2((v[i].z - mean) * rstd * gg.z + bb.z,
                       (v[i].w - mean) * rstd * gg.w + bb.w);
        *(uint2*)(op + c) = w;
    }
}

// ---------------------------------------------------------------------------
// Depthwise 3x3 conv + bias + BN affine; bf16 in, bf16 out, fp32 accumulate
// ---------------------------------------------------------------------------
__global__ void dwconv_bn(const bf16* __restrict__ in, const float* __restrict__ w,
                          const float* __restrict__ cb, const float* __restrict__ bng,
                          const float* __restrict__ bnb, bf16* __restrict__ out,
                          int hw_in, int hw_out, int stride,
                          int in_boff, int in_bstride, int out_boff, int out_bstride) {
    int c   = threadIdx.x;
    int blk = blockIdx.x;
    int ox  = blk % hw_out;
    int oy  = (blk / hw_out) % hw_out;
    int b   = blk / (hw_out * hw_out);
    const bf16* ip = in + (size_t)b * in_bstride + (size_t)in_boff * DIM;
    float acc = cb[c];
#pragma unroll
    for (int ky = 0; ky < 3; ky++) {
        int iy = oy * stride - 1 + ky;
        if (iy < 0 || iy >= hw_in) continue;
#pragma unroll
        for (int kx = 0; kx < 3; kx++) {
            int ix = ox * stride - 1 + kx;
            if (ix < 0 || ix >= hw_in) continue;
            acc += __bfloat162float(ip[(size_t)(iy * hw_in + ix) * DIM + c]) * w[c * 9 + ky * 3 + kx];
        }
    }
    float sc = bng[c] * rsqrtf(1.0f + 1e-5f);
    out[(size_t)b * out_bstride + (size_t)(out_boff + oy * hw_out + ox) * DIM + c]
        = __float2bfloat16(acc * sc + bnb[c]);
}

// ---------------------------------------------------------------------------
// cp.async 3-stage BF16 GEMM. 128x128x32 CTA tile, 8 warps, 64x32 warp tiles.
// smem: padded rows of 40 bf16 (20 words) -> conflict-free fragment loads.
// EPI: 0 = bias -> bf16 out, 1 = bias+GELU -> bf16 out, 2 = bias+residual -> fp32.
// Dynamic smem: 3 * (5120 + 5120) bf16 = 61440 B.
// ---------------------------------------------------------------------------
#define BSTG 10240   // bf16 elems per stage (A tile 5120 + B tile 5120)

__device__ __forceinline__ void gemm_load_stage_bf(
    uint32_t smem_u32, const bf16* Asrc, const bf16* Bsrc, int s, int k0) {
    uint32_t dA = smem_u32 + (uint32_t)(s * BSTG) * 2u;
    const bf16* pA = Asrc + k0;
    CP_A16(dA, pA);
    CP_A16(dA + 16u, pA + 8);
    uint32_t dB = smem_u32 + (uint32_t)(s * BSTG + 5120) * 2u;
    const bf16* pB = Bsrc + k0;
    CP_A16(dB, pB);
    CP_A16(dB + 16u, pB + 8);
}

template<int EPI>
__global__ void __launch_bounds__(256, 2)
gemm_bf(const bf16* __restrict__ A, const bf16* __restrict__ W,
        const float* __restrict__ bias, const float* __restrict__ res,
        void* __restrict__ Cv, int M, int N, int K) {
    extern __shared__ bf16 smem_bf[];
    uint32_t smem_u32 = (uint32_t)__cvta_generic_to_shared(smem_bf);

    int n0 = blockIdx.x * 128, m0 = blockIdx.y * 128;
    int t = threadIdx.x;
    int row = t >> 1, half = t & 1;

    // per-thread staging base (row*40 + half*16 bf16, two 16B chunks)
    uint32_t stoff = (uint32_t)(row * 40 + half * 16) * 2u;
    const bf16* Asrc = A + (size_t)(m0 + row) * K + half * 16;
    const bf16* Bsrc = W + (size_t)(n0 + row) * K + half * 16;

    int lane = t & 31, g = lane >> 2, tig = lane & 3;
    int w = t >> 5;
    int wm = (w >> 2) * 64, wn = (w & 3) * 32;

    float acc[4][4][4] = {};
    int ntiles = K >> 5;

    gemm_load_stage_bf(smem_u32 + stoff, Asrc, Bsrc, 0, 0);
    CP_COMMIT();
    gemm_load_stage_bf(smem_u32 + stoff, Asrc, Bsrc, 1, 32);
    CP_COMMIT();

    for (int i = 0; i < ntiles; i++) {
        CP_WAIT1();
        __syncthreads();
        if (i + 2 < ntiles)
            gemm_load_stage_bf(smem_u32 + stoff, Asrc, Bsrc, (i + 2) % 3, (i + 2) * 32);
        CP_COMMIT();

        const uint32_t* As_ = (const uint32_t*)(smem_bf + (i % 3) * BSTG);  // stride 20 words
        const uint32_t* Bs_ = As_ + 2560;
#pragma unroll
        for (int ks = 0; ks < 2; ks++) {
            uint32_t af[4][4], bf_[4][2];
#pragma unroll
            for (int mt = 0; mt < 4; mt++) {
                int r = wm + mt * 16 + g;
                af[mt][0] = As_[r * 20 + ks * 8 + tig];
                af[mt][1] = As_[(r + 8) * 20 + ks * 8 + tig];
                af[mt][2] = As_[r * 20 + ks * 8 + tig + 4];
                af[mt][3] = As_[(r + 8) * 20 + ks * 8 + tig + 4];
            }
#pragma unroll
            for (int nt = 0; nt < 4; nt++) {
                int c2 = wn + nt * 8 + g;
                bf_[nt][0] = Bs_[c2 * 20 + ks * 8 + tig];
                bf_[nt][1] = Bs_[c2 * 20 + ks * 8 + tig + 4];
            }
#pragma unroll
            for (int mt = 0; mt < 4; mt++)
#pragma unroll
                for (int nt = 0; nt < 4; nt++)
                    mma_bf16(acc[mt][nt], af[mt], bf_[nt]);
        }
    }

    // epilogue
#pragma unroll
    for (int mt = 0; mt < 4; mt++) {
#pragma unroll
        for (int nt = 0; nt < 4; nt++) {
            int rbase = m0 + wm + mt * 16 + g;
            int col = n0 + wn + nt * 8 + 2 * tig;
#pragma unroll
            for (int hh = 0; hh < 2; hh++) {
                int r = rbase + hh * 8;
                float v0 = acc[mt][nt][hh * 2 + 0] + bias[col];
                float v1 = acc[mt][nt][hh * 2 + 1] + bias[col + 1];
                if (EPI == 1) {
                    v0 = 0.5f * v0 * (1.0f + erff(v0 * 0.70710678118654752f));
                    v1 = 0.5f * v1 * (1.0f + erff(v1 * 0.70710678118654752f));
                }
                size_t gi = (size_t)r * N + col;
                if (EPI == 2) {
                    float* C = (float*)Cv;
                    *(float2*)(C + gi) = make_float2(v0 + res[gi], v1 + res[gi + 1]);
                } else {
                    bf16* C = (bf16*)Cv;
                    *(uint32_t*)(C + gi) = pack_bf2(v0, v1);
                }
            }
        }
    }
}

// ---------------------------------------------------------------------------
// Fused flash attention (bf16 tensor cores) + residual.
// CTA = 64 queries of one (b,h); 4 warps; KV tiles of 64.
// grid: (nq/64, B*H)
// ---------------------------------------------------------------------------
__global__ void __launch_bounds__(128)
attn_fused(const bf16* __restrict__ Q, const bf16* __restrict__ Kg,
           const bf16* __restrict__ Vg, const float* __restrict__ x,
           float* __restrict__ x2, int q_base, int kv_base, int nkv) {
    __shared__ __align__(16) bf16 Qs[64][52];        // [q][d]   stride 26 words
    __shared__ __align__(16) bf16 Ks[64][52];        // [kv][d]  stride 26 words
    __shared__ __align__(16) bf16 Vs[48][72];        // [d][kv]  stride 36 words
    __shared__ __align__(16) bf16 Ps[4][16][72];     // per-warp P patch

    int bh = blockIdx.y, b = bh >> 3, h = bh & 7;
    int q0 = blockIdx.x * 64;
    int t = threadIdx.x;
    int w = t >> 5, lane = t & 31, g = lane >> 2, tig = lane & 3;

    // stage Q tile: 64 rows x 6 chunks of 8 bf16
    for (int idx = t; idx < 384; idx += 128) {
        int r = idx / 6, c8 = (idx % 6) * 8;
        uint4 raw = *(const uint4*)(Q + (size_t)(b * NTOK + q_base + q0 + r) * DIM + h * HDIM + c8);
        *(uint2*)&Qs[r][c8]     = make_uint2(raw.x, raw.y);
        *(uint2*)&Qs[r][c8 + 4] = make_uint2(raw.z, raw.w);
    }
    __syncthreads();

    // Q fragments (3 k16 steps over d=48)
    uint32_t qf[3][4];
    int wrow = w * 16;
    {
        const uint32_t* Qw = (const uint32_t*)&Qs[0][0];
#pragma unroll
        for (int kt = 0; kt < 3; kt++) {
            qf[kt][0] = Qw[(wrow + g    ) * 26 + kt * 8 + tig];
            qf[kt][1] = Qw[(wrow + g + 8) * 26 + kt * 8 + tig];
            qf[kt][2] = Qw[(wrow + g    ) * 26 + kt * 8 + tig + 4];
            qf[kt][3] = Qw[(wrow + g + 8) * 26 + kt * 8 + tig + 4];
        }
    }

    float m0r = -1e30f, m1r = -1e30f, l0 = 0.0f, l1 = 0.0f;
    float oacc[6][4] = {};
    uint32_t* Pw = (uint32_t*)&Ps[w][0][0];          // stride 36 words

    for (int k0 = 0; k0 < nkv; k0 += 64) {
        __syncthreads();
        // K tile: natural layout [kv][d]
        for (int idx = t; idx < 384; idx += 128) {
            int r = idx / 6, c8 = (idx % 6) * 8;
            uint4 raw = *(const uint4*)(Kg + (size_t)(b * NKV + kv_base + k0 + r) * DIM + h * HDIM + c8);
            *(uint2*)&Ks[r][c8]     = make_uint2(raw.x, raw.y);
            *(uint2*)&Ks[r][c8 + 4] = make_uint2(raw.z, raw.w);
        }
        // V tile: transpose to [d][kv]
        for (int idx = t; idx < 384; idx += 128) {
            int r = idx / 6, c8 = (idx % 6) * 8;
            uint4 raw = *(const uint4*)(Vg + (size_t)(b * NKV + kv_base + k0 + r) * DIM + h * HDIM + c8);
            bf16 tmp[8];
            *(uint4*)tmp = raw;
#pragma unroll
            for (int i = 0; i < 8; i++) Vs[c8 + i][r] = tmp[i];
        }
        __syncthreads();

        // S = Q @ K^T (16 rows x 64 cols per warp)
        float sf[8][4] = {};
        {
            const uint32_t* Kw = (const uint32_t*)&Ks[0][0];
#pragma unroll
            for (int kt = 0; kt < 3; kt++) {
                uint32_t bf_[8][2];
#pragma unroll
                for (int nt = 0; nt < 8; nt++) {
                    bf_[nt][0] = Kw[(nt * 8 + g) * 26 + kt * 8 + tig];
                    bf_[nt][1] = Kw[(nt * 8 + g) * 26 + kt * 8 + tig + 4];
                }
#pragma unroll
                for (int nt = 0; nt < 8; nt++)
                    mma_bf16(sf[nt], qf[kt], bf_[nt]);
            }
        }
#pragma unroll
        for (int nt = 0; nt < 8; nt++) {
            sf[nt][0] *= ATT_SCALE; sf[nt][1] *= ATT_SCALE;
            sf[nt][2] *= ATT_SCALE; sf[nt][3] *= ATT_SCALE;
        }

        // online softmax (rows g and g+8)
        float tm0 = -1e30f, tm1 = -1e30f;
#pragma unroll
        for (int nt = 0; nt < 8; nt++) {
            tm0 = fmaxf(tm0, fmaxf(sf[nt][0], sf[nt][1]));
            tm1 = fmaxf(tm1, fmaxf(sf[nt][2], sf[nt][3]));
        }
        tm0 = fmaxf(tm0, __shfl_xor_sync(0xffffffffu, tm0, 1));
        tm0 = fmaxf(tm0, __shfl_xor_sync(0xffffffffu, tm0, 2));
        tm1 = fmaxf(tm1, __shfl_xor_sync(0xffffffffu, tm1, 1));
        tm1 = fmaxf(tm1, __shfl_xor_sync(0xffffffffu, tm1, 2));
        float nm0 = fmaxf(m0r, tm0), nm1 = fmaxf(m1r, tm1);
        float f0 = __expf(m0r - nm0), f1 = __expf(m1r - nm1);
        m0r = nm0; m1r = nm1;
        l0 *= f0; l1 *= f1;
#pragma unroll
        for (int nt = 0; nt < 6; nt++) {
            oacc[nt][0] *= f0; oacc[nt][1] *= f0;
            oacc[nt][2] *= f1; oacc[nt][3] *= f1;
        }
#pragma unroll
        for (int nt = 0; nt < 8; nt++) {
            float p0 = __expf(sf[nt][0] - m0r);
            float p1 = __expf(sf[nt][1] - m0r);
            float p2 = __expf(sf[nt][2] - m1r);
            float p3 = __expf(sf[nt][3] - m1r);
            l0 += p0 + p1; l1 += p2 + p3;
            Pw[(g    ) * 36 + nt * 4 + tig] = pack_bf2(p0, p1);
            Pw[(g + 8) * 36 + nt * 4 + tig] = pack_bf2(p2, p3);
        }
        __syncwarp();

        // O += P @ V  (4 k16 steps over kv=64)
        {
            const uint32_t* Vw = (const uint32_t*)&Vs[0][0];
#pragma unroll
            for (int ks = 0; ks < 4; ks++) {
                uint32_t pa[4];
                pa[0] = Pw[(g    ) * 36 + ks * 8 + tig];
                pa[1] = Pw[(g + 8) * 36 + ks * 8 + tig];
                pa[2] = Pw[(g    ) * 36 + ks * 8 + tig + 4];
                pa[3] = Pw[(g + 8) * 36 + ks * 8 + tig + 4];
#pragma unroll
                for (int nt = 0; nt < 6; nt++) {
                    uint32_t vb[2];
                    vb[0] = Vw[(nt * 8 + g) * 36 + ks * 8 + tig];
                    vb[1] = Vw[(nt * 8 + g) * 36 + ks * 8 + tig + 4];
                    mma_bf16(oacc[nt], pa, vb);
                }
            }
        }
        __syncwarp();
    }

    // epilogue: normalize + fp32 residual
    l0 += __shfl_xor_sync(0xffffffffu, l0, 1);
    l0 += __shfl_xor_sync(0xffffffffu, l0, 2);
    l1 += __shfl_xor_sync(0xffffffffu, l1, 1);
    l1 += __shfl_xor_sync(0xffffffffu, l1, 2);
    float inv0 = 1.0f / l0, inv1 = 1.0f / l1;
    int r0 = b * NTOK + q_base + q0 + wrow + g;
#pragma unroll
    for (int nt = 0; nt < 6; nt++) {
        int col = h * HDIM + nt * 8 + 2 * tig;
        size_t gi0 = (size_t)r0 * DIM + col;
        size_t gi1 = (size_t)(r0 + 8) * DIM + col;
        float2 xa = *(const float2*)(x + gi0);
        float2 xb = *(const float2*)(x + gi1);
        *(float2*)(x2 + gi0) = make_float2(xa.x + oacc[nt][0] * inv0, xa.y + oacc[nt][1] * inv0);
        *(float2*)(x2 + gi1) = make_float2(xb.x + oacc[nt][2] * inv1, xb.y + oacc[nt][3] * inv1);
    }
}

// ---------------------------------------------------------------------------
// Launch
// ---------------------------------------------------------------------------
extern "C" void kernel_launch(void* const* d_in, const int* in_sizes, int n_in,
                              void* d_out, int out_size) {
    (void)in_sizes; (void)n_in; (void)out_size;
    const float* x     = (const float*)d_in[0];
    const float* ln1_g = (const float*)d_in[1];
    const float* ln1_b = (const float*)d_in[2];
    const float* dwq_w = (const float*)d_in[3];
    const float* dwq_b = (const float*)d_in[4];
    const float* bnq_g = (const float*)d_in[5];
    const float* bnq_b = (const float*)d_in[6];
    const float* dwk_w = (const float*)d_in[7];
    const float* dwk_b = (const float*)d_in[8];
    const float* bnk_g = (const float*)d_in[9];
    const float* bnk_b = (const float*)d_in[10];
    const float* dwv_w = (const float*)d_in[11];
    const float* dwv_b = (const float*)d_in[12];
    const float* bnv_g = (const float*)d_in[13];
    const float* bnv_b = (const float*)d_in[14];
    const float* pq_w  = (const float*)d_in[15];
    const float* pq_b  = (const float*)d_in[16];
    const float* pk_w  = (const float*)d_in[17];
    const float* pk_b  = (const float*)d_in[18];
    const float* pv_w  = (const float*)d_in[19];
    const float* pv_b  = (const float*)d_in[20];
    const float* ln2_g = (const float*)d_in[21];
    const float* ln2_b = (const float*)d_in[22];
    const float* ff1_w = (const float*)d_in[23];
    const float* ff1_b = (const float*)d_in[24];
    const float* ff2_w = (const float*)d_in[25];
    const float* ff2_b = (const float*)d_in[26];
    float* out = (float*)d_out;

    bf16 *xn, *qc, *kc, *vc, *Q, *K, *V, *h1, *wq, *wk, *wv, *w1, *w2;
    float *x2;
    cudaGetSymbolAddress((void**)&xn, g_xn);
    cudaGetSymbolAddress((void**)&qc, g_qc);
    cudaGetSymbolAddress((void**)&kc, g_kc);
    cudaGetSymbolAddress((void**)&vc, g_vc);
    cudaGetSymbolAddress((void**)&Q,  g_Q);
    cudaGetSymbolAddress((void**)&K,  g_K);
    cudaGetSymbolAddress((void**)&V,  g_V);
    cudaGetSymbolAddress((void**)&x2, g_x2);
    cudaGetSymbolAddress((void**)&h1, g_h1);
    cudaGetSymbolAddress((void**)&wq, g_wq);
    cudaGetSymbolAddress((void**)&wk, g_wk);
    cudaGetSymbolAddress((void**)&wv, g_wv);
    cudaGetSymbolAddress((void**)&w1, g_w1);
    cudaGetSymbolAddress((void**)&w2, g_w2);

    cudaFuncSetAttribute(gemm_bf<0>, cudaFuncAttributeMaxDynamicSharedMemorySize, 61440);
    cudaFuncSetAttribute(gemm_bf<1>, cudaFuncAttributeMaxDynamicSharedMemorySize, 61440);
    cudaFuncSetAttribute(gemm_bf<2>, cudaFuncAttributeMaxDynamicSharedMemorySize, 61440);

    const int BS_X  = NTOK * DIM;
    const int BS_KV = NKV * DIM;
    const int NW = DIM * DIM;
    const int NF = FFDIM * DIM;

    // 0. Weight conversion to bf16
    cvt_bf16<<<(NW + 255) / 256, 256>>>(pq_w, wq, NW);
    cvt_bf16<<<(NW + 255) / 256, 256>>>(pk_w, wk, NW);
    cvt_bf16<<<(NW + 255) / 256, 256>>>(pv_w, wv, NW);
    cvt_bf16<<<(NF + 255) / 256, 256>>>(ff1_w, w1, NF);
    cvt_bf16<<<(NF + 255) / 256, 256>>>(ff2_w, w2, NF);

    // 1. LN1 (bf16 output)
    ln_kernel<<<BATCH * NTOK / 8, 256>>>(x, ln1_g, ln1_b, xn);

    // 2. Depthwise convs (+bias+BN, bf16 in/out)
    dwconv_bn<<<BATCH * 1024, DIM>>>(xn, dwq_w, dwq_b, bnq_g, bnq_b, qc, 32, 32, 1, 0,    BS_X, 0,    BS_X);
    dwconv_bn<<<BATCH * 256,  DIM>>>(xn, dwq_w, dwq_b, bnq_g, bnq_b, qc, 16, 16, 1, 1024, BS_X, 1024, BS_X);
    dwconv_bn<<<BATCH * 256,  DIM>>>(xn, dwk_w, dwk_b, bnk_g, bnk_b, kc, 32, 16, 2, 0,    BS_X, 0,    BS_KV);
    dwconv_bn<<<BATCH * 64,   DIM>>>(xn, dwk_w, dwk_b, bnk_g, bnk_b, kc, 16, 8,  2, 1024, BS_X, 256,  BS_KV);
    dwconv_bn<<<BATCH * 256,  DIM>>>(xn, dwv_w, dwv_b, bnv_g, bnv_b, vc, 32, 16, 2, 0,    BS_X, 0,    BS_KV);
    dwconv_bn<<<BATCH * 64,   DIM>>>(xn, dwv_w, dwv_b, bnv_g, bnv_b, vc, 16, 8,  2, 1024, BS_X, 256,  BS_KV);

    // 3. Q/K/V projections (bf16 tensor cores)
    gemm_bf<0><<<dim3(3, 320), 256, 61440>>>(qc, wq, pq_b, nullptr, Q, BATCH * NTOK, DIM, DIM);
    gemm_bf<0><<<dim3(3, 80),  256, 61440>>>(kc, wk, pk_b, nullptr, K, BATCH * NKV,  DIM, DIM);
    gemm_bf<0><<<dim3(3, 80),  256, 61440>>>(vc, wv, pv_b, nullptr, V, BATCH * NKV,  DIM, DIM);

    // 4. Fused flash attention (+ residual)
    attn_fused<<<dim3(16, BATCH * HEADS), 128>>>(Q, K, V, x, x2, 0,    0,   NKV);
    attn_fused<<<dim3(4,  BATCH * HEADS), 128>>>(Q, K, V, x, x2, 1024, 256, 64);

    // 5. LN2 + FFN (residual fused into FFN2 epilogue, writes d_out)
    ln_kernel<<<BATCH * NTOK / 8, 256>>>(x2, ln2_g, ln2_b, xn);
    gemm_bf<1><<<dim3(12, 320), 256, 61440>>>(xn, w1, ff1_b, nullptr, h1, BATCH * NTOK, FFDIM, DIM);
    gemm_bf<2><<<dim3(3, 320),  256, 61440>>>(h1, w2, ff2_b, x2, out, BATCH * NTOK, DIM, FFDIM);
}

// round 9
// speedup vs baseline: 5.0884x; 1.1973x over previous
#include <cuda_runtime.h>
#include <cuda_bf16.h>
#include <math.h>
#include <stdint.h>

// ---------------------------------------------------------------------------
// Problem constants
// ---------------------------------------------------------------------------
#define BATCH   32
#define NTOK    1280
#define NS_     1024
#define NT_     256
#define DIM     384
#define HEADS   8
#define HDIM    48
#define NKV     320
#define FFDIM   1536
#define ATT_SCALE 0.14433756729740643f

typedef __nv_bfloat16 bf16;

// ---------------------------------------------------------------------------
// Scratch (device globals; no allocation allowed)
// ---------------------------------------------------------------------------
__device__ bf16  g_xn [BATCH * NTOK * DIM];
__device__ bf16  g_qc [BATCH * NTOK * DIM];
__device__ bf16  g_kc [BATCH * NKV  * DIM];
__device__ bf16  g_vc [BATCH * NKV  * DIM];
__device__ bf16  g_Q  [BATCH * NTOK * DIM];
__device__ bf16  g_K  [BATCH * NKV  * DIM];
__device__ bf16  g_V  [BATCH * NKV  * DIM];
__device__ float g_x2 [BATCH * NTOK * DIM];
__device__ bf16  g_h1 [BATCH * NTOK * FFDIM];
__device__ bf16  g_wq [DIM * DIM];
__device__ bf16  g_wk [DIM * DIM];
__device__ bf16  g_wv [DIM * DIM];
__device__ bf16  g_w1 [FFDIM * DIM];
__device__ bf16  g_w2 [DIM * FFDIM];

// ---------------------------------------------------------------------------
// Helpers
// ---------------------------------------------------------------------------
__device__ __forceinline__ void mma_bf16(float* c, const uint32_t* a, const uint32_t* b) {
    asm volatile(
        "mma.sync.aligned.m16n8k16.row.col.f32.bf16.bf16.f32 "
        "{%0,%1,%2,%3}, {%4,%5,%6,%7}, {%8,%9}, {%0,%1,%2,%3};"
        : "+f"(c[0]), "+f"(c[1]), "+f"(c[2]), "+f"(c[3])
        : "r"(a[0]), "r"(a[1]), "r"(a[2]), "r"(a[3]), "r"(b[0]), "r"(b[1]));
}

__device__ __forceinline__ void ldsm_x4(uint32_t addr, uint32_t* r) {
    asm volatile("ldmatrix.sync.aligned.m8n8.x4.shared.b16 {%0,%1,%2,%3}, [%4];"
        : "=r"(r[0]), "=r"(r[1]), "=r"(r[2]), "=r"(r[3]) : "r"(addr));
}

__device__ __forceinline__ uint32_t pack_bf2(float lo, float hi) {
    __nv_bfloat162 p = __floats2bfloat162_rn(lo, hi);
    return *(uint32_t*)&p;
}

#define CP_A16(dst, src) \
    asm volatile("cp.async.ca.shared.global [%0], [%1], 16;" :: "r"(dst), "l"(src))
#define CP_COMMIT() asm volatile("cp.async.commit_group;")
#define CP_WAIT1()  asm volatile("cp.async.wait_group 1;")

// ---------------------------------------------------------------------------
// Fused weight conversion fp32 -> bf16 for all 5 matrices, float4-vectorized.
// Segment sizes (in float4): 3x36864 (proj) + 2x147456 (ffn) = 405504.
// ---------------------------------------------------------------------------
__global__ void cvt_all(const float* __restrict__ s0, bf16* __restrict__ d0,
                        const float* __restrict__ s1, bf16* __restrict__ d1,
                        const float* __restrict__ s2, bf16* __restrict__ d2,
                        const float* __restrict__ s3, bf16* __restrict__ d3,
                        const float* __restrict__ s4, bf16* __restrict__ d4) {
    int i = blockIdx.x * 256 + threadIdx.x;
    const float* s; bf16* d;
    if      (i <  36864) { s = s0; d = d0; }
    else if (i <  73728) { s = s1; d = d1; i -=  36864; }
    else if (i < 110592) { s = s2; d = d2; i -=  73728; }
    else if (i < 258048) { s = s3; d = d3; i -= 110592; }
    else                 { s = s4; d = d4; i -= 258048; }
    float4 v = ((const float4*)s)[i];
    uint2 o;
    o.x = pack_bf2(v.x, v.y);
    o.y = pack_bf2(v.z, v.w);
    ((uint2*)d)[i] = o;
}

// ---------------------------------------------------------------------------
// LayerNorm: warp per token, float4 loads, bf16 packed stores.
// ---------------------------------------------------------------------------
__global__ void ln_kernel(const float* __restrict__ x, const float* __restrict__ g,
                          const float* __restrict__ b, bf16* __restrict__ out) {
    int tok  = (blockIdx.x * 256 + threadIdx.x) >> 5;
    int lane = threadIdx.x & 31;
    const float* xp = x + (size_t)tok * DIM;
    float4 v[3];
    float s = 0.0f, ss = 0.0f;
#pragma unroll
    for (int i = 0; i < 3; i++) {
        v[i] = *(const float4*)(xp + (lane + 32 * i) * 4);
        s  += v[i].x + v[i].y + v[i].z + v[i].w;
        ss += v[i].x * v[i].x + v[i].y * v[i].y + v[i].z * v[i].z + v[i].w * v[i].w;
    }
#pragma unroll
    for (int o = 16; o > 0; o >>= 1) {
        s  += __shfl_xor_sync(0xffffffffu, s,  o);
        ss += __shfl_xor_sync(0xffffffffu, ss, o);
    }
    float mean = s * (1.0f / DIM);
    float var  = ss * (1.0f / DIM) - mean * mean;
    float rstd = rsqrtf(var + 1e-5f);
    bf16* op = out + (size_t)tok * DIM;
#pragma unroll
    for (int i = 0; i < 3; i++) {
        int c = (lane + 32 * i) * 4;
        float4 gg = *(const float4*)(g + c);
        float4 bb = *(const float4*)(b + c);
        uint2 w;
        w.x = pack_bf2((v[i].x - mean) * rstd * gg.x + bb.x,
                       (v[i].y - mean) * rstd * gg.y + bb.y);
        w.y = pack_bf2((v[i].z - mean) * rstd * gg.z + bb.z,
                       (v[i].w - mean) * rstd * gg.w + bb.w);
        *(uint2*)(op + c) = w;
    }
}

// ---------------------------------------------------------------------------
// Depthwise 3x3 conv + bias + BN affine; 2 channels/thread, bf16x2 words.
// block = 192 threads.
// ---------------------------------------------------------------------------
__global__ void dwconv_bn(const bf16* __restrict__ in, const float* __restrict__ w,
                          const float* __restrict__ cb, const float* __restrict__ bng,
                          const float* __restrict__ bnb, bf16* __restrict__ out,
                          int hw_in, int hw_out, int stride,
                          int in_boff, int in_bstride, int out_boff, int out_bstride) {
    int c   = threadIdx.x * 2;
    int blk = blockIdx.x;
    int ox  = blk % hw_out;
    int oy  = (blk / hw_out) % hw_out;
    int b   = blk / (hw_out * hw_out);
    const bf16* ip = in + (size_t)b * in_bstride + (size_t)in_boff * DIM;
    float acc0 = cb[c], acc1 = cb[c + 1];
#pragma unroll
    for (int ky = 0; ky < 3; ky++) {
        int iy = oy * stride - 1 + ky;
        if (iy < 0 || iy >= hw_in) continue;
#pragma unroll
        for (int kx = 0; kx < 3; kx++) {
            int ix = ox * stride - 1 + kx;
            if (ix < 0 || ix >= hw_in) continue;
            uint32_t raw = *(const uint32_t*)(ip + (size_t)(iy * hw_in + ix) * DIM + c);
            __nv_bfloat162 pv = *(__nv_bfloat162*)&raw;
            int j = ky * 3 + kx;
            acc0 += __bfloat162float(pv.x) * w[c * 9 + j];
            acc1 += __bfloat162float(pv.y) * w[(c + 1) * 9 + j];
        }
    }
    float rs = rsqrtf(1.0f + 1e-5f);
    float o0 = acc0 * (bng[c] * rs)     + bnb[c];
    float o1 = acc1 * (bng[c + 1] * rs) + bnb[c + 1];
    *(uint32_t*)(out + (size_t)b * out_bstride + (size_t)(out_boff + oy * hw_out + ox) * DIM + c)
        = pack_bf2(o0, o1);
}

// ---------------------------------------------------------------------------
// cp.async 3-stage BF16 GEMM with ldmatrix fragment loads.
// 128x128x32 CTA tile, 8 warps, 64x32 warp tiles; smem rows of 40 bf16.
// EPI: 0 = bias -> bf16 out, 1 = bias+GELU -> bf16 out, 2 = bias+residual -> fp32.
// Dynamic smem: 3 * (5120 + 5120) bf16 = 61440 B.
// ---------------------------------------------------------------------------
#define BSTG 10240

__device__ __forceinline__ void gemm_load_stage_bf(
    uint32_t smem_u32, const bf16* Asrc, const bf16* Bsrc, int s, int k0) {
    uint32_t dA = smem_u32 + (uint32_t)(s * BSTG) * 2u;
    const bf16* pA = Asrc + k0;
    CP_A16(dA, pA);
    CP_A16(dA + 16u, pA + 8);
    uint32_t dB = smem_u32 + (uint32_t)(s * BSTG + 5120) * 2u;
    const bf16* pB = Bsrc + k0;
    CP_A16(dB, pB);
    CP_A16(dB + 16u, pB + 8);
}

template<int EPI>
__global__ void __launch_bounds__(256, 2)
gemm_bf(const bf16* __restrict__ A, const bf16* __restrict__ W,
        const float* __restrict__ bias, const float* __restrict__ res,
        void* __restrict__ Cv, int M, int N, int K) {
    extern __shared__ bf16 smem_bf[];
    uint32_t smem_u32 = (uint32_t)__cvta_generic_to_shared(smem_bf);

    int n0 = blockIdx.x * 128, m0 = blockIdx.y * 128;
    int t = threadIdx.x;
    int row = t >> 1, half = t & 1;

    uint32_t stoff = (uint32_t)(row * 40 + half * 16) * 2u;
    const bf16* Asrc = A + (size_t)(m0 + row) * K + half * 16;
    const bf16* Bsrc = W + (size_t)(n0 + row) * K + half * 16;

    int lane = t & 31, g = lane >> 2, tig = lane & 3;
    int w = t >> 5;
    int wm = (w >> 2) * 64, wn = (w & 3) * 32;

    // ldmatrix source addresses (stage-0 relative, bytes)
    int arow = wm + ((lane >> 3) & 1) * 8 + (lane & 7);
    int akw  = (lane >> 4) * 4;
    uint32_t a_base[4];
#pragma unroll
    for (int mt = 0; mt < 4; mt++)
        a_base[mt] = smem_u32 + (uint32_t)(((arow + mt * 16) * 20 + akw) * 4);
    int brow = wn + ((lane >> 4) & 1) * 8 + (lane & 7);
    int bkw  = ((lane >> 3) & 1) * 4;
    uint32_t b_base[2];
#pragma unroll
    for (int p = 0; p < 2; p++)
        b_base[p] = smem_u32 + (uint32_t)((2560 + (brow + p * 16) * 20 + bkw) * 4);

    float acc[4][4][4] = {};
    int ntiles = K >> 5;

    gemm_load_stage_bf(smem_u32 + stoff, Asrc, Bsrc, 0, 0);
    CP_COMMIT();
    gemm_load_stage_bf(smem_u32 + stoff, Asrc, Bsrc, 1, 32);
    CP_COMMIT();

    for (int i = 0; i < ntiles; i++) {
        CP_WAIT1();
        __syncthreads();
        if (i + 2 < ntiles)
            gemm_load_stage_bf(smem_u32 + stoff, Asrc, Bsrc, (i + 2) % 3, (i + 2) * 32);
        CP_COMMIT();

        uint32_t so = (uint32_t)((i % 3) * 20480);
#pragma unroll
        for (int ks = 0; ks < 2; ks++) {
            uint32_t af[4][4], bb[2][4];
#pragma unroll
            for (int mt = 0; mt < 4; mt++)
                ldsm_x4(a_base[mt] + so + ks * 32, af[mt]);
#pragma unroll
            for (int p = 0; p < 2; p++)
                ldsm_x4(b_base[p] + so + ks * 32, bb[p]);
#pragma unroll
            for (int mt = 0; mt < 4; mt++)
#pragma unroll
                for (int nt = 0; nt < 4; nt++) {
                    uint32_t bfr[2] = { bb[nt >> 1][(nt & 1) * 2], bb[nt >> 1][(nt & 1) * 2 + 1] };
                    mma_bf16(acc[mt][nt], af[mt], bfr);
                }
        }
    }

    // epilogue
#pragma unroll
    for (int mt = 0; mt < 4; mt++) {
#pragma unroll
        for (int nt = 0; nt < 4; nt++) {
            int rbase = m0 + wm + mt * 16 + g;
            int col = n0 + wn + nt * 8 + 2 * tig;
#pragma unroll
            for (int hh = 0; hh < 2; hh++) {
                int r = rbase + hh * 8;
                float v0 = acc[mt][nt][hh * 2 + 0] + bias[col];
                float v1 = acc[mt][nt][hh * 2 + 1] + bias[col + 1];
                if (EPI == 1) {
                    v0 = 0.5f * v0 * (1.0f + erff(v0 * 0.70710678118654752f));
                    v1 = 0.5f * v1 * (1.0f + erff(v1 * 0.70710678118654752f));
                }
                size_t gi = (size_t)r * N + col;
                if (EPI == 2) {
                    float* C = (float*)Cv;
                    *(float2*)(C + gi) = make_float2(v0 + res[gi], v1 + res[gi + 1]);
                } else {
                    bf16* C = (bf16*)Cv;
                    *(uint32_t*)(C + gi) = pack_bf2(v0, v1);
                }
            }
        }
    }
}

// ---------------------------------------------------------------------------
// Fused flash attention (bf16 tensor cores) + residual.
// CTA = 64 queries of one (b,h); 4 warps; KV tiles of 64.
// grid: (nq/64, B*H)
// ---------------------------------------------------------------------------
__global__ void __launch_bounds__(128)
attn_fused(const bf16* __restrict__ Q, const bf16* __restrict__ Kg,
           const bf16* __restrict__ Vg, const float* __restrict__ x,
           float* __restrict__ x2, int q_base, int kv_base, int nkv) {
    __shared__ __align__(16) bf16 Qs[64][52];
    __shared__ __align__(16) bf16 Ks[64][52];
    __shared__ __align__(16) bf16 Vs[48][72];
    __shared__ __align__(16) bf16 Ps[4][16][72];

    int bh = blockIdx.y, b = bh >> 3, h = bh & 7;
    int q0 = blockIdx.x * 64;
    int t = threadIdx.x;
    int w = t >> 5, lane = t & 31, g = lane >> 2, tig = lane & 3;

    for (int idx = t; idx < 384; idx += 128) {
        int r = idx / 6, c8 = (idx % 6) * 8;
        uint4 raw = *(const uint4*)(Q + (size_t)(b * NTOK + q_base + q0 + r) * DIM + h * HDIM + c8);
        *(uint2*)&Qs[r][c8]     = make_uint2(raw.x, raw.y);
        *(uint2*)&Qs[r][c8 + 4] = make_uint2(raw.z, raw.w);
    }
    __syncthreads();

    uint32_t qf[3][4];
    int wrow = w * 16;
    {
        const uint32_t* Qw = (const uint32_t*)&Qs[0][0];
#pragma unroll
        for (int kt = 0; kt < 3; kt++) {
            qf[kt][0] = Qw[(wrow + g    ) * 26 + kt * 8 + tig];
            qf[kt][1] = Qw[(wrow + g + 8) * 26 + kt * 8 + tig];
            qf[kt][2] = Qw[(wrow + g    ) * 26 + kt * 8 + tig + 4];
            qf[kt][3] = Qw[(wrow + g + 8) * 26 + kt * 8 + tig + 4];
        }
    }

    float m0r = -1e30f, m1r = -1e30f, l0 = 0.0f, l1 = 0.0f;
    float oacc[6][4] = {};
    uint32_t* Pw = (uint32_t*)&Ps[w][0][0];

    for (int k0 = 0; k0 < nkv; k0 += 64) {
        __syncthreads();
        for (int idx = t; idx < 384; idx += 128) {
            int r = idx / 6, c8 = (idx % 6) * 8;
            uint4 raw = *(const uint4*)(Kg + (size_t)(b * NKV + kv_base + k0 + r) * DIM + h * HDIM + c8);
            *(uint2*)&Ks[r][c8]     = make_uint2(raw.x, raw.y);
            *(uint2*)&Ks[r][c8 + 4] = make_uint2(raw.z, raw.w);
        }
        for (int idx = t; idx < 384; idx += 128) {
            int r = idx / 6, c8 = (idx % 6) * 8;
            uint4 raw = *(const uint4*)(Vg + (size_t)(b * NKV + kv_base + k0 + r) * DIM + h * HDIM + c8);
            bf16 tmp[8];
            *(uint4*)tmp = raw;
#pragma unroll
            for (int i = 0; i < 8; i++) Vs[c8 + i][r] = tmp[i];
        }
        __syncthreads();

        float sf[8][4] = {};
        {
            const uint32_t* Kw = (const uint32_t*)&Ks[0][0];
#pragma unroll
            for (int kt = 0; kt < 3; kt++) {
                uint32_t bf_[8][2];
#pragma unroll
                for (int nt = 0; nt < 8; nt++) {
                    bf_[nt][0] = Kw[(nt * 8 + g) * 26 + kt * 8 + tig];
                    bf_[nt][1] = Kw[(nt * 8 + g) * 26 + kt * 8 + tig + 4];
                }
#pragma unroll
                for (int nt = 0; nt < 8; nt++)
                    mma_bf16(sf[nt], qf[kt], bf_[nt]);
            }
        }
#pragma unroll
        for (int nt = 0; nt < 8; nt++) {
            sf[nt][0] *= ATT_SCALE; sf[nt][1] *= ATT_SCALE;
            sf[nt][2] *= ATT_SCALE; sf[nt][3] *= ATT_SCALE;
        }

        float tm0 = -1e30f, tm1 = -1e30f;
#pragma unroll
        for (int nt = 0; nt < 8; nt++) {
            tm0 = fmaxf(tm0, fmaxf(sf[nt][0], sf[nt][1]));
            tm1 = fmaxf(tm1, fmaxf(sf[nt][2], sf[nt][3]));
        }
        tm0 = fmaxf(tm0, __shfl_xor_sync(0xffffffffu, tm0, 1));
        tm0 = fmaxf(tm0, __shfl_xor_sync(0xffffffffu, tm0, 2));
        tm1 = fmaxf(tm1, __shfl_xor_sync(0xffffffffu, tm1, 1));
        tm1 = fmaxf(tm1, __shfl_xor_sync(0xffffffffu, tm1, 2));
        float nm0 = fmaxf(m0r, tm0), nm1 = fmaxf(m1r, tm1);
        float f0 = __expf(m0r - nm0), f1 = __expf(m1r - nm1);
        m0r = nm0; m1r = nm1;
        l0 *= f0; l1 *= f1;
#pragma unroll
        for (int nt = 0; nt < 6; nt++) {
            oacc[nt][0] *= f0; oacc[nt][1] *= f0;
            oacc[nt][2] *= f1; oacc[nt][3] *= f1;
        }
#pragma unroll
        for (int nt = 0; nt < 8; nt++) {
            float p0 = __expf(sf[nt][0] - m0r);
            float p1 = __expf(sf[nt][1] - m0r);
            float p2 = __expf(sf[nt][2] - m1r);
            float p3 = __expf(sf[nt][3] - m1r);
            l0 += p0 + p1; l1 += p2 + p3;
            Pw[(g    ) * 36 + nt * 4 + tig] = pack_bf2(p0, p1);
            Pw[(g + 8) * 36 + nt * 4 + tig] = pack_bf2(p2, p3);
        }
        __syncwarp();

        {
            const uint32_t* Vw = (const uint32_t*)&Vs[0][0];
#pragma unroll
            for (int ks = 0; ks < 4; ks++) {
                uint32_t pa[4];
                pa[0] = Pw[(g    ) * 36 + ks * 8 + tig];
                pa[1] = Pw[(g + 8) * 36 + ks * 8 + tig];
                pa[2] = Pw[(g    ) * 36 + ks * 8 + tig + 4];
                pa[3] = Pw[(g + 8) * 36 + ks * 8 + tig + 4];
#pragma unroll
                for (int nt = 0; nt < 6; nt++) {
                    uint32_t vb[2];
                    vb[0] = Vw[(nt * 8 + g) * 36 + ks * 8 + tig];
                    vb[1] = Vw[(nt * 8 + g) * 36 + ks * 8 + tig + 4];
                    mma_bf16(oacc[nt], pa, vb);
                }
            }
        }
        __syncwarp();
    }

    l0 += __shfl_xor_sync(0xffffffffu, l0, 1);
    l0 += __shfl_xor_sync(0xffffffffu, l0, 2);
    l1 += __shfl_xor_sync(0xffffffffu, l1, 1);
    l1 += __shfl_xor_sync(0xffffffffu, l1, 2);
    float inv0 = 1.0f / l0, inv1 = 1.0f / l1;
    int r0 = b * NTOK + q_base + q0 + wrow + g;
#pragma unroll
    for (int nt = 0; nt < 6; nt++) {
        int col = h * HDIM + nt * 8 + 2 * tig;
        size_t gi0 = (size_t)r0 * DIM + col;
        size_t gi1 = (size_t)(r0 + 8) * DIM + col;
        float2 xa = *(const float2*)(x + gi0);
        float2 xb = *(const float2*)(x + gi1);
        *(float2*)(x2 + gi0) = make_float2(xa.x + oacc[nt][0] * inv0, xa.y + oacc[nt][1] * inv0);
        *(float2*)(x2 + gi1) = make_float2(xb.x + oacc[nt][2] * inv1, xb.y + oacc[nt][3] * inv1);
    }
}

// ---------------------------------------------------------------------------
// Launch
// ---------------------------------------------------------------------------
extern "C" void kernel_launch(void* const* d_in, const int* in_sizes, int n_in,
                              void* d_out, int out_size) {
    (void)in_sizes; (void)n_in; (void)out_size;
    const float* x     = (const float*)d_in[0];
    const float* ln1_g = (const float*)d_in[1];
    const float* ln1_b = (const float*)d_in[2];
    const float* dwq_w = (const float*)d_in[3];
    const float* dwq_b = (const float*)d_in[4];
    const float* bnq_g = (const float*)d_in[5];
    const float* bnq_b = (const float*)d_in[6];
    const float* dwk_w = (const float*)d_in[7];
    const float* dwk_b = (const float*)d_in[8];
    const float* bnk_g = (const float*)d_in[9];
    const float* bnk_b = (const float*)d_in[10];
    const float* dwv_w = (const float*)d_in[11];
    const float* dwv_b = (const float*)d_in[12];
    const float* bnv_g = (const float*)d_in[13];
    const float* bnv_b = (const float*)d_in[14];
    const float* pq_w  = (const float*)d_in[15];
    const float* pq_b  = (const float*)d_in[16];
    const float* pk_w  = (const float*)d_in[17];
    const float* pk_b  = (const float*)d_in[18];
    const float* pv_w  = (const float*)d_in[19];
    const float* pv_b  = (const float*)d_in[20];
    const float* ln2_g = (const float*)d_in[21];
    const float* ln2_b = (const float*)d_in[22];
    const float* ff1_w = (const float*)d_in[23];
    const float* ff1_b = (const float*)d_in[24];
    const float* ff2_w = (const float*)d_in[25];
    const float* ff2_b = (const float*)d_in[26];
    float* out = (float*)d_out;

    bf16 *xn, *qc, *kc, *vc, *Q, *K, *V, *h1, *wq, *wk, *wv, *w1, *w2;
    float *x2;
    cudaGetSymbolAddress((void**)&xn, g_xn);
    cudaGetSymbolAddress((void**)&qc, g_qc);
    cudaGetSymbolAddress((void**)&kc, g_kc);
    cudaGetSymbolAddress((void**)&vc, g_vc);
    cudaGetSymbolAddress((void**)&Q,  g_Q);
    cudaGetSymbolAddress((void**)&K,  g_K);
    cudaGetSymbolAddress((void**)&V,  g_V);
    cudaGetSymbolAddress((void**)&x2, g_x2);
    cudaGetSymbolAddress((void**)&h1, g_h1);
    cudaGetSymbolAddress((void**)&wq, g_wq);
    cudaGetSymbolAddress((void**)&wk, g_wk);
    cudaGetSymbolAddress((void**)&wv, g_wv);
    cudaGetSymbolAddress((void**)&w1, g_w1);
    cudaGetSymbolAddress((void**)&w2, g_w2);

    cudaFuncSetAttribute(gemm_bf<0>, cudaFuncAttributeMaxDynamicSharedMemorySize, 61440);
    cudaFuncSetAttribute(gemm_bf<1>, cudaFuncAttributeMaxDynamicSharedMemorySize, 61440);
    cudaFuncSetAttribute(gemm_bf<2>, cudaFuncAttributeMaxDynamicSharedMemorySize, 61440);

    const int BS_X  = NTOK * DIM;
    const int BS_KV = NKV * DIM;

    // 0. Weight conversion to bf16 (single fused launch)
    cvt_all<<<1584, 256>>>(pq_w, wq, pk_w, wk, pv_w, wv, ff1_w, w1, ff2_w, w2);

    // 1. LN1 (bf16 output)
    ln_kernel<<<BATCH * NTOK / 8, 256>>>(x, ln1_g, ln1_b, xn);

    // 2. Depthwise convs (+bias+BN, bf16 in/out, 2 ch/thread)
    dwconv_bn<<<BATCH * 1024, 192>>>(xn, dwq_w, dwq_b, bnq_g, bnq_b, qc, 32, 32, 1, 0,    BS_X, 0,    BS_X);
    dwconv_bn<<<BATCH * 256,  192>>>(xn, dwq_w, dwq_b, bnq_g, bnq_b, qc, 16, 16, 1, 1024, BS_X, 1024, BS_X);
    dwconv_bn<<<BATCH * 256,  192>>>(xn, dwk_w, dwk_b, bnk_g, bnk_b, kc, 32, 16, 2, 0,    BS_X, 0,    BS_KV);
    dwconv_bn<<<BATCH * 64,   192>>>(xn, dwk_w, dwk_b, bnk_g, bnk_b, kc, 16, 8,  2, 1024, BS_X, 256,  BS_KV);
    dwconv_bn<<<BATCH * 256,  192>>>(xn, dwv_w, dwv_b, bnv_g, bnv_b, vc, 32, 16, 2, 0,    BS_X, 0,    BS_KV);
    dwconv_bn<<<BATCH * 64,   192>>>(xn, dwv_w, dwv_b, bnv_g, bnv_b, vc, 16, 8,  2, 1024, BS_X, 256,  BS_KV);

    // 3. Q/K/V projections (bf16 tensor cores + ldmatrix)
    gemm_bf<0><<<dim3(3, 320), 256, 61440>>>(qc, wq, pq_b, nullptr, Q, BATCH * NTOK, DIM, DIM);
    gemm_bf<0><<<dim3(3, 80),  256, 61440>>>(kc, wk, pk_b, nullptr, K, BATCH * NKV,  DIM, DIM);
    gemm_bf<0><<<dim3(3, 80),  256, 61440>>>(vc, wv, pv_b, nullptr, V, BATCH * NKV,  DIM, DIM);

    // 4. Fused flash attention (+ residual)
    attn_fused<<<dim3(16, BATCH * HEADS), 128>>>(Q, K, V, x, x2, 0,    0,   NKV);
    attn_fused<<<dim3(4,  BATCH * HEADS), 128>>>(Q, K, V, x, x2, 1024, 256, 64);

    // 5. LN2 + FFN (residual fused into FFN2 epilogue, writes d_out)
    ln_kernel<<<BATCH * NTOK / 8, 256>>>(x2, ln2_g, ln2_b, xn);
    gemm_bf<1><<<dim3(12, 320), 256, 61440>>>(xn, w1, ff1_b, nullptr, h1, BATCH * NTOK, FFDIM, DIM);
    gemm_bf<2><<<dim3(3, 320),  256, 61440>>>(h1, w2, ff2_b, x2, out, BATCH * NTOK, DIM, FFDIM);
}

// round 10
// speedup vs baseline: 5.1015x; 1.0026x over previous
#include <cuda_runtime.h>
#include <cuda_bf16.h>
#include <math.h>
#include <stdint.h>

// ---------------------------------------------------------------------------
// Problem constants
// ---------------------------------------------------------------------------
#define BATCH   32
#define NTOK    1280
#define NS_     1024
#define NT_     256
#define DIM     384
#define HEADS   8
#define HDIM    48
#define NKV     320
#define FFDIM   1536
#define ATT_SCALE 0.14433756729740643f

typedef __nv_bfloat16 bf16;

// ---------------------------------------------------------------------------
// Scratch (device globals; no allocation allowed)
// ---------------------------------------------------------------------------
__device__ bf16  g_xn [BATCH * NTOK * DIM];
__device__ bf16  g_qc [BATCH * NTOK * DIM];
__device__ bf16  g_kc [BATCH * NKV  * DIM];
__device__ bf16  g_vc [BATCH * NKV  * DIM];
__device__ bf16  g_Q  [BATCH * NTOK * DIM];
__device__ bf16  g_K  [BATCH * NKV  * DIM];
__device__ bf16  g_V  [BATCH * NKV  * DIM];
__device__ float g_x2 [BATCH * NTOK * DIM];
__device__ bf16  g_h1 [BATCH * NTOK * FFDIM];
__device__ bf16  g_wq [DIM * DIM];
__device__ bf16  g_wk [DIM * DIM];
__device__ bf16  g_wv [DIM * DIM];
__device__ bf16  g_w1 [FFDIM * DIM];
__device__ bf16  g_w2 [DIM * FFDIM];

// ---------------------------------------------------------------------------
// Helpers
// ---------------------------------------------------------------------------
__device__ __forceinline__ void mma_bf16(float* c, const uint32_t* a, const uint32_t* b) {
    asm volatile(
        "mma.sync.aligned.m16n8k16.row.col.f32.bf16.bf16.f32 "
        "{%0,%1,%2,%3}, {%4,%5,%6,%7}, {%8,%9}, {%0,%1,%2,%3};"
        : "+f"(c[0]), "+f"(c[1]), "+f"(c[2]), "+f"(c[3])
        : "r"(a[0]), "r"(a[1]), "r"(a[2]), "r"(a[3]), "r"(b[0]), "r"(b[1]));
}

__device__ __forceinline__ void ldsm_x4(uint32_t addr, uint32_t* r) {
    asm volatile("ldmatrix.sync.aligned.m8n8.x4.shared.b16 {%0,%1,%2,%3}, [%4];"
        : "=r"(r[0]), "=r"(r[1]), "=r"(r[2]), "=r"(r[3]) : "r"(addr));
}

__device__ __forceinline__ uint32_t pack_bf2(float lo, float hi) {
    __nv_bfloat162 p = __floats2bfloat162_rn(lo, hi);
    return *(uint32_t*)&p;
}

#define CP_A16(dst, src) \
    asm volatile("cp.async.ca.shared.global [%0], [%1], 16;" :: "r"(dst), "l"(src))
#define CP_COMMIT() asm volatile("cp.async.commit_group;")
#define CP_WAIT1()  asm volatile("cp.async.wait_group 1;")

// ---------------------------------------------------------------------------
// Fused weight conversion fp32 -> bf16 for all 5 matrices, float4-vectorized.
// Segment sizes (in float4): 3x36864 (proj) + 2x147456 (ffn) = 405504.
// ---------------------------------------------------------------------------
__global__ void cvt_all(const float* __restrict__ s0, bf16* __restrict__ d0,
                        const float* __restrict__ s1, bf16* __restrict__ d1,
                        const float* __restrict__ s2, bf16* __restrict__ d2,
                        const float* __restrict__ s3, bf16* __restrict__ d3,
                        const float* __restrict__ s4, bf16* __restrict__ d4) {
    int i = blockIdx.x * 256 + threadIdx.x;
    const float* s; bf16* d;
    if      (i <  36864) { s = s0; d = d0; }
    else if (i <  73728) { s = s1; d = d1; i -=  36864; }
    else if (i < 110592) { s = s2; d = d2; i -=  73728; }
    else if (i < 258048) { s = s3; d = d3; i -= 110592; }
    else                 { s = s4; d = d4; i -= 258048; }
    float4 v = ((const float4*)s)[i];
    uint2 o;
    o.x = pack_bf2(v.x, v.y);
    o.y = pack_bf2(v.z, v.w);
    ((uint2*)d)[i] = o;
}

// ---------------------------------------------------------------------------
// LayerNorm: warp per token, float4 loads, bf16 packed stores.
// ---------------------------------------------------------------------------
__global__ void ln_kernel(const float* __restrict__ x, const float* __restrict__ g,
                          const float* __restrict__ b, bf16* __restrict__ out) {
    int tok  = (blockIdx.x * 256 + threadIdx.x) >> 5;
    int lane = threadIdx.x & 31;
    const float* xp = x + (size_t)tok * DIM;
    float4 v[3];
    float s = 0.0f, ss = 0.0f;
#pragma unroll
    for (int i = 0; i < 3; i++) {
        v[i] = *(const float4*)(xp + (lane + 32 * i) * 4);
        s  += v[i].x + v[i].y + v[i].z + v[i].w;
        ss += v[i].x * v[i].x + v[i].y * v[i].y + v[i].z * v[i].z + v[i].w * v[i].w;
    }
#pragma unroll
    for (int o = 16; o > 0; o >>= 1) {
        s  += __shfl_xor_sync(0xffffffffu, s,  o);
        ss += __shfl_xor_sync(0xffffffffu, ss, o);
    }
    float mean = s * (1.0f / DIM);
    float var  = ss * (1.0f / DIM) - mean * mean;
    float rstd = rsqrtf(var + 1e-5f);
    bf16* op = out + (size_t)tok * DIM;
#pragma unroll
    for (int i = 0; i < 3; i++) {
        int c = (lane + 32 * i) * 4;
        float4 gg = *(const float4*)(g + c);
        float4 bb = *(const float4*)(b + c);
        uint2 w;
        w.x = pack_bf2((v[i].x - mean) * rstd * gg.x + bb.x,
                       (v[i].y - mean) * rstd * gg.y + bb.y);
        w.y = pack_bf2((v[i].z - mean) * rstd * gg.z + bb.z,
                       (v[i].w - mean) * rstd * gg.w + bb.w);
        *(uint2*)(op + c) = w;
    }
}

// ---------------------------------------------------------------------------
// Depthwise 3x3 conv + bias + BN affine; 2 channels/thread, bf16x2 words.
// block = 192 threads.
// ---------------------------------------------------------------------------
__global__ void dwconv_bn(const bf16* __restrict__ in, const float* __restrict__ w,
                          const float* __restrict__ cb, const float* __restrict__ bng,
                          const float* __restrict__ bnb, bf16* __restrict__ out,
                          int hw_in, int hw_out, int stride,
                          int in_boff, int in_bstride, int out_boff, int out_bstride) {
    int c   = threadIdx.x * 2;
    int blk = blockIdx.x;
    int ox  = blk % hw_out;
    int oy  = (blk / hw_out) % hw_out;
    int b   = blk / (hw_out * hw_out);
    const bf16* ip = in + (size_t)b * in_bstride + (size_t)in_boff * DIM;
    float acc0 = cb[c], acc1 = cb[c + 1];
#pragma unroll
    for (int ky = 0; ky < 3; ky++) {
        int iy = oy * stride - 1 + ky;
        if (iy < 0 || iy >= hw_in) continue;
#pragma unroll
        for (int kx = 0; kx < 3; kx++) {
            int ix = ox * stride - 1 + kx;
            if (ix < 0 || ix >= hw_in) continue;
            uint32_t raw = *(const uint32_t*)(ip + (size_t)(iy * hw_in + ix) * DIM + c);
            __nv_bfloat162 pv = *(__nv_bfloat162*)&raw;
            int j = ky * 3 + kx;
            acc0 += __bfloat162float(pv.x) * w[c * 9 + j];
            acc1 += __bfloat162float(pv.y) * w[(c + 1) * 9 + j];
        }
    }
    float rs = rsqrtf(1.0f + 1e-5f);
    float o0 = acc0 * (bng[c] * rs)     + bnb[c];
    float o1 = acc1 * (bng[c + 1] * rs) + bnb[c + 1];
    *(uint32_t*)(out + (size_t)b * out_bstride + (size_t)(out_boff + oy * hw_out + ox) * DIM + c)
        = pack_bf2(o0, o1);
}

// ---------------------------------------------------------------------------
// cp.async 3-stage BF16 GEMM with ldmatrix fragment loads.
// 128x128x32 CTA tile, 8 warps, 64x32 warp tiles; smem rows of 40 bf16.
// EPI: 0 = bias -> bf16 out, 1 = bias+GELU -> bf16 out, 2 = bias+residual -> fp32.
// Dynamic smem: 3 * (5120 + 5120) bf16 = 61440 B.
// ---------------------------------------------------------------------------
#define BSTG 10240

__device__ __forceinline__ void gemm_load_stage_bf(
    uint32_t smem_u32, const bf16* Asrc, const bf16* Bsrc, int s, int k0) {
    uint32_t dA = smem_u32 + (uint32_t)(s * BSTG) * 2u;
    const bf16* pA = Asrc + k0;
    CP_A16(dA, pA);
    CP_A16(dA + 16u, pA + 8);
    uint32_t dB = smem_u32 + (uint32_t)(s * BSTG + 5120) * 2u;
    const bf16* pB = Bsrc + k0;
    CP_A16(dB, pB);
    CP_A16(dB + 16u, pB + 8);
}

template<int EPI>
__global__ void __launch_bounds__(256, 2)
gemm_bf(const bf16* __restrict__ A, const bf16* __restrict__ W,
        const float* __restrict__ bias, const float* __restrict__ res,
        void* __restrict__ Cv, int M, int N, int K) {
    extern __shared__ bf16 smem_bf[];
    uint32_t smem_u32 = (uint32_t)__cvta_generic_to_shared(smem_bf);

    int n0 = blockIdx.x * 128, m0 = blockIdx.y * 128;
    int t = threadIdx.x;
    int row = t >> 1, half = t & 1;

    uint32_t stoff = (uint32_t)(row * 40 + half * 16) * 2u;
    const bf16* Asrc = A + (size_t)(m0 + row) * K + half * 16;
    const bf16* Bsrc = W + (size_t)(n0 + row) * K + half * 16;

    int lane = t & 31, g = lane >> 2, tig = lane & 3;
    int w = t >> 5;
    int wm = (w >> 2) * 64, wn = (w & 3) * 32;

    // ldmatrix source addresses (stage-0 relative, bytes)
    int arow = wm + ((lane >> 3) & 1) * 8 + (lane & 7);
    int akw  = (lane >> 4) * 4;
    uint32_t a_base[4];
#pragma unroll
    for (int mt = 0; mt < 4; mt++)
        a_base[mt] = smem_u32 + (uint32_t)(((arow + mt * 16) * 20 + akw) * 4);
    int brow = wn + ((lane >> 4) & 1) * 8 + (lane & 7);
    int bkw  = ((lane >> 3) & 1) * 4;
    uint32_t b_base[2];
#pragma unroll
    for (int p = 0; p < 2; p++)
        b_base[p] = smem_u32 + (uint32_t)((2560 + (brow + p * 16) * 20 + bkw) * 4);

    float acc[4][4][4] = {};
    int ntiles = K >> 5;

    gemm_load_stage_bf(smem_u32 + stoff, Asrc, Bsrc, 0, 0);
    CP_COMMIT();
    gemm_load_stage_bf(smem_u32 + stoff, Asrc, Bsrc, 1, 32);
    CP_COMMIT();

    for (int i = 0; i < ntiles; i++) {
        CP_WAIT1();
        __syncthreads();
        if (i + 2 < ntiles)
            gemm_load_stage_bf(smem_u32 + stoff, Asrc, Bsrc, (i + 2) % 3, (i + 2) * 32);
        CP_COMMIT();

        uint32_t so = (uint32_t)((i % 3) * 20480);
#pragma unroll
        for (int ks = 0; ks < 2; ks++) {
            uint32_t af[4][4], bb[2][4];
#pragma unroll
            for (int mt = 0; mt < 4; mt++)
                ldsm_x4(a_base[mt] + so + ks * 32, af[mt]);
#pragma unroll
            for (int p = 0; p < 2; p++)
                ldsm_x4(b_base[p] + so + ks * 32, bb[p]);
#pragma unroll
            for (int mt = 0; mt < 4; mt++)
#pragma unroll
                for (int nt = 0; nt < 4; nt++) {
                    uint32_t bfr[2] = { bb[nt >> 1][(nt & 1) * 2], bb[nt >> 1][(nt & 1) * 2 + 1] };
                    mma_bf16(acc[mt][nt], af[mt], bfr);
                }
        }
    }

    // epilogue
#pragma unroll
    for (int mt = 0; mt < 4; mt++) {
#pragma unroll
        for (int nt = 0; nt < 4; nt++) {
            int rbase = m0 + wm + mt * 16 + g;
            int col = n0 + wn + nt * 8 + 2 * tig;
#pragma unroll
            for (int hh = 0; hh < 2; hh++) {
                int r = rbase + hh * 8;
                float v0 = acc[mt][nt][hh * 2 + 0] + bias[col];
                float v1 = acc[mt][nt][hh * 2 + 1] + bias[col + 1];
                if (EPI == 1) {
                    v0 = 0.5f * v0 * (1.0f + erff(v0 * 0.70710678118654752f));
                    v1 = 0.5f * v1 * (1.0f + erff(v1 * 0.70710678118654752f));
                }
                size_t gi = (size_t)r * N + col;
                if (EPI == 2) {
                    float* C = (float*)Cv;
                    *(float2*)(C + gi) = make_float2(v0 + res[gi], v1 + res[gi + 1]);
                } else {
                    bf16* C = (bf16*)Cv;
                    *(uint32_t*)(C + gi) = pack_bf2(v0, v1);
                }
            }
        }
    }
}

// ---------------------------------------------------------------------------
// Fused flash attention (bf16 tensor cores) + residual.
// CTA = 64 queries of one (b,h); 4 warps; KV tiles of 64.
// grid: (nq/64, B*H)
// ---------------------------------------------------------------------------
__global__ void __launch_bounds__(128)
attn_fused(const bf16* __restrict__ Q, const bf16* __restrict__ Kg,
           const bf16* __restrict__ Vg, const float* __restrict__ x,
           float* __restrict__ x2, int q_base, int kv_base, int nkv) {
    __shared__ __align__(16) bf16 Qs[64][52];
    __shared__ __align__(16) bf16 Ks[64][52];
    __shared__ __align__(16) bf16 Vs[48][72];
    __shared__ __align__(16) bf16 Ps[4][16][72];

    int bh = blockIdx.y, b = bh >> 3, h = bh & 7;
    int q0 = blockIdx.x * 64;
    int t = threadIdx.x;
    int w = t >> 5, lane = t & 31, g = lane >> 2, tig = lane & 3;

    for (int idx = t; idx < 384; idx += 128) {
        int r = idx / 6, c8 = (idx % 6) * 8;
        uint4 raw = *(const uint4*)(Q + (size_t)(b * NTOK + q_base + q0 + r) * DIM + h * HDIM + c8);
        *(uint2*)&Qs[r][c8]     = make_uint2(raw.x, raw.y);
        *(uint2*)&Qs[r][c8 + 4] = make_uint2(raw.z, raw.w);
    }
    __syncthreads();

    uint32_t qf[3][4];
    int wrow = w * 16;
    {
        const uint32_t* Qw = (const uint32_t*)&Qs[0][0];
#pragma unroll
        for (int kt = 0; kt < 3; kt++) {
            qf[kt][0] = Qw[(wrow + g    ) * 26 + kt * 8 + tig];
            qf[kt][1] = Qw[(wrow + g + 8) * 26 + kt * 8 + tig];
            qf[kt][2] = Qw[(wrow + g    ) * 26 + kt * 8 + tig + 4];
            qf[kt][3] = Qw[(wrow + g + 8) * 26 + kt * 8 + tig + 4];
        }
    }

    float m0r = -1e30f, m1r = -1e30f, l0 = 0.0f, l1 = 0.0f;
    float oacc[6][4] = {};
    uint32_t* Pw = (uint32_t*)&Ps[w][0][0];

    for (int k0 = 0; k0 < nkv; k0 += 64) {
        __syncthreads();
        for (int idx = t; idx < 384; idx += 128) {
            int r = idx / 6, c8 = (idx % 6) * 8;
            uint4 raw = *(const uint4*)(Kg + (size_t)(b * NKV + kv_base + k0 + r) * DIM + h * HDIM + c8);
            *(uint2*)&Ks[r][c8]     = make_uint2(raw.x, raw.y);
            *(uint2*)&Ks[r][c8 + 4] = make_uint2(raw.z, raw.w);
        }
        for (int idx = t; idx < 384; idx += 128) {
            int r = idx / 6, c8 = (idx % 6) * 8;
            uint4 raw = *(const uint4*)(Vg + (size_t)(b * NKV + kv_base + k0 + r) * DIM + h * HDIM + c8);
            bf16 tmp[8];
            *(uint4*)tmp = raw;
#pragma unroll
            for (int i = 0; i < 8; i++) Vs[c8 + i][r] = tmp[i];
        }
        __syncthreads();

        float sf[8][4] = {};
        {
            const uint32_t* Kw = (const uint32_t*)&Ks[0][0];
#pragma unroll
            for (int kt = 0; kt < 3; kt++) {
                uint32_t bf_[8][2];
#pragma unroll
                for (int nt = 0; nt < 8; nt++) {
                    bf_[nt][0] = Kw[(nt * 8 + g) * 26 + kt * 8 + tig];
                    bf_[nt][1] = Kw[(nt * 8 + g) * 26 + kt * 8 + tig + 4];
                }
#pragma unroll
                for (int nt = 0; nt < 8; nt++)
                    mma_bf16(sf[nt], qf[kt], bf_[nt]);
            }
        }
#pragma unroll
        for (int nt = 0; nt < 8; nt++) {
            sf[nt][0] *= ATT_SCALE; sf[nt][1] *= ATT_SCALE;
            sf[nt][2] *= ATT_SCALE; sf[nt][3] *= ATT_SCALE;
        }

        float tm0 = -1e30f, tm1 = -1e30f;
#pragma unroll
        for (int nt = 0; nt < 8; nt++) {
            tm0 = fmaxf(tm0, fmaxf(sf[nt][0], sf[nt][1]));
            tm1 = fmaxf(tm1, fmaxf(sf[nt][2], sf[nt][3]));
        }
        tm0 = fmaxf(tm0, __shfl_xor_sync(0xffffffffu, tm0, 1));
        tm0 = fmaxf(tm0, __shfl_xor_sync(0xffffffffu, tm0, 2));
        tm1 = fmaxf(tm1, __shfl_xor_sync(0xffffffffu, tm1, 1));
        tm1 = fmaxf(tm1, __shfl_xor_sync(0xffffffffu, tm1, 2));
        float nm0 = fmaxf(m0r, tm0), nm1 = fmaxf(m1r, tm1);
        float f0 = __expf(m0r - nm0), f1 = __expf(m1r - nm1);
        m0r = nm0; m1r = nm1;
        l0 *= f0; l1 *= f1;
#pragma unroll
        for (int nt = 0; nt < 6; nt++) {
            oacc[nt][0] *= f0; oacc[nt][1] *= f0;
            oacc[nt][2] *= f1; oacc[nt][3] *= f1;
        }
#pragma unroll
        for (int nt = 0; nt < 8; nt++) {
            float p0 = __expf(sf[nt][0] - m0r);
            float p1 = __expf(sf[nt][1] - m0r);
            float p2 = __expf(sf[nt][2] - m1r);
            float p3 = __expf(sf[nt][3] - m1r);
            l0 += p0 + p1; l1 += p2 + p3;
            Pw[(g    ) * 36 + nt * 4 + tig] = pack_bf2(p0, p1);
            Pw[(g + 8) * 36 + nt * 4 + tig] = pack_bf2(p2, p3);
        }
        __syncwarp();

        {
            const uint32_t* Vw = (const uint32_t*)&Vs[0][0];
#pragma unroll
            for (int ks = 0; ks < 4; ks++) {
                uint32_t pa[4];
                pa[0] = Pw[(g    ) * 36 + ks * 8 + tig];
                pa[1] = Pw[(g + 8) * 36 + ks * 8 + tig];
                pa[2] = Pw[(g    ) * 36 + ks * 8 + tig + 4];
                pa[3] = Pw[(g + 8) * 36 + ks * 8 + tig + 4];
#pragma unroll
                for (int nt = 0; nt < 6; nt++) {
                    uint32_t vb[2];
                    vb[0] = Vw[(nt * 8 + g) * 36 + ks * 8 + tig];
                    vb[1] = Vw[(nt * 8 + g) * 36 + ks * 8 + tig + 4];
                    mma_bf16(oacc[nt], pa, vb);
                }
            }
        }
        __syncwarp();
    }

    l0 += __shfl_xor_sync(0xffffffffu, l0, 1);
    l0 += __shfl_xor_sync(0xffffffffu, l0, 2);
    l1 += __shfl_xor_sync(0xffffffffu, l1, 1);
    l1 += __shfl_xor_sync(0xffffffffu, l1, 2);
    float inv0 = 1.0f / l0, inv1 = 1.0f / l1;
    int r0 = b * NTOK + q_base + q0 + wrow + g;
#pragma unroll
    for (int nt = 0; nt < 6; nt++) {
        int col = h * HDIM + nt * 8 + 2 * tig;
        size_t gi0 = (size_t)r0 * DIM + col;
        size_t gi1 = (size_t)(r0 + 8) * DIM + col;
        float2 xa = *(const float2*)(x + gi0);
        float2 xb = *(const float2*)(x + gi1);
        *(float2*)(x2 + gi0) = make_float2(xa.x + oacc[nt][0] * inv0, xa.y + oacc[nt][1] * inv0);
        *(float2*)(x2 + gi1) = make_float2(xb.x + oacc[nt][2] * inv1, xb.y + oacc[nt][3] * inv1);
    }
}

// ---------------------------------------------------------------------------
// Launch
// ---------------------------------------------------------------------------
extern "C" void kernel_launch(void* const* d_in, const int* in_sizes, int n_in,
                              void* d_out, int out_size) {
    (void)in_sizes; (void)n_in; (void)out_size;
    const float* x     = (const float*)d_in[0];
    const float* ln1_g = (const float*)d_in[1];
    const float* ln1_b = (const float*)d_in[2];
    const float* dwq_w = (const float*)d_in[3];
    const float* dwq_b = (const float*)d_in[4];
    const float* bnq_g = (const float*)d_in[5];
    const float* bnq_b = (const float*)d_in[6];
    const float* dwk_w = (const float*)d_in[7];
    const float* dwk_b = (const float*)d_in[8];
    const float* bnk_g = (const float*)d_in[9];
    const float* bnk_b = (const float*)d_in[10];
    const float* dwv_w = (const float*)d_in[11];
    const float* dwv_b = (const float*)d_in[12];
    const float* bnv_g = (const float*)d_in[13];
    const float* bnv_b = (const float*)d_in[14];
    const float* pq_w  = (const float*)d_in[15];
    const float* pq_b  = (const float*)d_in[16];
    const float* pk_w  = (const float*)d_in[17];
    const float* pk_b  = (const float*)d_in[18];
    const float* pv_w  = (const float*)d_in[19];
    const float* pv_b  = (const float*)d_in[20];
    const float* ln2_g = (const float*)d_in[21];
    const float* ln2_b = (const float*)d_in[22];
    const float* ff1_w = (const float*)d_in[23];
    const float* ff1_b = (const float*)d_in[24];
    const float* ff2_w = (const float*)d_in[25];
    const float* ff2_b = (const float*)d_in[26];
    float* out = (float*)d_out;

    bf16 *xn, *qc, *kc, *vc, *Q, *K, *V, *h1, *wq, *wk, *wv, *w1, *w2;
    float *x2;
    cudaGetSymbolAddress((void**)&xn, g_xn);
    cudaGetSymbolAddress((void**)&qc, g_qc);
    cudaGetSymbolAddress((void**)&kc, g_kc);
    cudaGetSymbolAddress((void**)&vc, g_vc);
    cudaGetSymbolAddress((void**)&Q,  g_Q);
    cudaGetSymbolAddress((void**)&K,  g_K);
    cudaGetSymbolAddress((void**)&V,  g_V);
    cudaGetSymbolAddress((void**)&x2, g_x2);
    cudaGetSymbolAddress((void**)&h1, g_h1);
    cudaGetSymbolAddress((void**)&wq, g_wq);
    cudaGetSymbolAddress((void**)&wk, g_wk);
    cudaGetSymbolAddress((void**)&wv, g_wv);
    cudaGetSymbolAddress((void**)&w1, g_w1);
    cudaGetSymbolAddress((void**)&w2, g_w2);

    cudaFuncSetAttribute(gemm_bf<0>, cudaFuncAttributeMaxDynamicSharedMemorySize, 61440);
    cudaFuncSetAttribute(gemm_bf<1>, cudaFuncAttributeMaxDynamicSharedMemorySize, 61440);
    cudaFuncSetAttribute(gemm_bf<2>, cudaFuncAttributeMaxDynamicSharedMemorySize, 61440);

    const int BS_X  = NTOK * DIM;
    const int BS_KV = NKV * DIM;

    // 0. Weight conversion to bf16 (single fused launch)
    cvt_all<<<1584, 256>>>(pq_w, wq, pk_w, wk, pv_w, wv, ff1_w, w1, ff2_w, w2);

    // 1. LN1 (bf16 output)
    ln_kernel<<<BATCH * NTOK / 8, 256>>>(x, ln1_g, ln1_b, xn);

    // 2. Depthwise convs (+bias+BN, bf16 in/out, 2 ch/thread)
    dwconv_bn<<<BATCH * 1024, 192>>>(xn, dwq_w, dwq_b, bnq_g, bnq_b, qc, 32, 32, 1, 0,    BS_X, 0,    BS_X);
    dwconv_bn<<<BATCH * 256,  192>>>(xn, dwq_w, dwq_b, bnq_g, bnq_b, qc, 16, 16, 1, 1024, BS_X, 1024, BS_X);
    dwconv_bn<<<BATCH * 256,  192>>>(xn, dwk_w, dwk_b, bnk_g, bnk_b, kc, 32, 16, 2, 0,    BS_X, 0,    BS_KV);
    dwconv_bn<<<BATCH * 64,   192>>>(xn, dwk_w, dwk_b, bnk_g, bnk_b, kc, 16, 8,  2, 1024, BS_X, 256,  BS_KV);
    dwconv_bn<<<BATCH * 256,  192>>>(xn, dwv_w, dwv_b, bnv_g, bnv_b, vc, 32, 16, 2, 0,    BS_X, 0,    BS_KV);
    dwconv_bn<<<BATCH * 64,   192>>>(xn, dwv_w, dwv_b, bnv_g, bnv_b, vc, 16, 8,  2, 1024, BS_X, 256,  BS_KV);

    // 3. Q/K/V projections (bf16 tensor cores + ldmatrix)
    gemm_bf<0><<<dim3(3, 320), 256, 61440>>>(qc, wq, pq_b, nullptr, Q, BATCH * NTOK, DIM, DIM);
    gemm_bf<0><<<dim3(3, 80),  256, 61440>>>(kc, wk, pk_b, nullptr, K, BATCH * NKV,  DIM, DIM);
    gemm_bf<0><<<dim3(3, 80),  256, 61440>>>(vc, wv, pv_b, nullptr, V, BATCH * NKV,  DIM, DIM);

    // 4. Fused flash attention (+ residual)
    attn_fused<<<dim3(16, BATCH * HEADS), 128>>>(Q, K, V, x, x2, 0,    0,   NKV);
    attn_fused<<<dim3(4,  BATCH * HEADS), 128>>>(Q, K, V, x, x2, 1024, 256, 64);

    // 5. LN2 + FFN (residual fused into FFN2 epilogue, writes d_out)
    ln_kernel<<<BATCH * NTOK / 8, 256>>>(x2, ln2_g, ln2_b, xn);
    gemm_bf<1><<<dim3(12, 320), 256, 61440>>>(xn, w1, ff1_b, nullptr, h1, BATCH * NTOK, FFDIM, DIM);
    gemm_bf<2><<<dim3(3, 320),  256, 61440>>>(h1, w2, ff2_b, x2, out, BATCH * NTOK, DIM, FFDIM);
}

// round 11
// speedup vs baseline: 5.5145x; 1.0810x over previous
#include <cuda_runtime.h>
#include <cuda_bf16.h>
#include <math.h>
#include <stdint.h>

// ---------------------------------------------------------------------------
// Problem constants
// ---------------------------------------------------------------------------
#define BATCH   32
#define NTOK    1280
#define NS_     1024
#define NT_     256
#define DIM     384
#define HEADS   8
#define HDIM    48
#define NKV     320
#define FFDIM   1536
#define ATT_SCALE 0.14433756729740643f

typedef __nv_bfloat16 bf16;

// ---------------------------------------------------------------------------
// Scratch (device globals; no allocation allowed)
// ---------------------------------------------------------------------------
__device__ bf16  g_xn [BATCH * NTOK * DIM];
__device__ bf16  g_qc [BATCH * NTOK * DIM];
__device__ bf16  g_kc [BATCH * NKV  * DIM];
__device__ bf16  g_vc [BATCH * NKV  * DIM];
__device__ bf16  g_Q  [BATCH * NTOK * DIM];
__device__ bf16  g_K  [BATCH * NKV  * DIM];
__device__ bf16  g_V  [BATCH * NKV  * DIM];
__device__ float g_x2 [BATCH * NTOK * DIM];
__device__ bf16  g_h1 [BATCH * NTOK * FFDIM];
__device__ bf16  g_wq [DIM * DIM];
__device__ bf16  g_wk [DIM * DIM];
__device__ bf16  g_wv [DIM * DIM];
__device__ bf16  g_w1 [FFDIM * DIM];
__device__ bf16  g_w2 [DIM * FFDIM];

// ---------------------------------------------------------------------------
// Helpers
// ---------------------------------------------------------------------------
__device__ __forceinline__ void mma_bf16(float* c, const uint32_t* a, const uint32_t* b) {
    asm volatile(
        "mma.sync.aligned.m16n8k16.row.col.f32.bf16.bf16.f32 "
        "{%0,%1,%2,%3}, {%4,%5,%6,%7}, {%8,%9}, {%0,%1,%2,%3};"
        : "+f"(c[0]), "+f"(c[1]), "+f"(c[2]), "+f"(c[3])
        : "r"(a[0]), "r"(a[1]), "r"(a[2]), "r"(a[3]), "r"(b[0]), "r"(b[1]));
}

__device__ __forceinline__ void ldsm_x4(uint32_t addr, uint32_t* r) {
    asm volatile("ldmatrix.sync.aligned.m8n8.x4.shared.b16 {%0,%1,%2,%3}, [%4];"
        : "=r"(r[0]), "=r"(r[1]), "=r"(r[2]), "=r"(r[3]) : "r"(addr));
}

__device__ __forceinline__ void ldsm_x4_t(uint32_t addr, uint32_t* r) {
    asm volatile("ldmatrix.sync.aligned.m8n8.x4.trans.shared.b16 {%0,%1,%2,%3}, [%4];"
        : "=r"(r[0]), "=r"(r[1]), "=r"(r[2]), "=r"(r[3]) : "r"(addr));
}

__device__ __forceinline__ uint32_t pack_bf2(float lo, float hi) {
    __nv_bfloat162 p = __floats2bfloat162_rn(lo, hi);
    return *(uint32_t*)&p;
}

#define CP_A16(dst, src) \
    asm volatile("cp.async.ca.shared.global [%0], [%1], 16;" :: "r"(dst), "l"(src))
#define CP_COMMIT() asm volatile("cp.async.commit_group;")
#define CP_WAIT1()  asm volatile("cp.async.wait_group 1;")
#define CP_WAIT0()  asm volatile("cp.async.wait_group 0;")

// ---------------------------------------------------------------------------
// Fused weight conversion fp32 -> bf16 for all 5 matrices, float4-vectorized.
// ---------------------------------------------------------------------------
__global__ void cvt_all(const float* __restrict__ s0, bf16* __restrict__ d0,
                        const float* __restrict__ s1, bf16* __restrict__ d1,
                        const float* __restrict__ s2, bf16* __restrict__ d2,
                        const float* __restrict__ s3, bf16* __restrict__ d3,
                        const float* __restrict__ s4, bf16* __restrict__ d4) {
    int i = blockIdx.x * 256 + threadIdx.x;
    const float* s; bf16* d;
    if      (i <  36864) { s = s0; d = d0; }
    else if (i <  73728) { s = s1; d = d1; i -=  36864; }
    else if (i < 110592) { s = s2; d = d2; i -=  73728; }
    else if (i < 258048) { s = s3; d = d3; i -= 110592; }
    else                 { s = s4; d = d4; i -= 258048; }
    float4 v = ((const float4*)s)[i];
    uint2 o;
    o.x = pack_bf2(v.x, v.y);
    o.y = pack_bf2(v.z, v.w);
    ((uint2*)d)[i] = o;
}

// ---------------------------------------------------------------------------
// LayerNorm: warp per token, float4 loads, bf16 packed stores.
// ---------------------------------------------------------------------------
__global__ void ln_kernel(const float* __restrict__ x, const float* __restrict__ g,
                          const float* __restrict__ b, bf16* __restrict__ out) {
    int tok  = (blockIdx.x * 256 + threadIdx.x) >> 5;
    int lane = threadIdx.x & 31;
    const float* xp = x + (size_t)tok * DIM;
    float4 v[3];
    float s = 0.0f, ss = 0.0f;
#pragma unroll
    for (int i = 0; i < 3; i++) {
        v[i] = *(const float4*)(xp + (lane + 32 * i) * 4);
        s  += v[i].x + v[i].y + v[i].z + v[i].w;
        ss += v[i].x * v[i].x + v[i].y * v[i].y + v[i].z * v[i].z + v[i].w * v[i].w;
    }
#pragma unroll
    for (int o = 16; o > 0; o >>= 1) {
        s  += __shfl_xor_sync(0xffffffffu, s,  o);
        ss += __shfl_xor_sync(0xffffffffu, ss, o);
    }
    float mean = s * (1.0f / DIM);
    float var  = ss * (1.0f / DIM) - mean * mean;
    float rstd = rsqrtf(var + 1e-5f);
    bf16* op = out + (size_t)tok * DIM;
#pragma unroll
    for (int i = 0; i < 3; i++) {
        int c = (lane + 32 * i) * 4;
        float4 gg = *(const float4*)(g + c);
        float4 bb = *(const float4*)(b + c);
        uint2 w;
        w.x = pack_bf2((v[i].x - mean) * rstd * gg.x + bb.x,
                       (v[i].y - mean) * rstd * gg.y + bb.y);
        w.y = pack_bf2((v[i].z - mean) * rstd * gg.z + bb.z,
                       (v[i].w - mean) * rstd * gg.w + bb.w);
        *(uint2*)(op + c) = w;
    }
}

// ---------------------------------------------------------------------------
// Depthwise 3x3 conv + bias + BN affine; 2 channels/thread, bf16x2 words.
// ---------------------------------------------------------------------------
__global__ void dwconv_bn(const bf16* __restrict__ in, const float* __restrict__ w,
                          const float* __restrict__ cb, const float* __restrict__ bng,
                          const float* __restrict__ bnb, bf16* __restrict__ out,
                          int hw_in, int hw_out, int stride,
                          int in_boff, int in_bstride, int out_boff, int out_bstride) {
    int c   = threadIdx.x * 2;
    int blk = blockIdx.x;
    int ox  = blk % hw_out;
    int oy  = (blk / hw_out) % hw_out;
    int b   = blk / (hw_out * hw_out);
    const bf16* ip = in + (size_t)b * in_bstride + (size_t)in_boff * DIM;
    float acc0 = cb[c], acc1 = cb[c + 1];
#pragma unroll
    for (int ky = 0; ky < 3; ky++) {
        int iy = oy * stride - 1 + ky;
        if (iy < 0 || iy >= hw_in) continue;
#pragma unroll
        for (int kx = 0; kx < 3; kx++) {
            int ix = ox * stride - 1 + kx;
            if (ix < 0 || ix >= hw_in) continue;
            uint32_t raw = *(const uint32_t*)(ip + (size_t)(iy * hw_in + ix) * DIM + c);
            __nv_bfloat162 pv = *(__nv_bfloat162*)&raw;
            int j = ky * 3 + kx;
            acc0 += __bfloat162float(pv.x) * w[c * 9 + j];
            acc1 += __bfloat162float(pv.y) * w[(c + 1) * 9 + j];
        }
    }
    float rs = rsqrtf(1.0f + 1e-5f);
    float o0 = acc0 * (bng[c] * rs)     + bnb[c];
    float o1 = acc1 * (bng[c + 1] * rs) + bnb[c + 1];
    *(uint32_t*)(out + (size_t)b * out_bstride + (size_t)(out_boff + oy * hw_out + ox) * DIM + c)
        = pack_bf2(o0, o1);
}

// K and V conv share geometry (stride 2) — one launch, blockIdx.y selects set.
__global__ void dwconv_bn_kv(const bf16* __restrict__ in,
                             const float* __restrict__ wk, const float* __restrict__ cbk,
                             const float* __restrict__ gk, const float* __restrict__ bbk,
                             const float* __restrict__ wv, const float* __restrict__ cbv,
                             const float* __restrict__ gv, const float* __restrict__ bbv,
                             bf16* __restrict__ outk, bf16* __restrict__ outv,
                             int hw_in, int hw_out,
                             int in_boff, int in_bstride, int out_boff, int out_bstride) {
    const float* w  = blockIdx.y ? wv  : wk;
    const float* cb = blockIdx.y ? cbv : cbk;
    const float* bng = blockIdx.y ? gv : gk;
    const float* bnb = blockIdx.y ? bbv : bbk;
    bf16* out = blockIdx.y ? outv : outk;
    int c   = threadIdx.x * 2;
    int blk = blockIdx.x;
    int ox  = blk % hw_out;
    int oy  = (blk / hw_out) % hw_out;
    int b   = blk / (hw_out * hw_out);
    const bf16* ip = in + (size_t)b * in_bstride + (size_t)in_boff * DIM;
    float acc0 = cb[c], acc1 = cb[c + 1];
#pragma unroll
    for (int ky = 0; ky < 3; ky++) {
        int iy = oy * 2 - 1 + ky;
        if (iy < 0 || iy >= hw_in) continue;
#pragma unroll
        for (int kx = 0; kx < 3; kx++) {
            int ix = ox * 2 - 1 + kx;
            if (ix < 0 || ix >= hw_in) continue;
            uint32_t raw = *(const uint32_t*)(ip + (size_t)(iy * hw_in + ix) * DIM + c);
            __nv_bfloat162 pv = *(__nv_bfloat162*)&raw;
            int j = ky * 3 + kx;
            acc0 += __bfloat162float(pv.x) * w[c * 9 + j];
            acc1 += __bfloat162float(pv.y) * w[(c + 1) * 9 + j];
        }
    }
    float rs = rsqrtf(1.0f + 1e-5f);
    float o0 = acc0 * (bng[c] * rs)     + bnb[c];
    float o1 = acc1 * (bng[c + 1] * rs) + bnb[c + 1];
    *(uint32_t*)(out + (size_t)b * out_bstride + (size_t)(out_boff + oy * hw_out + ox) * DIM + c)
        = pack_bf2(o0, o1);
}

// ---------------------------------------------------------------------------
// cp.async 3-stage BF16 GEMM with ldmatrix fragment loads (unchanged).
// ---------------------------------------------------------------------------
#define BSTG 10240

__device__ __forceinline__ void gemm_load_stage_bf(
    uint32_t smem_u32, const bf16* Asrc, const bf16* Bsrc, int s, int k0) {
    uint32_t dA = smem_u32 + (uint32_t)(s * BSTG) * 2u;
    const bf16* pA = Asrc + k0;
    CP_A16(dA, pA);
    CP_A16(dA + 16u, pA + 8);
    uint32_t dB = smem_u32 + (uint32_t)(s * BSTG + 5120) * 2u;
    const bf16* pB = Bsrc + k0;
    CP_A16(dB, pB);
    CP_A16(dB + 16u, pB + 8);
}

template<int EPI>
__global__ void __launch_bounds__(256, 2)
gemm_bf(const bf16* __restrict__ A, const bf16* __restrict__ W,
        const float* __restrict__ bias, const float* __restrict__ res,
        void* __restrict__ Cv, int M, int N, int K) {
    extern __shared__ bf16 smem_bf[];
    uint32_t smem_u32 = (uint32_t)__cvta_generic_to_shared(smem_bf);

    int n0 = blockIdx.x * 128, m0 = blockIdx.y * 128;
    int t = threadIdx.x;
    int row = t >> 1, half = t & 1;

    uint32_t stoff = (uint32_t)(row * 40 + half * 16) * 2u;
    const bf16* Asrc = A + (size_t)(m0 + row) * K + half * 16;
    const bf16* Bsrc = W + (size_t)(n0 + row) * K + half * 16;

    int lane = t & 31, g = lane >> 2, tig = lane & 3;
    int w = t >> 5;
    int wm = (w >> 2) * 64, wn = (w & 3) * 32;

    int arow = wm + ((lane >> 3) & 1) * 8 + (lane & 7);
    int akw  = (lane >> 4) * 4;
    uint32_t a_base[4];
#pragma unroll
    for (int mt = 0; mt < 4; mt++)
        a_base[mt] = smem_u32 + (uint32_t)(((arow + mt * 16) * 20 + akw) * 4);
    int brow = wn + ((lane >> 4) & 1) * 8 + (lane & 7);
    int bkw  = ((lane >> 3) & 1) * 4;
    uint32_t b_base[2];
#pragma unroll
    for (int p = 0; p < 2; p++)
        b_base[p] = smem_u32 + (uint32_t)((2560 + (brow + p * 16) * 20 + bkw) * 4);

    float acc[4][4][4] = {};
    int ntiles = K >> 5;

    gemm_load_stage_bf(smem_u32 + stoff, Asrc, Bsrc, 0, 0);
    CP_COMMIT();
    gemm_load_stage_bf(smem_u32 + stoff, Asrc, Bsrc, 1, 32);
    CP_COMMIT();

    for (int i = 0; i < ntiles; i++) {
        CP_WAIT1();
        __syncthreads();
        if (i + 2 < ntiles)
            gemm_load_stage_bf(smem_u32 + stoff, Asrc, Bsrc, (i + 2) % 3, (i + 2) * 32);
        CP_COMMIT();

        uint32_t so = (uint32_t)((i % 3) * 20480);
#pragma unroll
        for (int ks = 0; ks < 2; ks++) {
            uint32_t af[4][4], bb[2][4];
#pragma unroll
            for (int mt = 0; mt < 4; mt++)
                ldsm_x4(a_base[mt] + so + ks * 32, af[mt]);
#pragma unroll
            for (int p = 0; p < 2; p++)
                ldsm_x4(b_base[p] + so + ks * 32, bb[p]);
#pragma unroll
            for (int mt = 0; mt < 4; mt++)
#pragma unroll
                for (int nt = 0; nt < 4; nt++) {
                    uint32_t bfr[2] = { bb[nt >> 1][(nt & 1) * 2], bb[nt >> 1][(nt & 1) * 2 + 1] };
                    mma_bf16(acc[mt][nt], af[mt], bfr);
                }
        }
    }

#pragma unroll
    for (int mt = 0; mt < 4; mt++) {
#pragma unroll
        for (int nt = 0; nt < 4; nt++) {
            int rbase = m0 + wm + mt * 16 + g;
            int col = n0 + wn + nt * 8 + 2 * tig;
#pragma unroll
            for (int hh = 0; hh < 2; hh++) {
                int r = rbase + hh * 8;
                float v0 = acc[mt][nt][hh * 2 + 0] + bias[col];
                float v1 = acc[mt][nt][hh * 2 + 1] + bias[col + 1];
                if (EPI == 1) {
                    v0 = 0.5f * v0 * (1.0f + erff(v0 * 0.70710678118654752f));
                    v1 = 0.5f * v1 * (1.0f + erff(v1 * 0.70710678118654752f));
                }
                size_t gi = (size_t)r * N + col;
                if (EPI == 2) {
                    float* C = (float*)Cv;
                    *(float2*)(C + gi) = make_float2(v0 + res[gi], v1 + res[gi + 1]);
                } else {
                    bf16* C = (bf16*)Cv;
                    *(uint32_t*)(C + gi) = pack_bf2(v0, v1);
                }
            }
        }
    }
}

// ---------------------------------------------------------------------------
// Fused flash attention, cp.async double-buffered K/V + ldmatrix fragments.
// grid: (20, B*H): blockIdx.x 0..15 = search tiles (nkv=320),
//                  16..19 = target tiles (nkv=64, kv_base=256).
// All smem tiles have row stride 56 bf16 (112 B, 16B-aligned, conflict-free).
// ---------------------------------------------------------------------------
__global__ void __launch_bounds__(128)
attn_fused(const bf16* __restrict__ Q, const bf16* __restrict__ Kg,
           const bf16* __restrict__ Vg, const float* __restrict__ x,
           float* __restrict__ x2) {
    __shared__ __align__(16) bf16 Qs[64][56];
    __shared__ __align__(16) bf16 Ks[2][64][56];
    __shared__ __align__(16) bf16 Vs[2][64][56];   // natural [kv][d] layout
    __shared__ __align__(16) bf16 Ps[4][16][72];

    int bh = blockIdx.y, b = bh >> 3, h = bh & 7;
    int bx = blockIdx.x;
    int q_base, kv_base, niter;
    if (bx < 16) { q_base = bx * 64;               kv_base = 0;   niter = 5; }
    else         { q_base = 1024 + (bx - 16) * 64; kv_base = 256; niter = 1; }

    int t = threadIdx.x;
    int w = t >> 5, lane = t & 31, g = lane >> 2, tig = lane & 3;
    int wrow = w * 16;

    uint32_t qs_u32 = (uint32_t)__cvta_generic_to_shared(&Qs[0][0]);
    uint32_t ks_u32 = (uint32_t)__cvta_generic_to_shared(&Ks[0][0][0]);
    uint32_t vs_u32 = (uint32_t)__cvta_generic_to_shared(&Vs[0][0][0]);

    // stage Q (regular loads)
    for (int idx = t; idx < 384; idx += 128) {
        int r = idx / 6, c8 = (idx % 6) * 8;
        uint4 raw = *(const uint4*)(Q + (size_t)(b * NTOK + q_base + r) * DIM + h * HDIM + c8);
        *(uint2*)&Qs[r][c8]     = make_uint2(raw.x, raw.y);
        *(uint2*)&Qs[r][c8 + 4] = make_uint2(raw.z, raw.w);
    }

    // stage KV tile 0 (cp.async)
    {
        const bf16* kbase = Kg + (size_t)(b * NKV + kv_base) * DIM + h * HDIM;
        const bf16* vbase = Vg + (size_t)(b * NKV + kv_base) * DIM + h * HDIM;
#pragma unroll
        for (int j0 = 0; j0 < 768; j0 += 128) {
            int j = j0 + t;
            int hv = j >= 384;
            int jj = hv ? j - 384 : j;
            int r = jj / 6, c8 = (jj % 6) * 8;
            const bf16* src = (hv ? vbase : kbase) + (size_t)r * DIM + c8;
            uint32_t dst = (hv ? vs_u32 : ks_u32) + (uint32_t)((r * 56 + c8) * 2);
            CP_A16(dst, src);
        }
        CP_COMMIT();
    }
    __syncthreads();

    // Q fragments via ldmatrix (3 k16 steps over d=48)
    uint32_t qf[3][4];
    {
        uint32_t qaddr = qs_u32 + (uint32_t)(((wrow + (lane & 15)) * 56 + (lane >> 4) * 8) * 2);
#pragma unroll
        for (int kt = 0; kt < 3; kt++)
            ldsm_x4(qaddr + kt * 32, qf[kt]);
    }

    // ldmatrix lane addresses (buffer 0, bytes; buffer stride 7168)
    uint32_t kaddr0 = ks_u32 + (uint32_t)((((lane & 7) + ((lane >> 4) & 1) * 8) * 56
                                           + ((lane >> 3) & 1) * 8) * 2);
    uint32_t vaddr0 = vs_u32 + (uint32_t)(((lane & 15) * 56 + (lane >> 4) * 8) * 2);

    float m0r = -1e30f, m1r = -1e30f, l0 = 0.0f, l1 = 0.0f;
    float oacc[6][4] = {};
    uint32_t* Pw = (uint32_t*)&Ps[w][0][0];

    for (int i = 0; i < niter; i++) {
        CP_WAIT0();
        __syncthreads();

        // prefetch next tile into the other buffer
        if (i + 1 < niter) {
            int k0n = (i + 1) * 64;
            uint32_t bufo = (uint32_t)(((i + 1) & 1) * 7168);
            const bf16* kbase = Kg + (size_t)(b * NKV + kv_base + k0n) * DIM + h * HDIM;
            const bf16* vbase = Vg + (size_t)(b * NKV + kv_base + k0n) * DIM + h * HDIM;
#pragma unroll
            for (int j0 = 0; j0 < 768; j0 += 128) {
                int j = j0 + t;
                int hv = j >= 384;
                int jj = hv ? j - 384 : j;
                int r = jj / 6, c8 = (jj % 6) * 8;
                const bf16* src = (hv ? vbase : kbase) + (size_t)r * DIM + c8;
                uint32_t dst = (hv ? vs_u32 : ks_u32) + bufo + (uint32_t)((r * 56 + c8) * 2);
                CP_A16(dst, src);
            }
        }
        CP_COMMIT();

        uint32_t bufc = (uint32_t)((i & 1) * 7168);

        // S = Q @ K^T  (16 q-rows x 64 kv per warp)
        float sf[8][4] = {};
#pragma unroll
        for (int kt = 0; kt < 3; kt++) {
#pragma unroll
            for (int p = 0; p < 4; p++) {
                uint32_t kb[4];
                ldsm_x4(kaddr0 + bufc + (uint32_t)(p * 16 * 112 + kt * 32), kb);
                uint32_t b0[2] = { kb[0], kb[1] };
                uint32_t b1[2] = { kb[2], kb[3] };
                mma_bf16(sf[2 * p],     qf[kt], b0);
                mma_bf16(sf[2 * p + 1], qf[kt], b1);
            }
        }
#pragma unroll
        for (int nt = 0; nt < 8; nt++) {
            sf[nt][0] *= ATT_SCALE; sf[nt][1] *= ATT_SCALE;
            sf[nt][2] *= ATT_SCALE; sf[nt][3] *= ATT_SCALE;
        }

        // online softmax (rows g and g+8)
        float tm0 = -1e30f, tm1 = -1e30f;
#pragma unroll
        for (int nt = 0; nt < 8; nt++) {
            tm0 = fmaxf(tm0, fmaxf(sf[nt][0], sf[nt][1]));
            tm1 = fmaxf(tm1, fmaxf(sf[nt][2], sf[nt][3]));
        }
        tm0 = fmaxf(tm0, __shfl_xor_sync(0xffffffffu, tm0, 1));
        tm0 = fmaxf(tm0, __shfl_xor_sync(0xffffffffu, tm0, 2));
        tm1 = fmaxf(tm1, __shfl_xor_sync(0xffffffffu, tm1, 1));
        tm1 = fmaxf(tm1, __shfl_xor_sync(0xffffffffu, tm1, 2));
        float nm0 = fmaxf(m0r, tm0), nm1 = fmaxf(m1r, tm1);
        float f0 = __expf(m0r - nm0), f1 = __expf(m1r - nm1);
        m0r = nm0; m1r = nm1;
        l0 *= f0; l1 *= f1;
#pragma unroll
        for (int nt = 0; nt < 6; nt++) {
            oacc[nt][0] *= f0; oacc[nt][1] *= f0;
            oacc[nt][2] *= f1; oacc[nt][3] *= f1;
        }
#pragma unroll
        for (int nt = 0; nt < 8; nt++) {
            float p0 = __expf(sf[nt][0] - m0r);
            float p1 = __expf(sf[nt][1] - m0r);
            float p2 = __expf(sf[nt][2] - m1r);
            float p3 = __expf(sf[nt][3] - m1r);
            l0 += p0 + p1; l1 += p2 + p3;
            Pw[(g    ) * 36 + nt * 4 + tig] = pack_bf2(p0, p1);
            Pw[(g + 8) * 36 + nt * 4 + tig] = pack_bf2(p2, p3);
        }
        __syncwarp();

        // O += P @ V  (V in natural layout; B frags via ldmatrix.trans)
#pragma unroll
        for (int ks = 0; ks < 4; ks++) {
            uint32_t pa[4];
            pa[0] = Pw[(g    ) * 36 + ks * 8 + tig];
            pa[1] = Pw[(g + 8) * 36 + ks * 8 + tig];
            pa[2] = Pw[(g    ) * 36 + ks * 8 + tig + 4];
            pa[3] = Pw[(g + 8) * 36 + ks * 8 + tig + 4];
#pragma unroll
            for (int jv = 0; jv < 3; jv++) {
                uint32_t vv[4];
                ldsm_x4_t(vaddr0 + bufc + (uint32_t)(ks * 16 * 112 + jv * 32), vv);
                uint32_t b0[2] = { vv[0], vv[1] };
                uint32_t b1[2] = { vv[2], vv[3] };
                mma_bf16(oacc[2 * jv],     pa, b0);
                mma_bf16(oacc[2 * jv + 1], pa, b1);
            }
        }
        __syncwarp();
    }

    // epilogue: normalize + fp32 residual
    l0 += __shfl_xor_sync(0xffffffffu, l0, 1);
    l0 += __shfl_xor_sync(0xffffffffu, l0, 2);
    l1 += __shfl_xor_sync(0xffffffffu, l1, 1);
    l1 += __shfl_xor_sync(0xffffffffu, l1, 2);
    float inv0 = 1.0f / l0, inv1 = 1.0f / l1;
    int r0 = b * NTOK + q_base + wrow + g;
#pragma unroll
    for (int nt = 0; nt < 6; nt++) {
        int col = h * HDIM + nt * 8 + 2 * tig;
        size_t gi0 = (size_t)r0 * DIM + col;
        size_t gi1 = (size_t)(r0 + 8) * DIM + col;
        float2 xa = *(const float2*)(x + gi0);
        float2 xb = *(const float2*)(x + gi1);
        *(float2*)(x2 + gi0) = make_float2(xa.x + oacc[nt][0] * inv0, xa.y + oacc[nt][1] * inv0);
        *(float2*)(x2 + gi1) = make_float2(xb.x + oacc[nt][2] * inv1, xb.y + oacc[nt][3] * inv1);
    }
}

// ---------------------------------------------------------------------------
// Launch
// ---------------------------------------------------------------------------
extern "C" void kernel_launch(void* const* d_in, const int* in_sizes, int n_in,
                              void* d_out, int out_size) {
    (void)in_sizes; (void)n_in; (void)out_size;
    const float* x     = (const float*)d_in[0];
    const float* ln1_g = (const float*)d_in[1];
    const float* ln1_b = (const float*)d_in[2];
    const float* dwq_w = (const float*)d_in[3];
    const float* dwq_b = (const float*)d_in[4];
    const float* bnq_g = (const float*)d_in[5];
    const float* bnq_b = (const float*)d_in[6];
    const float* dwk_w = (const float*)d_in[7];
    const float* dwk_b = (const float*)d_in[8];
    const float* bnk_g = (const float*)d_in[9];
    const float* bnk_b = (const float*)d_in[10];
    const float* dwv_w = (const float*)d_in[11];
    const float* dwv_b = (const float*)d_in[12];
    const float* bnv_g = (const float*)d_in[13];
    const float* bnv_b = (const float*)d_in[14];
    const float* pq_w  = (const float*)d_in[15];
    const float* pq_b  = (const float*)d_in[16];
    const float* pk_w  = (const float*)d_in[17];
    const float* pk_b  = (const float*)d_in[18];
    const float* pv_w  = (const float*)d_in[19];
    const float* pv_b  = (const float*)d_in[20];
    const float* ln2_g = (const float*)d_in[21];
    const float* ln2_b = (const float*)d_in[22];
    const float* ff1_w = (const float*)d_in[23];
    const float* ff1_b = (const float*)d_in[24];
    const float* ff2_w = (const float*)d_in[25];
    const float* ff2_b = (const float*)d_in[26];
    float* out = (float*)d_out;

    bf16 *xn, *qc, *kc, *vc, *Q, *K, *V, *h1, *wq, *wk, *wv, *w1, *w2;
    float *x2;
    cudaGetSymbolAddress((void**)&xn, g_xn);
    cudaGetSymbolAddress((void**)&qc, g_qc);
    cudaGetSymbolAddress((void**)&kc, g_kc);
    cudaGetSymbolAddress((void**)&vc, g_vc);
    cudaGetSymbolAddress((void**)&Q,  g_Q);
    cudaGetSymbolAddress((void**)&K,  g_K);
    cudaGetSymbolAddress((void**)&V,  g_V);
    cudaGetSymbolAddress((void**)&x2, g_x2);
    cudaGetSymbolAddress((void**)&h1, g_h1);
    cudaGetSymbolAddress((void**)&wq, g_wq);
    cudaGetSymbolAddress((void**)&wk, g_wk);
    cudaGetSymbolAddress((void**)&wv, g_wv);
    cudaGetSymbolAddress((void**)&w1, g_w1);
    cudaGetSymbolAddress((void**)&w2, g_w2);

    cudaFuncSetAttribute(gemm_bf<0>, cudaFuncAttributeMaxDynamicSharedMemorySize, 61440);
    cudaFuncSetAttribute(gemm_bf<1>, cudaFuncAttributeMaxDynamicSharedMemorySize, 61440);
    cudaFuncSetAttribute(gemm_bf<2>, cudaFuncAttributeMaxDynamicSharedMemorySize, 61440);

    const int BS_X  = NTOK * DIM;
    const int BS_KV = NKV * DIM;

    // 0. Weight conversion to bf16 (single fused launch)
    cvt_all<<<1584, 256>>>(pq_w, wq, pk_w, wk, pv_w, wv, ff1_w, w1, ff2_w, w2);

    // 1. LN1 (bf16 output)
    ln_kernel<<<BATCH * NTOK / 8, 256>>>(x, ln1_g, ln1_b, xn);

    // 2. Depthwise convs (+bias+BN); K/V merged per geometry
    dwconv_bn<<<BATCH * 1024, 192>>>(xn, dwq_w, dwq_b, bnq_g, bnq_b, qc, 32, 32, 1, 0,    BS_X, 0,    BS_X);
    dwconv_bn<<<BATCH * 256,  192>>>(xn, dwq_w, dwq_b, bnq_g, bnq_b, qc, 16, 16, 1, 1024, BS_X, 1024, BS_X);
    dwconv_bn_kv<<<dim3(BATCH * 256, 2), 192>>>(xn, dwk_w, dwk_b, bnk_g, bnk_b,
                                                dwv_w, dwv_b, bnv_g, bnv_b,
                                                kc, vc, 32, 16, 0,    BS_X, 0,   BS_KV);
    dwconv_bn_kv<<<dim3(BATCH * 64,  2), 192>>>(xn, dwk_w, dwk_b, bnk_g, bnk_b,
                                                dwv_w, dwv_b, bnv_g, bnv_b,
                                                kc, vc, 16, 8,  1024, BS_X, 256, BS_KV);

    // 3. Q/K/V projections (bf16 tensor cores + ldmatrix)
    gemm_bf<0><<<dim3(3, 320), 256, 61440>>>(qc, wq, pq_b, nullptr, Q, BATCH * NTOK, DIM, DIM);
    gemm_bf<0><<<dim3(3, 80),  256, 61440>>>(kc, wk, pk_b, nullptr, K, BATCH * NKV,  DIM, DIM);
    gemm_bf<0><<<dim3(3, 80),  256, 61440>>>(vc, wv, pv_b, nullptr, V, BATCH * NKV,  DIM, DIM);

    // 4. Fused flash attention (+ residual), search & target in one launch
    attn_fused<<<dim3(20, BATCH * HEADS), 128>>>(Q, K, V, x, x2);

    // 5. LN2 + FFN (residual fused into FFN2 epilogue, writes d_out)
    ln_kernel<<<BATCH * NTOK / 8, 256>>>(x2, ln2_g, ln2_b, xn);
    gemm_bf<1><<<dim3(12, 320), 256, 61440>>>(xn, w1, ff1_b, nullptr, h1, BATCH * NTOK, FFDIM, DIM);
    gemm_bf<2><<<dim3(3, 320),  256, 61440>>>(h1, w2, ff2_b, x2, out, BATCH * NTOK, DIM, FFDIM);
}

// round 12
// speedup vs baseline: 5.6353x; 1.0219x over previous
#include <cuda_runtime.h>
#include <cuda_bf16.h>
#include <math.h>
#include <stdint.h>

// ---------------------------------------------------------------------------
// Problem constants
// ---------------------------------------------------------------------------
#define BATCH   32
#define NTOK    1280
#define NS_     1024
#define NT_     256
#define DIM     384
#define HEADS   8
#define HDIM    48
#define NKV     320
#define FFDIM   1536
#define ATT_SCALE 0.14433756729740643f
// ATT_SCALE * log2(e): softmax computed in base-2 domain
#define ATT_SC2  0.20823031926528282f

typedef __nv_bfloat16 bf16;

// ---------------------------------------------------------------------------
// Scratch (device globals; no allocation allowed)
// ---------------------------------------------------------------------------
__device__ bf16  g_xn [BATCH * NTOK * DIM];
__device__ bf16  g_qc [BATCH * NTOK * DIM];
__device__ bf16  g_kc [BATCH * NKV  * DIM];
__device__ bf16  g_vc [BATCH * NKV  * DIM];
__device__ bf16  g_Q  [BATCH * NTOK * DIM];
__device__ bf16  g_K  [BATCH * NKV  * DIM];
__device__ bf16  g_V  [BATCH * NKV  * DIM];
__device__ float g_x2 [BATCH * NTOK * DIM];
__device__ bf16  g_h1 [BATCH * NTOK * FFDIM];
__device__ bf16  g_wq [DIM * DIM];
__device__ bf16  g_wk [DIM * DIM];
__device__ bf16  g_wv [DIM * DIM];
__device__ bf16  g_w1 [FFDIM * DIM];
__device__ bf16  g_w2 [DIM * FFDIM];

// ---------------------------------------------------------------------------
// Helpers
// ---------------------------------------------------------------------------
__device__ __forceinline__ void mma_bf16(float* c, const uint32_t* a, const uint32_t* b) {
    asm volatile(
        "mma.sync.aligned.m16n8k16.row.col.f32.bf16.bf16.f32 "
        "{%0,%1,%2,%3}, {%4,%5,%6,%7}, {%8,%9}, {%0,%1,%2,%3};"
        : "+f"(c[0]), "+f"(c[1]), "+f"(c[2]), "+f"(c[3])
        : "r"(a[0]), "r"(a[1]), "r"(a[2]), "r"(a[3]), "r"(b[0]), "r"(b[1]));
}

__device__ __forceinline__ void ldsm_x4(uint32_t addr, uint32_t* r) {
    asm volatile("ldmatrix.sync.aligned.m8n8.x4.shared.b16 {%0,%1,%2,%3}, [%4];"
        : "=r"(r[0]), "=r"(r[1]), "=r"(r[2]), "=r"(r[3]) : "r"(addr));
}

__device__ __forceinline__ void ldsm_x4_t(uint32_t addr, uint32_t* r) {
    asm volatile("ldmatrix.sync.aligned.m8n8.x4.trans.shared.b16 {%0,%1,%2,%3}, [%4];"
        : "=r"(r[0]), "=r"(r[1]), "=r"(r[2]), "=r"(r[3]) : "r"(addr));
}

__device__ __forceinline__ float ex2f(float x) {
    float r;
    asm("ex2.approx.f32 %0, %1;" : "=f"(r) : "f"(x));
    return r;
}

__device__ __forceinline__ uint32_t pack_bf2(float lo, float hi) {
    __nv_bfloat162 p = __floats2bfloat162_rn(lo, hi);
    return *(uint32_t*)&p;
}

#define CP_A16(dst, src) \
    asm volatile("cp.async.ca.shared.global [%0], [%1], 16;" :: "r"(dst), "l"(src))
#define CP_COMMIT() asm volatile("cp.async.commit_group;")
#define CP_WAIT1()  asm volatile("cp.async.wait_group 1;")
#define CP_WAIT0()  asm volatile("cp.async.wait_group 0;")

// ---------------------------------------------------------------------------
// Fused weight conversion fp32 -> bf16 for all 5 matrices, float4-vectorized.
// ---------------------------------------------------------------------------
__global__ void cvt_all(const float* __restrict__ s0, bf16* __restrict__ d0,
                        const float* __restrict__ s1, bf16* __restrict__ d1,
                        const float* __restrict__ s2, bf16* __restrict__ d2,
                        const float* __restrict__ s3, bf16* __restrict__ d3,
                        const float* __restrict__ s4, bf16* __restrict__ d4) {
    int i = blockIdx.x * 256 + threadIdx.x;
    const float* s; bf16* d;
    if      (i <  36864) { s = s0; d = d0; }
    else if (i <  73728) { s = s1; d = d1; i -=  36864; }
    else if (i < 110592) { s = s2; d = d2; i -=  73728; }
    else if (i < 258048) { s = s3; d = d3; i -= 110592; }
    else                 { s = s4; d = d4; i -= 258048; }
    float4 v = ((const float4*)s)[i];
    uint2 o;
    o.x = pack_bf2(v.x, v.y);
    o.y = pack_bf2(v.z, v.w);
    ((uint2*)d)[i] = o;
}

// ---------------------------------------------------------------------------
// LayerNorm: warp per token, float4 loads, bf16 packed stores.
// ---------------------------------------------------------------------------
__global__ void ln_kernel(const float* __restrict__ x, const float* __restrict__ g,
                          const float* __restrict__ b, bf16* __restrict__ out) {
    int tok  = (blockIdx.x * 256 + threadIdx.x) >> 5;
    int lane = threadIdx.x & 31;
    const float* xp = x + (size_t)tok * DIM;
    float4 v[3];
    float s = 0.0f, ss = 0.0f;
#pragma unroll
    for (int i = 0; i < 3; i++) {
        v[i] = *(const float4*)(xp + (lane + 32 * i) * 4);
        s  += v[i].x + v[i].y + v[i].z + v[i].w;
        ss += v[i].x * v[i].x + v[i].y * v[i].y + v[i].z * v[i].z + v[i].w * v[i].w;
    }
#pragma unroll
    for (int o = 16; o > 0; o >>= 1) {
        s  += __shfl_xor_sync(0xffffffffu, s,  o);
        ss += __shfl_xor_sync(0xffffffffu, ss, o);
    }
    float mean = s * (1.0f / DIM);
    float var  = ss * (1.0f / DIM) - mean * mean;
    float rstd = rsqrtf(var + 1e-5f);
    bf16* op = out + (size_t)tok * DIM;
#pragma unroll
    for (int i = 0; i < 3; i++) {
        int c = (lane + 32 * i) * 4;
        float4 gg = *(const float4*)(g + c);
        float4 bb = *(const float4*)(b + c);
        uint2 w;
        w.x = pack_bf2((v[i].x - mean) * rstd * gg.x + bb.x,
                       (v[i].y - mean) * rstd * gg.y + bb.y);
        w.y = pack_bf2((v[i].z - mean) * rstd * gg.z + bb.z,
                       (v[i].w - mean) * rstd * gg.w + bb.w);
        *(uint2*)(op + c) = w;
    }
}

// ---------------------------------------------------------------------------
// Depthwise 3x3 conv core (2 channels/thread, bf16x2 words)
// ---------------------------------------------------------------------------
__device__ __forceinline__ void dw_body(
    const bf16* __restrict__ in, const float* __restrict__ w,
    const float* __restrict__ cb, const float* __restrict__ bng,
    const float* __restrict__ bnb, bf16* __restrict__ out,
    int blk, int hw_in, int hw_out, int stride,
    int in_boff, int out_boff, int out_bstride) {
    int c   = threadIdx.x * 2;
    int ox  = blk % hw_out;
    int oy  = (blk / hw_out) % hw_out;
    int b   = blk / (hw_out * hw_out);
    const bf16* ip = in + (size_t)b * (NTOK * DIM) + (size_t)in_boff * DIM;
    float acc0 = cb[c], acc1 = cb[c + 1];
#pragma unroll
    for (int ky = 0; ky < 3; ky++) {
        int iy = oy * stride - 1 + ky;
        if (iy < 0 || iy >= hw_in) continue;
#pragma unroll
        for (int kx = 0; kx < 3; kx++) {
            int ix = ox * stride - 1 + kx;
            if (ix < 0 || ix >= hw_in) continue;
            uint32_t raw = *(const uint32_t*)(ip + (size_t)(iy * hw_in + ix) * DIM + c);
            __nv_bfloat162 pv = *(__nv_bfloat162*)&raw;
            int j = ky * 3 + kx;
            acc0 += __bfloat162float(pv.x) * w[c * 9 + j];
            acc1 += __bfloat162float(pv.y) * w[(c + 1) * 9 + j];
        }
    }
    float rs = rsqrtf(1.0f + 1e-5f);
    float o0 = acc0 * (bng[c] * rs)     + bnb[c];
    float o1 = acc1 * (bng[c + 1] * rs) + bnb[c + 1];
    *(uint32_t*)(out + (size_t)b * out_bstride + (size_t)(out_boff + oy * hw_out + ox) * DIM + c)
        = pack_bf2(o0, o1);
}

// Q conv: search (32x32, stride 1) + target (16x16, stride 1) in one launch.
__global__ void dwconv_q(const bf16* __restrict__ in, const float* __restrict__ w,
                         const float* __restrict__ cb, const float* __restrict__ bng,
                         const float* __restrict__ bnb, bf16* __restrict__ out) {
    int blk = blockIdx.x;
    if (blk < BATCH * 1024)
        dw_body(in, w, cb, bng, bnb, out, blk, 32, 32, 1, 0, 0, NTOK * DIM);
    else
        dw_body(in, w, cb, bng, bnb, out, blk - BATCH * 1024, 16, 16, 1, 1024, 1024, NTOK * DIM);
}

// K/V conv: blockIdx.y selects K or V; x-partition selects geometry.
__global__ void dwconv_kv(const bf16* __restrict__ in,
                          const float* __restrict__ wk, const float* __restrict__ cbk,
                          const float* __restrict__ gk, const float* __restrict__ bbk,
                          const float* __restrict__ wv, const float* __restrict__ cbv,
                          const float* __restrict__ gv, const float* __restrict__ bbv,
                          bf16* __restrict__ outk, bf16* __restrict__ outv) {
    const float* w   = blockIdx.y ? wv  : wk;
    const float* cb  = blockIdx.y ? cbv : cbk;
    const float* bng = blockIdx.y ? gv  : gk;
    const float* bnb = blockIdx.y ? bbv : bbk;
    bf16* out = blockIdx.y ? outv : outk;
    int blk = blockIdx.x;
    if (blk < BATCH * 256)
        dw_body(in, w, cb, bng, bnb, out, blk, 32, 16, 2, 0, 0, NKV * DIM);
    else
        dw_body(in, w, cb, bng, bnb, out, blk - BATCH * 256, 16, 8, 2, 1024, 256, NKV * DIM);
}

// ---------------------------------------------------------------------------
// cp.async 3-stage BF16 GEMM mainloop (shared by gemm_bf and gemm_proj).
// ---------------------------------------------------------------------------
#define BSTG 10240

__device__ __forceinline__ void gemm_load_stage_bf(
    uint32_t smem_u32, const bf16* Asrc, const bf16* Bsrc, int s, int k0) {
    uint32_t dA = smem_u32 + (uint32_t)(s * BSTG) * 2u;
    const bf16* pA = Asrc + k0;
    CP_A16(dA, pA);
    CP_A16(dA + 16u, pA + 8);
    uint32_t dB = smem_u32 + (uint32_t)(s * BSTG + 5120) * 2u;
    const bf16* pB = Bsrc + k0;
    CP_A16(dB, pB);
    CP_A16(dB + 16u, pB + 8);
}

struct GemmCtx {
    uint32_t a_base[4];
    uint32_t b_base[2];
    uint32_t stoff;
};

__device__ __forceinline__ void gemm_ctx_init(GemmCtx& cx, uint32_t smem_u32) {
    int t = threadIdx.x;
    int row = t >> 1, half = t & 1;
    cx.stoff = (uint32_t)(row * 40 + half * 16) * 2u;
    int lane = t & 31;
    int w = t >> 5;
    int wm = (w >> 2) * 64, wn = (w & 3) * 32;
    int arow = wm + ((lane >> 3) & 1) * 8 + (lane & 7);
    int akw  = (lane >> 4) * 4;
#pragma unroll
    for (int mt = 0; mt < 4; mt++)
        cx.a_base[mt] = smem_u32 + (uint32_t)(((arow + mt * 16) * 20 + akw) * 4);
    int brow = wn + ((lane >> 4) & 1) * 8 + (lane & 7);
    int bkw  = ((lane >> 3) & 1) * 4;
#pragma unroll
    for (int p = 0; p < 2; p++)
        cx.b_base[p] = smem_u32 + (uint32_t)((2560 + (brow + p * 16) * 20 + bkw) * 4);
}

__device__ __forceinline__ void gemm_mainloop(
    const GemmCtx& cx, uint32_t smem_u32,
    const bf16* Asrc, const bf16* Bsrc, int ntiles, float acc[4][4][4]) {
    gemm_load_stage_bf(smem_u32 + cx.stoff, Asrc, Bsrc, 0, 0);
    CP_COMMIT();
    gemm_load_stage_bf(smem_u32 + cx.stoff, Asrc, Bsrc, 1, 32);
    CP_COMMIT();
    for (int i = 0; i < ntiles; i++) {
        CP_WAIT1();
        __syncthreads();
        if (i + 2 < ntiles)
            gemm_load_stage_bf(smem_u32 + cx.stoff, Asrc, Bsrc, (i + 2) % 3, (i + 2) * 32);
        CP_COMMIT();
        uint32_t so = (uint32_t)((i % 3) * 20480);
#pragma unroll
        for (int ks = 0; ks < 2; ks++) {
            uint32_t af[4][4], bb[2][4];
#pragma unroll
            for (int mt = 0; mt < 4; mt++)
                ldsm_x4(cx.a_base[mt] + so + ks * 32, af[mt]);
#pragma unroll
            for (int p = 0; p < 2; p++)
                ldsm_x4(cx.b_base[p] + so + ks * 32, bb[p]);
#pragma unroll
            for (int mt = 0; mt < 4; mt++)
#pragma unroll
                for (int nt = 0; nt < 4; nt++) {
                    uint32_t bfr[2] = { bb[nt >> 1][(nt & 1) * 2], bb[nt >> 1][(nt & 1) * 2 + 1] };
                    mma_bf16(acc[mt][nt], af[mt], bfr);
                }
        }
    }
}

// FFN GEMMs. EPI: 1 = bias+GELU -> bf16, 2 = bias+residual -> fp32.
template<int EPI>
__global__ void __launch_bounds__(256, 2)
gemm_bf(const bf16* __restrict__ A, const bf16* __restrict__ W,
        const float* __restrict__ bias, const float* __restrict__ res,
        void* __restrict__ Cv, int M, int N, int K) {
    extern __shared__ bf16 smem_bf[];
    uint32_t smem_u32 = (uint32_t)__cvta_generic_to_shared(smem_bf);
    int n0 = blockIdx.x * 128, m0 = blockIdx.y * 128;
    int t = threadIdx.x;
    int row = t >> 1, half = t & 1;
    int lane = t & 31, g = lane >> 2, tig = lane & 3;
    int w = t >> 5;
    int wm = (w >> 2) * 64, wn = (w & 3) * 32;

    GemmCtx cx; gemm_ctx_init(cx, smem_u32);
    const bf16* Asrc = A + (size_t)(m0 + row) * K + half * 16;
    const bf16* Bsrc = W + (size_t)(n0 + row) * K + half * 16;
    float acc[4][4][4] = {};
    gemm_mainloop(cx, smem_u32, Asrc, Bsrc, K >> 5, acc);

#pragma unroll
    for (int mt = 0; mt < 4; mt++) {
#pragma unroll
        for (int nt = 0; nt < 4; nt++) {
            int rbase = m0 + wm + mt * 16 + g;
            int col = n0 + wn + nt * 8 + 2 * tig;
#pragma unroll
            for (int hh = 0; hh < 2; hh++) {
                int r = rbase + hh * 8;
                float v0 = acc[mt][nt][hh * 2 + 0] + bias[col];
                float v1 = acc[mt][nt][hh * 2 + 1] + bias[col + 1];
                if (EPI == 1) {
                    v0 = 0.5f * v0 * (1.0f + erff(v0 * 0.70710678118654752f));
                    v1 = 0.5f * v1 * (1.0f + erff(v1 * 0.70710678118654752f));
                }
                size_t gi = (size_t)r * N + col;
                if (EPI == 2) {
                    float* C = (float*)Cv;
                    *(float2*)(C + gi) = make_float2(v0 + res[gi], v1 + res[gi + 1]);
                } else {
                    bf16* C = (bf16*)Cv;
                    *(uint32_t*)(C + gi) = pack_bf2(v0, v1);
                }
            }
        }
    }
}

// Merged Q/K/V projection GEMM: grid (3, 480); by<320 -> Q, <400 -> K, else V.
__global__ void __launch_bounds__(256, 2)
gemm_proj(const bf16* __restrict__ Aq, const bf16* __restrict__ Wq, const float* __restrict__ bq, bf16* __restrict__ Cq,
          const bf16* __restrict__ Ak, const bf16* __restrict__ Wk, const float* __restrict__ bk, bf16* __restrict__ Ck,
          const bf16* __restrict__ Av, const bf16* __restrict__ Wv, const float* __restrict__ bv, bf16* __restrict__ Cv2) {
    extern __shared__ bf16 smem_bf[];
    uint32_t smem_u32 = (uint32_t)__cvta_generic_to_shared(smem_bf);
    int by = blockIdx.y;
    const bf16 *A, *W; const float* bias; bf16* C;
    if (by < 320)      { A = Aq; W = Wq; bias = bq; C = Cq; }
    else if (by < 400) { A = Ak; W = Wk; bias = bk; C = Ck; by -= 320; }
    else               { A = Av; W = Wv; bias = bv; C = Cv2; by -= 400; }

    int n0 = blockIdx.x * 128, m0 = by * 128;
    int t = threadIdx.x;
    int row = t >> 1, half = t & 1;
    int lane = t & 31, g = lane >> 2, tig = lane & 3;
    int w = t >> 5;
    int wm = (w >> 2) * 64, wn = (w & 3) * 32;

    GemmCtx cx; gemm_ctx_init(cx, smem_u32);
    const bf16* Asrc = A + (size_t)(m0 + row) * DIM + half * 16;
    const bf16* Bsrc = W + (size_t)(n0 + row) * DIM + half * 16;
    float acc[4][4][4] = {};
    gemm_mainloop(cx, smem_u32, Asrc, Bsrc, DIM >> 5, acc);

#pragma unroll
    for (int mt = 0; mt < 4; mt++) {
#pragma unroll
        for (int nt = 0; nt < 4; nt++) {
            int rbase = m0 + wm + mt * 16 + g;
            int col = n0 + wn + nt * 8 + 2 * tig;
#pragma unroll
            for (int hh = 0; hh < 2; hh++) {
                int r = rbase + hh * 8;
                float v0 = acc[mt][nt][hh * 2 + 0] + bias[col];
                float v1 = acc[mt][nt][hh * 2 + 1] + bias[col + 1];
                *(uint32_t*)(C + (size_t)r * DIM + col) = pack_bf2(v0, v1);
            }
        }
    }
}

// ---------------------------------------------------------------------------
// Fused flash attention, base-2 online softmax, cp.async K/V + ldmatrix.
// grid: (20, B*H): bx 0..15 search (nkv=320), 16..19 target (nkv=64).
// ---------------------------------------------------------------------------
__global__ void __launch_bounds__(128)
attn_fused(const bf16* __restrict__ Q, const bf16* __restrict__ Kg,
           const bf16* __restrict__ Vg, const float* __restrict__ x,
           float* __restrict__ x2) {
    __shared__ __align__(16) bf16 Qs[64][56];
    __shared__ __align__(16) bf16 Ks[2][64][56];
    __shared__ __align__(16) bf16 Vs[2][64][56];
    __shared__ __align__(16) bf16 Ps[4][16][72];

    int bh = blockIdx.y, b = bh >> 3, h = bh & 7;
    int bx = blockIdx.x;
    int q_base, kv_base, niter;
    if (bx < 16) { q_base = bx * 64;               kv_base = 0;   niter = 5; }
    else         { q_base = 1024 + (bx - 16) * 64; kv_base = 256; niter = 1; }

    int t = threadIdx.x;
    int w = t >> 5, lane = t & 31, g = lane >> 2, tig = lane & 3;
    int wrow = w * 16;

    uint32_t qs_u32 = (uint32_t)__cvta_generic_to_shared(&Qs[0][0]);
    uint32_t ks_u32 = (uint32_t)__cvta_generic_to_shared(&Ks[0][0][0]);
    uint32_t vs_u32 = (uint32_t)__cvta_generic_to_shared(&Vs[0][0][0]);

    for (int idx = t; idx < 384; idx += 128) {
        int r = idx / 6, c8 = (idx % 6) * 8;
        uint4 raw = *(const uint4*)(Q + (size_t)(b * NTOK + q_base + r) * DIM + h * HDIM + c8);
        *(uint2*)&Qs[r][c8]     = make_uint2(raw.x, raw.y);
        *(uint2*)&Qs[r][c8 + 4] = make_uint2(raw.z, raw.w);
    }

    {
        const bf16* kbase = Kg + (size_t)(b * NKV + kv_base) * DIM + h * HDIM;
        const bf16* vbase = Vg + (size_t)(b * NKV + kv_base) * DIM + h * HDIM;
#pragma unroll
        for (int j0 = 0; j0 < 768; j0 += 128) {
            int j = j0 + t;
            int hv = j >= 384;
            int jj = hv ? j - 384 : j;
            int r = jj / 6, c8 = (jj % 6) * 8;
            const bf16* src = (hv ? vbase : kbase) + (size_t)r * DIM + c8;
            uint32_t dst = (hv ? vs_u32 : ks_u32) + (uint32_t)((r * 56 + c8) * 2);
            CP_A16(dst, src);
        }
        CP_COMMIT();
    }
    __syncthreads();

    uint32_t qf[3][4];
    {
        uint32_t qaddr = qs_u32 + (uint32_t)(((wrow + (lane & 15)) * 56 + (lane >> 4) * 8) * 2);
#pragma unroll
        for (int kt = 0; kt < 3; kt++)
            ldsm_x4(qaddr + kt * 32, qf[kt]);
    }

    uint32_t kaddr0 = ks_u32 + (uint32_t)((((lane & 7) + ((lane >> 4) & 1) * 8) * 56
                                           + ((lane >> 3) & 1) * 8) * 2);
    uint32_t vaddr0 = vs_u32 + (uint32_t)(((lane & 15) * 56 + (lane >> 4) * 8) * 2);

    float m0r = -1e30f, m1r = -1e30f, l0 = 0.0f, l1 = 0.0f;
    float oacc[6][4] = {};
    uint32_t* Pw = (uint32_t*)&Ps[w][0][0];

    for (int i = 0; i < niter; i++) {
        CP_WAIT0();
        __syncthreads();

        if (i + 1 < niter) {
            int k0n = (i + 1) * 64;
            uint32_t bufo = (uint32_t)(((i + 1) & 1) * 7168);
            const bf16* kbase = Kg + (size_t)(b * NKV + kv_base + k0n) * DIM + h * HDIM;
            const bf16* vbase = Vg + (size_t)(b * NKV + kv_base + k0n) * DIM + h * HDIM;
#pragma unroll
            for (int j0 = 0; j0 < 768; j0 += 128) {
                int j = j0 + t;
                int hv = j >= 384;
                int jj = hv ? j - 384 : j;
                int r = jj / 6, c8 = (jj % 6) * 8;
                const bf16* src = (hv ? vbase : kbase) + (size_t)r * DIM + c8;
                uint32_t dst = (hv ? vs_u32 : ks_u32) + bufo + (uint32_t)((r * 56 + c8) * 2);
                CP_A16(dst, src);
            }
        }
        CP_COMMIT();

        uint32_t bufc = (uint32_t)((i & 1) * 7168);

        // S' = Q @ K^T * (scale*log2e)   (base-2 softmax domain)
        float sf[8][4] = {};
#pragma unroll
        for (int kt = 0; kt < 3; kt++) {
#pragma unroll
            for (int p = 0; p < 4; p++) {
                uint32_t kb[4];
                ldsm_x4(kaddr0 + bufc + (uint32_t)(p * 16 * 112 + kt * 32), kb);
                uint32_t b0[2] = { kb[0], kb[1] };
                uint32_t b1[2] = { kb[2], kb[3] };
                mma_bf16(sf[2 * p],     qf[kt], b0);
                mma_bf16(sf[2 * p + 1], qf[kt], b1);
            }
        }
#pragma unroll
        for (int nt = 0; nt < 8; nt++) {
            sf[nt][0] *= ATT_SC2; sf[nt][1] *= ATT_SC2;
            sf[nt][2] *= ATT_SC2; sf[nt][3] *= ATT_SC2;
        }

        float tm0 = -1e30f, tm1 = -1e30f;
#pragma unroll
        for (int nt = 0; nt < 8; nt++) {
            tm0 = fmaxf(tm0, fmaxf(sf[nt][0], sf[nt][1]));
            tm1 = fmaxf(tm1, fmaxf(sf[nt][2], sf[nt][3]));
        }
        tm0 = fmaxf(tm0, __shfl_xor_sync(0xffffffffu, tm0, 1));
        tm0 = fmaxf(tm0, __shfl_xor_sync(0xffffffffu, tm0, 2));
        tm1 = fmaxf(tm1, __shfl_xor_sync(0xffffffffu, tm1, 1));
        tm1 = fmaxf(tm1, __shfl_xor_sync(0xffffffffu, tm1, 2));
        float nm0 = fmaxf(m0r, tm0), nm1 = fmaxf(m1r, tm1);
        float f0 = ex2f(m0r - nm0), f1 = ex2f(m1r - nm1);
        m0r = nm0; m1r = nm1;
        l0 *= f0; l1 *= f1;
#pragma unroll
        for (int nt = 0; nt < 6; nt++) {
            oacc[nt][0] *= f0; oacc[nt][1] *= f0;
            oacc[nt][2] *= f1; oacc[nt][3] *= f1;
        }
#pragma unroll
        for (int nt = 0; nt < 8; nt++) {
            float p0 = ex2f(sf[nt][0] - m0r);
            float p1 = ex2f(sf[nt][1] - m0r);
            float p2 = ex2f(sf[nt][2] - m1r);
            float p3 = ex2f(sf[nt][3] - m1r);
            l0 += p0 + p1; l1 += p2 + p3;
            Pw[(g    ) * 36 + nt * 4 + tig] = pack_bf2(p0, p1);
            Pw[(g + 8) * 36 + nt * 4 + tig] = pack_bf2(p2, p3);
        }
        __syncwarp();

#pragma unroll
        for (int ks = 0; ks < 4; ks++) {
            uint32_t pa[4];
            pa[0] = Pw[(g    ) * 36 + ks * 8 + tig];
            pa[1] = Pw[(g + 8) * 36 + ks * 8 + tig];
            pa[2] = Pw[(g    ) * 36 + ks * 8 + tig + 4];
            pa[3] = Pw[(g + 8) * 36 + ks * 8 + tig + 4];
#pragma unroll
            for (int jv = 0; jv < 3; jv++) {
                uint32_t vv[4];
                ldsm_x4_t(vaddr0 + bufc + (uint32_t)(ks * 16 * 112 + jv * 32), vv);
                uint32_t b0[2] = { vv[0], vv[1] };
                uint32_t b1[2] = { vv[2], vv[3] };
                mma_bf16(oacc[2 * jv],     pa, b0);
                mma_bf16(oacc[2 * jv + 1], pa, b1);
            }
        }
        __syncwarp();
    }

    l0 += __shfl_xor_sync(0xffffffffu, l0, 1);
    l0 += __shfl_xor_sync(0xffffffffu, l0, 2);
    l1 += __shfl_xor_sync(0xffffffffu, l1, 1);
    l1 += __shfl_xor_sync(0xffffffffu, l1, 2);
    float inv0 = 1.0f / l0, inv1 = 1.0f / l1;
    int r0 = b * NTOK + q_base + wrow + g;
#pragma unroll
    for (int nt = 0; nt < 6; nt++) {
        int col = h * HDIM + nt * 8 + 2 * tig;
        size_t gi0 = (size_t)r0 * DIM + col;
        size_t gi1 = (size_t)(r0 + 8) * DIM + col;
        float2 xa = *(const float2*)(x + gi0);
        float2 xb = *(const float2*)(x + gi1);
        *(float2*)(x2 + gi0) = make_float2(xa.x + oacc[nt][0] * inv0, xa.y + oacc[nt][1] * inv0);
        *(float2*)(x2 + gi1) = make_float2(xb.x + oacc[nt][2] * inv1, xb.y + oacc[nt][3] * inv1);
    }
}

// ---------------------------------------------------------------------------
// Launch
// ---------------------------------------------------------------------------
extern "C" void kernel_launch(void* const* d_in, const int* in_sizes, int n_in,
                              void* d_out, int out_size) {
    (void)in_sizes; (void)n_in; (void)out_size;
    const float* x     = (const float*)d_in[0];
    const float* ln1_g = (const float*)d_in[1];
    const float* ln1_b = (const float*)d_in[2];
    const float* dwq_w = (const float*)d_in[3];
    const float* dwq_b = (const float*)d_in[4];
    const float* bnq_g = (const float*)d_in[5];
    const float* bnq_b = (const float*)d_in[6];
    const float* dwk_w = (const float*)d_in[7];
    const float* dwk_b = (const float*)d_in[8];
    const float* bnk_g = (const float*)d_in[9];
    const float* bnk_b = (const float*)d_in[10];
    const float* dwv_w = (const float*)d_in[11];
    const float* dwv_b = (const float*)d_in[12];
    const float* bnv_g = (const float*)d_in[13];
    const float* bnv_b = (const float*)d_in[14];
    const float* pq_w  = (const float*)d_in[15];
    const float* pq_b  = (const float*)d_in[16];
    const float* pk_w  = (const float*)d_in[17];
    const float* pk_b  = (const float*)d_in[18];
    const float* pv_w  = (const float*)d_in[19];
    const float* pv_b  = (const float*)d_in[20];
    const float* ln2_g = (const float*)d_in[21];
    const float* ln2_b = (const float*)d_in[22];
    const float* ff1_w = (const float*)d_in[23];
    const float* ff1_b = (const float*)d_in[24];
    const float* ff2_w = (const float*)d_in[25];
    const float* ff2_b = (const float*)d_in[26];
    float* out = (float*)d_out;

    bf16 *xn, *qc, *kc, *vc, *Q, *K, *V, *h1, *wq, *wk, *wv, *w1, *w2;
    float *x2;
    cudaGetSymbolAddress((void**)&xn, g_xn);
    cudaGetSymbolAddress((void**)&qc, g_qc);
    cudaGetSymbolAddress((void**)&kc, g_kc);
    cudaGetSymbolAddress((void**)&vc, g_vc);
    cudaGetSymbolAddress((void**)&Q,  g_Q);
    cudaGetSymbolAddress((void**)&K,  g_K);
    cudaGetSymbolAddress((void**)&V,  g_V);
    cudaGetSymbolAddress((void**)&x2, g_x2);
    cudaGetSymbolAddress((void**)&h1, g_h1);
    cudaGetSymbolAddress((void**)&wq, g_wq);
    cudaGetSymbolAddress((void**)&wk, g_wk);
    cudaGetSymbolAddress((void**)&wv, g_wv);
    cudaGetSymbolAddress((void**)&w1, g_w1);
    cudaGetSymbolAddress((void**)&w2, g_w2);

    cudaFuncSetAttribute(gemm_bf<1>, cudaFuncAttributeMaxDynamicSharedMemorySize, 61440);
    cudaFuncSetAttribute(gemm_bf<2>, cudaFuncAttributeMaxDynamicSharedMemorySize, 61440);
    cudaFuncSetAttribute(gemm_proj,  cudaFuncAttributeMaxDynamicSharedMemorySize, 61440);

    // 1. Weight conversion
    cvt_all<<<1584, 256>>>(pq_w, wq, pk_w, wk, pv_w, wv, ff1_w, w1, ff2_w, w2);

    // 2. LN1
    ln_kernel<<<BATCH * NTOK / 8, 256>>>(x, ln1_g, ln1_b, xn);

    // 3. Depthwise convs (2 launches total)
    dwconv_q<<<BATCH * 1280, 192>>>(xn, dwq_w, dwq_b, bnq_g, bnq_b, qc);
    dwconv_kv<<<dim3(BATCH * 320, 2), 192>>>(xn, dwk_w, dwk_b, bnk_g, bnk_b,
                                             dwv_w, dwv_b, bnv_g, bnv_b, kc, vc);

    // 4. Q/K/V projections — single merged launch
    gemm_proj<<<dim3(3, 480), 256, 61440>>>(qc, wq, pq_b, Q,
                                            kc, wk, pk_b, K,
                                            vc, wv, pv_b, V);

    // 5. Fused flash attention (+ residual) — launch #6 (ncu -s 5 captures this)
    attn_fused<<<dim3(20, BATCH * HEADS), 128>>>(Q, K, V, x, x2);

    // 6. LN2 + FFN
    ln_kernel<<<BATCH * NTOK / 8, 256>>>(x2, ln2_g, ln2_b, xn);
    gemm_bf<1><<<dim3(12, 320), 256, 61440>>>(xn, w1, ff1_b, nullptr, h1, BATCH * NTOK, FFDIM, DIM);
    gemm_bf<2><<<dim3(3, 320),  256, 61440>>>(h1, w2, ff2_b, x2, out, BATCH * NTOK, DIM, FFDIM);
}

// round 15
// speedup vs baseline: 5.6898x; 1.0097x over previous
#include <cuda_runtime.h>
#include <cuda_bf16.h>
#include <math.h>
#include <stdint.h>

// ---------------------------------------------------------------------------
// Problem constants
// ---------------------------------------------------------------------------
#define BATCH   32
#define NTOK    1280
#define NS_     1024
#define NT_     256
#define DIM     384
#define HEADS   8
#define HDIM    48
#define NKV     320
#define FFDIM   1536
#define ATT_SCALE 0.14433756729740643f
// ATT_SCALE * log2(e): softmax computed in base-2 domain
#define ATT_SC2  0.20823031926528282f

typedef __nv_bfloat16 bf16;

// ---------------------------------------------------------------------------
// Scratch (device globals; no allocation allowed)
// ---------------------------------------------------------------------------
__device__ bf16  g_xn [BATCH * NTOK * DIM];
__device__ bf16  g_qc [BATCH * NTOK * DIM];
__device__ bf16  g_kc [BATCH * NKV  * DIM];
__device__ bf16  g_vc [BATCH * NKV  * DIM];
__device__ bf16  g_Q  [BATCH * NTOK * DIM];
__device__ bf16  g_K  [BATCH * NKV  * DIM];
__device__ bf16  g_V  [BATCH * NKV  * DIM];
__device__ float g_x2 [BATCH * NTOK * DIM];
__device__ bf16  g_h1 [BATCH * NTOK * FFDIM];
__device__ bf16  g_wq [DIM * DIM];
__device__ bf16  g_wk [DIM * DIM];
__device__ bf16  g_wv [DIM * DIM];
__device__ bf16  g_w1 [FFDIM * DIM];
__device__ bf16  g_w2 [DIM * FFDIM];

// ---------------------------------------------------------------------------
// Helpers
// ---------------------------------------------------------------------------
__device__ __forceinline__ void mma_bf16(float* c, const uint32_t* a, const uint32_t* b) {
    asm volatile(
        "mma.sync.aligned.m16n8k16.row.col.f32.bf16.bf16.f32 "
        "{%0,%1,%2,%3}, {%4,%5,%6,%7}, {%8,%9}, {%0,%1,%2,%3};"
        : "+f"(c[0]), "+f"(c[1]), "+f"(c[2]), "+f"(c[3])
        : "r"(a[0]), "r"(a[1]), "r"(a[2]), "r"(a[3]), "r"(b[0]), "r"(b[1]));
}

__device__ __forceinline__ void ldsm_x4(uint32_t addr, uint32_t* r) {
    asm volatile("ldmatrix.sync.aligned.m8n8.x4.shared.b16 {%0,%1,%2,%3}, [%4];"
        : "=r"(r[0]), "=r"(r[1]), "=r"(r[2]), "=r"(r[3]) : "r"(addr));
}

__device__ __forceinline__ void ldsm_x4_t(uint32_t addr, uint32_t* r) {
    asm volatile("ldmatrix.sync.aligned.m8n8.x4.trans.shared.b16 {%0,%1,%2,%3}, [%4];"
        : "=r"(r[0]), "=r"(r[1]), "=r"(r[2]), "=r"(r[3]) : "r"(addr));
}

__device__ __forceinline__ float ex2f(float x) {
    float r;
    asm("ex2.approx.f32 %0, %1;" : "=f"(r) : "f"(x));
    return r;
}

__device__ __forceinline__ uint32_t pack_bf2(float lo, float hi) {
    __nv_bfloat162 p = __floats2bfloat162_rn(lo, hi);
    return *(uint32_t*)&p;
}

#define CP_A16(dst, src) \
    asm volatile("cp.async.ca.shared.global [%0], [%1], 16;" :: "r"(dst), "l"(src))
#define CP_COMMIT() asm volatile("cp.async.commit_group;")
#define CP_WAIT1()  asm volatile("cp.async.wait_group 1;")
#define CP_WAIT0()  asm volatile("cp.async.wait_group 0;")

// ---------------------------------------------------------------------------
// LayerNorm body: one warp per token, float4 loads, bf16 packed stores.
// ---------------------------------------------------------------------------
__device__ __forceinline__ void ln_body(const float* __restrict__ x,
                                        const float* __restrict__ g,
                                        const float* __restrict__ b,
                                        bf16* __restrict__ out,
                                        int tok, int lane) {
    const float* xp = x + (size_t)tok * DIM;
    float4 v[3];
    float s = 0.0f, ss = 0.0f;
#pragma unroll
    for (int i = 0; i < 3; i++) {
        v[i] = *(const float4*)(xp + (lane + 32 * i) * 4);
        s  += v[i].x + v[i].y + v[i].z + v[i].w;
        ss += v[i].x * v[i].x + v[i].y * v[i].y + v[i].z * v[i].z + v[i].w * v[i].w;
    }
#pragma unroll
    for (int o = 16; o > 0; o >>= 1) {
        s  += __shfl_xor_sync(0xffffffffu, s,  o);
        ss += __shfl_xor_sync(0xffffffffu, ss, o);
    }
    float mean = s * (1.0f / DIM);
    float var  = ss * (1.0f / DIM) - mean * mean;
    float rstd = rsqrtf(var + 1e-5f);
    bf16* op = out + (size_t)tok * DIM;
#pragma unroll
    for (int i = 0; i < 3; i++) {
        int c = (lane + 32 * i) * 4;
        float4 gg = *(const float4*)(g + c);
        float4 bb = *(const float4*)(b + c);
        uint2 w;
        w.x = pack_bf2((v[i].x - mean) * rstd * gg.x + bb.x,
                       (v[i].y - mean) * rstd * gg.y + bb.y);
        w.y = pack_bf2((v[i].z - mean) * rstd * gg.z + bb.z,
                       (v[i].w - mean) * rstd * gg.w + bb.w);
        *(uint2*)(op + c) = w;
    }
}

// LN2 standalone
__global__ void ln_kernel(const float* __restrict__ x, const float* __restrict__ g,
                          const float* __restrict__ b, bf16* __restrict__ out) {
    int tok  = (blockIdx.x * 256 + threadIdx.x) >> 5;
    ln_body(x, g, b, out, tok, threadIdx.x & 31);
}

// ---------------------------------------------------------------------------
// Fused: weight conversion (blocks 0..1583) + LN1 (blocks 1584..6703)
// ---------------------------------------------------------------------------
__global__ void cvt_ln1(const float* __restrict__ s0, bf16* __restrict__ d0,
                        const float* __restrict__ s1, bf16* __restrict__ d1,
                        const float* __restrict__ s2, bf16* __restrict__ d2,
                        const float* __restrict__ s3, bf16* __restrict__ d3,
                        const float* __restrict__ s4, bf16* __restrict__ d4,
                        const float* __restrict__ x, const float* __restrict__ lg,
                        const float* __restrict__ lb, bf16* __restrict__ xo) {
    if (blockIdx.x < 1584) {
        int i = blockIdx.x * 256 + threadIdx.x;
        const float* s; bf16* d;
        if      (i <  36864) { s = s0; d = d0; }
        else if (i <  73728) { s = s1; d = d1; i -=  36864; }
        else if (i < 110592) { s = s2; d = d2; i -=  73728; }
        else if (i < 258048) { s = s3; d = d3; i -= 110592; }
        else                 { s = s4; d = d4; i -= 258048; }
        float4 v = ((const float4*)s)[i];
        uint2 o;
        o.x = pack_bf2(v.x, v.y);
        o.y = pack_bf2(v.z, v.w);
        ((uint2*)d)[i] = o;
    } else {
        int tok = ((blockIdx.x - 1584) * 256 + threadIdx.x) >> 5;
        ln_body(x, lg, lb, xo, tok, threadIdx.x & 31);
    }
}

// ---------------------------------------------------------------------------
// Depthwise 3x3 conv core (2 channels/thread, bf16x2 words)
// ---------------------------------------------------------------------------
__device__ __forceinline__ void dw_body(
    const bf16* __restrict__ in, const float* __restrict__ w,
    const float* __restrict__ cb, const float* __restrict__ bng,
    const float* __restrict__ bnb, bf16* __restrict__ out,
    int blk, int hw_in, int hw_out, int stride,
    int in_boff, int out_boff, int out_bstride) {
    int c   = threadIdx.x * 2;
    int ox  = blk % hw_out;
    int oy  = (blk / hw_out) % hw_out;
    int b   = blk / (hw_out * hw_out);
    const bf16* ip = in + (size_t)b * (NTOK * DIM) + (size_t)in_boff * DIM;
    float acc0 = cb[c], acc1 = cb[c + 1];
#pragma unroll
    for (int ky = 0; ky < 3; ky++) {
        int iy = oy * stride - 1 + ky;
        if (iy < 0 || iy >= hw_in) continue;
#pragma unroll
        for (int kx = 0; kx < 3; kx++) {
            int ix = ox * stride - 1 + kx;
            if (ix < 0 || ix >= hw_in) continue;
            uint32_t raw = *(const uint32_t*)(ip + (size_t)(iy * hw_in + ix) * DIM + c);
            __nv_bfloat162 pv = *(__nv_bfloat162*)&raw;
            int j = ky * 3 + kx;
            acc0 += __bfloat162float(pv.x) * w[c * 9 + j];
            acc1 += __bfloat162float(pv.y) * w[(c + 1) * 9 + j];
        }
    }
    float rs = rsqrtf(1.0f + 1e-5f);
    float o0 = acc0 * (bng[c] * rs)     + bnb[c];
    float o1 = acc1 * (bng[c + 1] * rs) + bnb[c + 1];
    *(uint32_t*)(out + (size_t)b * out_bstride + (size_t)(out_boff + oy * hw_out + ox) * DIM + c)
        = pack_bf2(o0, o1);
}

// All 6 conv geometries in ONE launch; grid = 40960 (q) + 10240 (k) + 10240 (v)
__global__ void dwconv_all(const bf16* __restrict__ in,
                           const float* __restrict__ wq, const float* __restrict__ cbq,
                           const float* __restrict__ gq, const float* __restrict__ bbq,
                           const float* __restrict__ wk, const float* __restrict__ cbk,
                           const float* __restrict__ gk, const float* __restrict__ bbk,
                           const float* __restrict__ wv, const float* __restrict__ cbv,
                           const float* __restrict__ gv, const float* __restrict__ bbv,
                           bf16* __restrict__ outq, bf16* __restrict__ outk,
                           bf16* __restrict__ outv) {
    int blk = blockIdx.x;
    if (blk < BATCH * 1280) {                     // Q conv (stride 1)
        if (blk < BATCH * 1024)
            dw_body(in, wq, cbq, gq, bbq, outq, blk, 32, 32, 1, 0, 0, NTOK * DIM);
        else
            dw_body(in, wq, cbq, gq, bbq, outq, blk - BATCH * 1024, 16, 16, 1, 1024, 1024, NTOK * DIM);
        return;
    }
    blk -= BATCH * 1280;
    const float *w, *cb, *bng, *bnb; bf16* out;
    if (blk < BATCH * 320) { w = wk; cb = cbk; bng = gk; bnb = bbk; out = outk; }
    else { blk -= BATCH * 320; w = wv; cb = cbv; bng = gv; bnb = bbv; out = outv; }
    if (blk < BATCH * 256)
        dw_body(in, w, cb, bng, bnb, out, blk, 32, 16, 2, 0, 0, NKV * DIM);
    else
        dw_body(in, w, cb, bng, bnb, out, blk - BATCH * 256, 16, 8, 2, 1024, 256, NKV * DIM);
}

// ---------------------------------------------------------------------------
// cp.async 3-stage BF16 GEMM mainloop (identical to round-12 baseline)
// ---------------------------------------------------------------------------
#define BSTG 10240

__device__ __forceinline__ void gemm_load_stage_bf(
    uint32_t smem_u32, const bf16* Asrc, const bf16* Bsrc, int s, int k0) {
    uint32_t dA = smem_u32 + (uint32_t)(s * BSTG) * 2u;
    const bf16* pA = Asrc + k0;
    CP_A16(dA, pA);
    CP_A16(dA + 16u, pA + 8);
    uint32_t dB = smem_u32 + (uint32_t)(s * BSTG + 5120) * 2u;
    const bf16* pB = Bsrc + k0;
    CP_A16(dB, pB);
    CP_A16(dB + 16u, pB + 8);
}

struct GemmCtx {
    uint32_t a_base[4];
    uint32_t b_base[2];
    uint32_t stoff;
};

__device__ __forceinline__ void gemm_ctx_init(GemmCtx& cx, uint32_t smem_u32) {
    int t = threadIdx.x;
    int row = t >> 1, half = t & 1;
    cx.stoff = (uint32_t)(row * 40 + half * 16) * 2u;
    int lane = t & 31;
    int w = t >> 5;
    int wm = (w >> 2) * 64, wn = (w & 3) * 32;
    int arow = wm + ((lane >> 3) & 1) * 8 + (lane & 7);
    int akw  = (lane >> 4) * 4;
#pragma unroll
    for (int mt = 0; mt < 4; mt++)
        cx.a_base[mt] = smem_u32 + (uint32_t)(((arow + mt * 16) * 20 + akw) * 4);
    int brow = wn + ((lane >> 4) & 1) * 8 + (lane & 7);
    int bkw  = ((lane >> 3) & 1) * 4;
#pragma unroll
    for (int p = 0; p < 2; p++)
        cx.b_base[p] = smem_u32 + (uint32_t)((2560 + (brow + p * 16) * 20 + bkw) * 4);
}

__device__ __forceinline__ void gemm_mainloop(
    const GemmCtx& cx, uint32_t smem_u32,
    const bf16* Asrc, const bf16* Bsrc, int ntiles, float acc[4][4][4]) {
    gemm_load_stage_bf(smem_u32 + cx.stoff, Asrc, Bsrc, 0, 0);
    CP_COMMIT();
    gemm_load_stage_bf(smem_u32 + cx.stoff, Asrc, Bsrc, 1, 32);
    CP_COMMIT();
    for (int i = 0; i < ntiles; i++) {
        CP_WAIT1();
        __syncthreads();
        if (i + 2 < ntiles)
            gemm_load_stage_bf(smem_u32 + cx.stoff, Asrc, Bsrc, (i + 2) % 3, (i + 2) * 32);
        CP_COMMIT();
        uint32_t so = (uint32_t)((i % 3) * 20480);
#pragma unroll
        for (int ks = 0; ks < 2; ks++) {
            uint32_t af[4][4], bb[2][4];
#pragma unroll
            for (int mt = 0; mt < 4; mt++)
                ldsm_x4(cx.a_base[mt] + so + ks * 32, af[mt]);
#pragma unroll
            for (int p = 0; p < 2; p++)
                ldsm_x4(cx.b_base[p] + so + ks * 32, bb[p]);
#pragma unroll
            for (int mt = 0; mt < 4; mt++)
#pragma unroll
                for (int nt = 0; nt < 4; nt++) {
                    uint32_t bfr[2] = { bb[nt >> 1][(nt & 1) * 2], bb[nt >> 1][(nt & 1) * 2 + 1] };
                    mma_bf16(acc[mt][nt], af[mt], bfr);
                }
        }
    }
}

// FFN GEMMs. EPI: 1 = bias+GELU -> bf16, 2 = bias+residual -> fp32.
template<int EPI>
__global__ void __launch_bounds__(256, 2)
gemm_bf(const bf16* __restrict__ A, const bf16* __restrict__ W,
        const float* __restrict__ bias, const float* __restrict__ res,
        void* __restrict__ Cv, int M, int N, int K) {
    extern __shared__ bf16 smem_bf[];
    uint32_t smem_u32 = (uint32_t)__cvta_generic_to_shared(smem_bf);
    int n0 = blockIdx.x * 128, m0 = blockIdx.y * 128;
    int t = threadIdx.x;
    int row = t >> 1, half = t & 1;
    int lane = t & 31, g = lane >> 2, tig = lane & 3;
    int w = t >> 5;
    int wm = (w >> 2) * 64, wn = (w & 3) * 32;

    GemmCtx cx; gemm_ctx_init(cx, smem_u32);
    const bf16* Asrc = A + (size_t)(m0 + row) * K + half * 16;
    const bf16* Bsrc = W + (size_t)(n0 + row) * K + half * 16;
    float acc[4][4][4] = {};
    gemm_mainloop(cx, smem_u32, Asrc, Bsrc, K >> 5, acc);

#pragma unroll
    for (int mt = 0; mt < 4; mt++) {
#pragma unroll
        for (int nt = 0; nt < 4; nt++) {
            int rbase = m0 + wm + mt * 16 + g;
            int col = n0 + wn + nt * 8 + 2 * tig;
#pragma unroll
            for (int hh = 0; hh < 2; hh++) {
                int r = rbase + hh * 8;
                float v0 = acc[mt][nt][hh * 2 + 0] + bias[col];
                float v1 = acc[mt][nt][hh * 2 + 1] + bias[col + 1];
                if (EPI == 1) {
                    v0 = 0.5f * v0 * (1.0f + erff(v0 * 0.70710678118654752f));
                    v1 = 0.5f * v1 * (1.0f + erff(v1 * 0.70710678118654752f));
                }
                size_t gi = (size_t)r * N + col;
                if (EPI == 2) {
                    float* C = (float*)Cv;
                    *(float2*)(C + gi) = make_float2(v0 + res[gi], v1 + res[gi + 1]);
                } else {
                    bf16* C = (bf16*)Cv;
                    *(uint32_t*)(C + gi) = pack_bf2(v0, v1);
                }
            }
        }
    }
}

// Merged Q/K/V projection GEMM: grid (3, 480); by<320 -> Q, <400 -> K, else V.
__global__ void __launch_bounds__(256, 2)
gemm_proj(const bf16* __restrict__ Aq, const bf16* __restrict__ Wq, const float* __restrict__ bq, bf16* __restrict__ Cq,
          const bf16* __restrict__ Ak, const bf16* __restrict__ Wk, const float* __restrict__ bk, bf16* __restrict__ Ck,
          const bf16* __restrict__ Av, const bf16* __restrict__ Wv, const float* __restrict__ bv, bf16* __restrict__ Cv2) {
    extern __shared__ bf16 smem_bf[];
    uint32_t smem_u32 = (uint32_t)__cvta_generic_to_shared(smem_bf);
    int by = blockIdx.y;
    const bf16 *A, *W; const float* bias; bf16* C;
    if (by < 320)      { A = Aq; W = Wq; bias = bq; C = Cq; }
    else if (by < 400) { A = Ak; W = Wk; bias = bk; C = Ck; by -= 320; }
    else               { A = Av; W = Wv; bias = bv; C = Cv2; by -= 400; }

    int n0 = blockIdx.x * 128, m0 = by * 128;
    int t = threadIdx.x;
    int row = t >> 1, half = t & 1;
    int lane = t & 31, g = lane >> 2, tig = lane & 3;
    int w = t >> 5;
    int wm = (w >> 2) * 64, wn = (w & 3) * 32;

    GemmCtx cx; gemm_ctx_init(cx, smem_u32);
    const bf16* Asrc = A + (size_t)(m0 + row) * DIM + half * 16;
    const bf16* Bsrc = W + (size_t)(n0 + row) * DIM + half * 16;
    float acc[4][4][4] = {};
    gemm_mainloop(cx, smem_u32, Asrc, Bsrc, DIM >> 5, acc);

#pragma unroll
    for (int mt = 0; mt < 4; mt++) {
#pragma unroll
        for (int nt = 0; nt < 4; nt++) {
            int rbase = m0 + wm + mt * 16 + g;
            int col = n0 + wn + nt * 8 + 2 * tig;
#pragma unroll
            for (int hh = 0; hh < 2; hh++) {
                int r = rbase + hh * 8;
                float v0 = acc[mt][nt][hh * 2 + 0] + bias[col];
                float v1 = acc[mt][nt][hh * 2 + 1] + bias[col + 1];
                *(uint32_t*)(C + (size_t)r * DIM + col) = pack_bf2(v0, v1);
            }
        }
    }
}

// ---------------------------------------------------------------------------
// Fused flash attention, base-2 online softmax, cp.async K/V + ldmatrix.
// grid: (20, B*H): bx 0..15 search (nkv=320), 16..19 target (nkv=64).
// ---------------------------------------------------------------------------
__global__ void __launch_bounds__(128)
attn_fused(const bf16* __restrict__ Q, const bf16* __restrict__ Kg,
           const bf16* __restrict__ Vg, const float* __restrict__ x,
           float* __restrict__ x2) {
    __shared__ __align__(16) bf16 Qs[64][56];
    __shared__ __align__(16) bf16 Ks[2][64][56];
    __shared__ __align__(16) bf16 Vs[2][64][56];
    __shared__ __align__(16) bf16 Ps[4][16][72];

    int bh = blockIdx.y, b = bh >> 3, h = bh & 7;
    int bx = blockIdx.x;
    int q_base, kv_base, niter;
    if (bx < 16) { q_base = bx * 64;               kv_base = 0;   niter = 5; }
    else         { q_base = 1024 + (bx - 16) * 64; kv_base = 256; niter = 1; }

    int t = threadIdx.x;
    int w = t >> 5, lane = t & 31, g = lane >> 2, tig = lane & 3;
    int wrow = w * 16;

    uint32_t qs_u32 = (uint32_t)__cvta_generic_to_shared(&Qs[0][0]);
    uint32_t ks_u32 = (uint32_t)__cvta_generic_to_shared(&Ks[0][0][0]);
    uint32_t vs_u32 = (uint32_t)__cvta_generic_to_shared(&Vs[0][0][0]);

    for (int idx = t; idx < 384; idx += 128) {
        int r = idx / 6, c8 = (idx % 6) * 8;
        uint4 raw = *(const uint4*)(Q + (size_t)(b * NTOK + q_base + r) * DIM + h * HDIM + c8);
        *(uint2*)&Qs[r][c8]     = make_uint2(raw.x, raw.y);
        *(uint2*)&Qs[r][c8 + 4] = make_uint2(raw.z, raw.w);
    }

    {
        const bf16* kbase = Kg + (size_t)(b * NKV + kv_base) * DIM + h * HDIM;
        const bf16* vbase = Vg + (size_t)(b * NKV + kv_base) * DIM + h * HDIM;
#pragma unroll
        for (int j0 = 0; j0 < 768; j0 += 128) {
            int j = j0 + t;
            int hv = j >= 384;
            int jj = hv ? j - 384 : j;
            int r = jj / 6, c8 = (jj % 6) * 8;
            const bf16* src = (hv ? vbase : kbase) + (size_t)r * DIM + c8;
            uint32_t dst = (hv ? vs_u32 : ks_u32) + (uint32_t)((r * 56 + c8) * 2);
            CP_A16(dst, src);
        }
        CP_COMMIT();
    }
    __syncthreads();

    uint32_t qf[3][4];
    {
        uint32_t qaddr = qs_u32 + (uint32_t)(((wrow + (lane & 15)) * 56 + (lane >> 4) * 8) * 2);
#pragma unroll
        for (int kt = 0; kt < 3; kt++)
            ldsm_x4(qaddr + kt * 32, qf[kt]);
    }

    uint32_t kaddr0 = ks_u32 + (uint32_t)((((lane & 7) + ((lane >> 4) & 1) * 8) * 56
                                           + ((lane >> 3) & 1) * 8) * 2);
    uint32_t vaddr0 = vs_u32 + (uint32_t)(((lane & 15) * 56 + (lane >> 4) * 8) * 2);

    float m0r = -1e30f, m1r = -1e30f, l0 = 0.0f, l1 = 0.0f;
    float oacc[6][4] = {};
    uint32_t* Pw = (uint32_t*)&Ps[w][0][0];

    for (int i = 0; i < niter; i++) {
        CP_WAIT0();
        __syncthreads();

        if (i + 1 < niter) {
            int k0n = (i + 1) * 64;
            uint32_t bufo = (uint32_t)(((i + 1) & 1) * 7168);
            const bf16* kbase = Kg + (size_t)(b * NKV + kv_base + k0n) * DIM + h * HDIM;
            const bf16* vbase = Vg + (size_t)(b * NKV + kv_base + k0n) * DIM + h * HDIM;
#pragma unroll
            for (int j0 = 0; j0 < 768; j0 += 128) {
                int j = j0 + t;
                int hv = j >= 384;
                int jj = hv ? j - 384 : j;
                int r = jj / 6, c8 = (jj % 6) * 8;
                const bf16* src = (hv ? vbase : kbase) + (size_t)r * DIM + c8;
                uint32_t dst = (hv ? vs_u32 : ks_u32) + bufo + (uint32_t)((r * 56 + c8) * 2);
                CP_A16(dst, src);
            }
        }
        CP_COMMIT();

        uint32_t bufc = (uint32_t)((i & 1) * 7168);

        // S' = Q @ K^T * (scale*log2e)
        float sf[8][4] = {};
#pragma unroll
        for (int kt = 0; kt < 3; kt++) {
#pragma unroll
            for (int p = 0; p < 4; p++) {
                uint32_t kb[4];
                ldsm_x4(kaddr0 + bufc + (uint32_t)(p * 16 * 112 + kt * 32), kb);
                uint32_t b0[2] = { kb[0], kb[1] };
                uint32_t b1[2] = { kb[2], kb[3] };
                mma_bf16(sf[2 * p],     qf[kt], b0);
                mma_bf16(sf[2 * p + 1], qf[kt], b1);
            }
        }
#pragma unroll
        for (int nt = 0; nt < 8; nt++) {
            sf[nt][0] *= ATT_SC2; sf[nt][1] *= ATT_SC2;
            sf[nt][2] *= ATT_SC2; sf[nt][3] *= ATT_SC2;
        }

        float tm0 = -1e30f, tm1 = -1e30f;
#pragma unroll
        for (int nt = 0; nt < 8; nt++) {
            tm0 = fmaxf(tm0, fmaxf(sf[nt][0], sf[nt][1]));
            tm1 = fmaxf(tm1, fmaxf(sf[nt][2], sf[nt][3]));
        }
        tm0 = fmaxf(tm0, __shfl_xor_sync(0xffffffffu, tm0, 1));
        tm0 = fmaxf(tm0, __shfl_xor_sync(0xffffffffu, tm0, 2));
        tm1 = fmaxf(tm1, __shfl_xor_sync(0xffffffffu, tm1, 1));
        tm1 = fmaxf(tm1, __shfl_xor_sync(0xffffffffu, tm1, 2));
        float nm0 = fmaxf(m0r, tm0), nm1 = fmaxf(m1r, tm1);
        float f0 = ex2f(m0r - nm0), f1 = ex2f(m1r - nm1);
        m0r = nm0; m1r = nm1;
        l0 *= f0; l1 *= f1;
#pragma unroll
        for (int nt = 0; nt < 6; nt++) {
            oacc[nt][0] *= f0; oacc[nt][1] *= f0;
            oacc[nt][2] *= f1; oacc[nt][3] *= f1;
        }
#pragma unroll
        for (int nt = 0; nt < 8; nt++) {
            float p0 = ex2f(sf[nt][0] - m0r);
            float p1 = ex2f(sf[nt][1] - m0r);
            float p2 = ex2f(sf[nt][2] - m1r);
            float p3 = ex2f(sf[nt][3] - m1r);
            l0 += p0 + p1; l1 += p2 + p3;
            Pw[(g    ) * 36 + nt * 4 + tig] = pack_bf2(p0, p1);
            Pw[(g + 8) * 36 + nt * 4 + tig] = pack_bf2(p2, p3);
        }
        __syncwarp();

#pragma unroll
        for (int ks = 0; ks < 4; ks++) {
            uint32_t pa[4];
            pa[0] = Pw[(g    ) * 36 + ks * 8 + tig];
            pa[1] = Pw[(g + 8) * 36 + ks * 8 + tig];
            pa[2] = Pw[(g    ) * 36 + ks * 8 + tig + 4];
            pa[3] = Pw[(g + 8) * 36 + ks * 8 + tig + 4];
#pragma unroll
            for (int jv = 0; jv < 3; jv++) {
                uint32_t vv[4];
                ldsm_x4_t(vaddr0 + bufc + (uint32_t)(ks * 16 * 112 + jv * 32), vv);
                uint32_t b0[2] = { vv[0], vv[1] };
                uint32_t b1[2] = { vv[2], vv[3] };
                mma_bf16(oacc[2 * jv],     pa, b0);
                mma_bf16(oacc[2 * jv + 1], pa, b1);
            }
        }
        __syncwarp();
    }

    l0 += __shfl_xor_sync(0xffffffffu, l0, 1);
    l0 += __shfl_xor_sync(0xffffffffu, l0, 2);
    l1 += __shfl_xor_sync(0xffffffffu, l1, 1);
    l1 += __shfl_xor_sync(0xffffffffu, l1, 2);
    float inv0 = 1.0f / l0, inv1 = 1.0f / l1;
    int r0 = b * NTOK + q_base + wrow + g;
#pragma unroll
    for (int nt = 0; nt < 6; nt++) {
        int col = h * HDIM + nt * 8 + 2 * tig;
        size_t gi0 = (size_t)r0 * DIM + col;
        size_t gi1 = (size_t)(r0 + 8) * DIM + col;
        float2 xa = *(const float2*)(x + gi0);
        float2 xb = *(const float2*)(x + gi1);
        *(float2*)(x2 + gi0) = make_float2(xa.x + oacc[nt][0] * inv0, xa.y + oacc[nt][1] * inv0);
        *(float2*)(x2 + gi1) = make_float2(xb.x + oacc[nt][2] * inv1, xb.y + oacc[nt][3] * inv1);
    }
}

// ---------------------------------------------------------------------------
// Launch
// ---------------------------------------------------------------------------
extern "C" void kernel_launch(void* const* d_in, const int* in_sizes, int n_in,
                              void* d_out, int out_size) {
    (void)in_sizes; (void)n_in; (void)out_size;
    const float* x     = (const float*)d_in[0];
    const float* ln1_g = (const float*)d_in[1];
    const float* ln1_b = (const float*)d_in[2];
    const float* dwq_w = (const float*)d_in[3];
    const float* dwq_b = (const float*)d_in[4];
    const float* bnq_g = (const float*)d_in[5];
    const float* bnq_b = (const float*)d_in[6];
    const float* dwk_w = (const float*)d_in[7];
    const float* dwk_b = (const float*)d_in[8];
    const float* bnk_g = (const float*)d_in[9];
    const float* bnk_b = (const float*)d_in[10];
    const float* dwv_w = (const float*)d_in[11];
    const float* dwv_b = (const float*)d_in[12];
    const float* bnv_g = (const float*)d_in[13];
    const float* bnv_b = (const float*)d_in[14];
    const float* pq_w  = (const float*)d_in[15];
    const float* pq_b  = (const float*)d_in[16];
    const float* pk_w  = (const float*)d_in[17];
    const float* pk_b  = (const float*)d_in[18];
    const float* pv_w  = (const float*)d_in[19];
    const float* pv_b  = (const float*)d_in[20];
    const float* ln2_g = (const float*)d_in[21];
    const float* ln2_b = (const float*)d_in[22];
    const float* ff1_w = (const float*)d_in[23];
    const float* ff1_b = (const float*)d_in[24];
    const float* ff2_w = (const float*)d_in[25];
    const float* ff2_b = (const float*)d_in[26];
    float* out = (float*)d_out;

    bf16 *xn, *qc, *kc, *vc, *Q, *K, *V, *h1, *wq, *wk, *wv, *w1, *w2;
    float *x2;
    cudaGetSymbolAddress((void**)&xn, g_xn);
    cudaGetSymbolAddress((void**)&qc, g_qc);
    cudaGetSymbolAddress((void**)&kc, g_kc);
    cudaGetSymbolAddress((void**)&vc, g_vc);
    cudaGetSymbolAddress((void**)&Q,  g_Q);
    cudaGetSymbolAddress((void**)&K,  g_K);
    cudaGetSymbolAddress((void**)&V,  g_V);
    cudaGetSymbolAddress((void**)&x2, g_x2);
    cudaGetSymbolAddress((void**)&h1, g_h1);
    cudaGetSymbolAddress((void**)&wq, g_wq);
    cudaGetSymbolAddress((void**)&wk, g_wk);
    cudaGetSymbolAddress((void**)&wv, g_wv);
    cudaGetSymbolAddress((void**)&w1, g_w1);
    cudaGetSymbolAddress((void**)&w2, g_w2);

    cudaFuncSetAttribute(gemm_bf<1>, cudaFuncAttributeMaxDynamicSharedMemorySize, 61440);
    cudaFuncSetAttribute(gemm_bf<2>, cudaFuncAttributeMaxDynamicSharedMemorySize, 61440);
    cudaFuncSetAttribute(gemm_proj,  cudaFuncAttributeMaxDynamicSharedMemorySize, 61440);

    // 1. Weight conversion + LN1 (single fused launch)
    cvt_ln1<<<1584 + BATCH * NTOK / 8, 256>>>(pq_w, wq, pk_w, wk, pv_w, wv,
                                              ff1_w, w1, ff2_w, w2,
                                              x, ln1_g, ln1_b, xn);

    // 2. All depthwise convs in one launch (q 40960 + k 10240 + v 10240 blocks)
    dwconv_all<<<BATCH * 1280 + 2 * BATCH * 320, 192>>>(
        xn,
        dwq_w, dwq_b, bnq_g, bnq_b,
        dwk_w, dwk_b, bnk_g, bnk_b,
        dwv_w, dwv_b, bnv_g, bnv_b,
        qc, kc, vc);

    // 3. Q/K/V projections — single merged launch
    gemm_proj<<<dim3(3, 480), 256, 61440>>>(qc, wq, pq_b, Q,
                                            kc, wk, pk_b, K,
                                            vc, wv, pv_b, V);

    // 4. Fused flash attention (+ residual)
    attn_fused<<<dim3(20, BATCH * HEADS), 128>>>(Q, K, V, x, x2);

    // 5. LN2 + FFN
    ln_kernel<<<BATCH * NTOK / 8, 256>>>(x2, ln2_g, ln2_b, xn);
    gemm_bf<1><<<dim3(12, 320), 256, 61440>>>(xn, w1, ff1_b, nullptr, h1, BATCH * NTOK, FFDIM, DIM);
    gemm_bf<2><<<dim3(3, 320),  256, 61440>>>(h1, w2, ff2_b, x2, out, BATCH * NTOK, DIM, FFDIM);
}